// round 8
// baseline (speedup 1.0000x reference)
#include <cuda_runtime.h>
#include <cstdint>
#include <math.h>

// ---------------------------------------------------------------------------
// Problem constants (fixed by the dataset)
// ---------------------------------------------------------------------------
#define Bb   512
#define Tt   50
#define Dd   100
#define BT   (Bb*Tt)          // 25600
#define NN   100000
#define NOUT (NN-1)           // 99999

typedef unsigned long long ull;

// ---------------------------------------------------------------------------
// f32x2 packed-FMA helpers (sm_100a+/sm_103a FFMA2 path)
// ---------------------------------------------------------------------------
__device__ __forceinline__ ull pack2(float x, float y) {
    ull r; asm("mov.b64 %0, {%1, %2};" : "=l"(r) : "f"(x), "f"(y)); return r;
}
__device__ __forceinline__ void unpack2(ull v, float& x, float& y) {
    asm("mov.b64 {%0, %1}, %2;" : "=f"(x), "=f"(y) : "l"(v));
}
__device__ __forceinline__ void fma2(ull& d, ull a, ull b) {
    asm("fma.rn.f32x2 %0, %1, %2, %3;" : "=l"(d) : "l"(a), "l"(b), "l"(d));
}
__device__ __forceinline__ float sigmoidf_(float x) { return 1.0f / (1.0f + expf(-x)); }

// ---------------------------------------------------------------------------
// Scratch (static device globals: runtime allocation is forbidden)
// ---------------------------------------------------------------------------
__device__ float g_h   [BT*Dd];     // gathered embeddings (h)
__device__ float g_hin [BT*Dd];     // h@W_in + b_in
__device__ float g_hout[BT*Dd];     // h@W_out + b_out
__device__ float g_X   [BT*3*Dd];   // [a_in | a_out | h]  -> later [a_in | a_out | r*h]
__device__ float g_rh  [BT*Dd];     // r * h
__device__ float g_u   [BT*Dd];     // update gate u
__device__ float g_hnew[BT*Dd];     // re_emb
__device__ float g_seqh[BT*Dd];     // seq_h (alias-gathered re_emb)
__device__ float g_seq [BT*Dd];     // seq_h @ nasr_w2
__device__ float g_last[Bb*Dd];     // last_h @ nasr_w1
__device__ float g_y1  [Bb*Dd];     // ma @ B_mat

// ---------------------------------------------------------------------------
// K1: gather h = embedding[item]; also seed g_X[:,200:300] = h
// ---------------------------------------------------------------------------
__global__ void gather_h_kernel(const float* __restrict__ emb,
                                const int* __restrict__ item) {
    int i = blockIdx.x * 256 + threadIdx.x;
    if (i >= BT*Dd) return;
    int row = i / Dd;
    int c   = i - row * Dd;
    float v = emb[(size_t)item[row] * Dd + c];
    g_h[i] = v;
    g_X[(size_t)row * 300 + 200 + c] = v;
}

// ---------------------------------------------------------------------------
// Generic tiled fp32 GEMM with f32x2 accumulators.
//   C[M,N] = epi(A[M,K] @ B + bias)
//   TRANSB=false: B is [K,N] row-major (ldb = row stride)
//   TRANSB=true : B is [N,K] row-major (ldb = row stride), i.e. C = A @ B^T
// Tile: BM=128, BN=64, BK=16; 256 threads; thread tile 8x4 (2 f32x2 col pairs).
// A is stored lane-duplicated in SMEM (ull) so the hot loop is LDS + FFMA2 only.
// EPI: 0 = plain (+bias if non-null)
//      1 = gates: v=sigmoid(v+bias); n<100 -> y1p=r*h ; n>=100 -> y2p=u
//      2 = cand : c=tanh(v+bias); C = u*h + (1-u)*c
// M must be a multiple of 128 (true for all call sites: 25600, 512).
// ---------------------------------------------------------------------------
template<int EPI, bool TRANSB>
__global__ void __launch_bounds__(256)
gemm_kernel(const float* __restrict__ A, const float* __restrict__ Bm,
            const float* __restrict__ bias, float* __restrict__ C,
            int M, int N, int K, int lda, int ldb, int ldc,
            const float* __restrict__ x1,   // EPI1/2: h
            const float* __restrict__ x2,   // EPI2:   u
            float* __restrict__ y1p,        // EPI1:   r*h out
            float* __restrict__ y2p)        // EPI1:   u out
{
    const int BM = 128, BN = 64, BK = 16;
    __shared__ ull   As2[BK][BM];   // 16 KB, value duplicated in both lanes
    __shared__ float Bs [BK][BN];   // 4 KB

    int tid = threadIdx.x;
    int tx  = tid & 15;             // N direction (16 * 4 cols)
    int ty  = tid >> 4;             // M direction (16 * 8 rows)
    int m0  = blockIdx.y * BM;
    int n0  = blockIdx.x * BN;

    // loader indices
    int alr = tid >> 1;             // 0..127 : A row
    int alk = (tid & 1) * 8;        // 0 or 8 : A k-offset
    int blk = tid >> 4;             // 0..15  : B k (non-trans)
    int bln = (tid & 15) * 4;       //        : B n (non-trans)
    int bnt = tid >> 2;             // 0..63  : B n (trans)
    int bkt = (tid & 3) * 4;        //        : B k (trans)

    ull acc[8][2];
    #pragma unroll
    for (int i = 0; i < 8; i++) { acc[i][0] = 0ULL; acc[i][1] = 0ULL; }

    for (int k0 = 0; k0 < K; k0 += BK) {
        // --- load A tile (transposed + lane-duplicated) ---
        const float* Arow = A + (size_t)(m0 + alr) * lda;
        #pragma unroll
        for (int j = 0; j < 8; j++) {
            int k = k0 + alk + j;
            float v = (k < K) ? Arow[k] : 0.0f;
            As2[alk + j][alr] = pack2(v, v);
        }
        // --- load B tile ---
        if (!TRANSB) {
            #pragma unroll
            for (int j = 0; j < 4; j++) {
                int k = k0 + blk, n = n0 + bln + j;
                Bs[blk][bln + j] = (k < K && n < N) ? Bm[(size_t)k * ldb + n] : 0.0f;
            }
        } else {
            const float* Brow = Bm + (size_t)(n0 + bnt) * ldb;
            bool nok = (n0 + bnt) < N;
            #pragma unroll
            for (int j = 0; j < 4; j++) {
                int k = k0 + bkt + j;
                Bs[bkt + j][bnt] = (nok && k < K) ? Brow[k] : 0.0f;
            }
        }
        __syncthreads();

        #pragma unroll
        for (int kk = 0; kk < BK; kk++) {
            const ull* bp = reinterpret_cast<const ull*>(&Bs[kk][tx * 4]);
            ull b0 = bp[0], b1 = bp[1];
            const ulonglong2* ap = reinterpret_cast<const ulonglong2*>(&As2[kk][ty * 8]);
            ulonglong2 a01 = ap[0], a23 = ap[1], a45 = ap[2], a67 = ap[3];
            ull av[8] = {a01.x, a01.y, a23.x, a23.y, a45.x, a45.y, a67.x, a67.y};
            #pragma unroll
            for (int i = 0; i < 8; i++) {
                fma2(acc[i][0], av[i], b0);
                fma2(acc[i][1], av[i], b1);
            }
        }
        __syncthreads();
    }

    // --- epilogue ---
    #pragma unroll
    for (int i = 0; i < 8; i++) {
        int gm = m0 + ty * 8 + i;
        if (gm >= M) continue;
        #pragma unroll
        for (int p = 0; p < 2; p++) {
            float v0, v1;
            unpack2(acc[i][p], v0, v1);
            int gn0 = n0 + tx * 4 + p * 2;
            float vs[2] = {v0, v1};
            #pragma unroll
            for (int q = 0; q < 2; q++) {
                int gn = gn0 + q;
                if (gn >= N) continue;
                float v = vs[q];
                if (EPI == 0) {
                    if (bias) v += bias[gn];
                    C[(size_t)gm * ldc + gn] = v;
                } else if (EPI == 1) {
                    float g = sigmoidf_(v + bias[gn]);
                    if (gn < Dd) {
                        y1p[(size_t)gm * Dd + gn] = g * x1[(size_t)gm * Dd + gn];
                    } else {
                        y2p[(size_t)gm * Dd + (gn - Dd)] = g;
                    }
                } else { // EPI == 2
                    float cc = tanhf(v + bias[gn]);
                    float uu = x2[(size_t)gm * Dd + gn];
                    float hh = x1[(size_t)gm * Dd + gn];
                    C[(size_t)gm * ldc + gn] = uu * hh + (1.0f - uu) * cc;
                }
            }
        }
    }
}

// ---------------------------------------------------------------------------
// K3: per-batch adjacency propagation  a[t,c] = sum_s adj[b,t,s] * hv[b,s,c]
// One block per batch; writes into g_X at column offset coloff.
// 2x4 register tile via f32x2.
// ---------------------------------------------------------------------------
__global__ void __launch_bounds__(256)
adj_kernel(const float* __restrict__ adj, const float* __restrict__ hv, int coloff)
{
    __shared__ float adjS[Tt*Tt];   // 10 KB
    __shared__ float hS[Tt*Dd];     // 20 KB
    int b = blockIdx.x;
    int tid = threadIdx.x;
    for (int i = tid; i < Tt*Tt; i += 256) adjS[i] = adj[(size_t)b*Tt*Tt + i];
    for (int i = tid; i < Tt*Dd; i += 256) hS[i]   = hv[(size_t)b*Tt*Dd + i];
    __syncthreads();

    // tasks: 25 t-pairs x 25 col-quads = 625
    for (int task = tid; task < 625; task += 256) {
        int tg = task / 25, cg = task - tg * 25;
        int t0 = tg * 2, c0 = cg * 4;
        ull a00 = 0, a01 = 0, a10 = 0, a11 = 0;
        #pragma unroll 5
        for (int s = 0; s < Tt; s++) {
            const ull* hp = reinterpret_cast<const ull*>(&hS[s * Dd + c0]);
            ull b0 = hp[0], b1 = hp[1];
            float w0 = adjS[t0 * Tt + s];
            float w1 = adjS[(t0 + 1) * Tt + s];
            ull p0 = pack2(w0, w0), p1 = pack2(w1, w1);
            fma2(a00, p0, b0); fma2(a01, p0, b1);
            fma2(a10, p1, b0); fma2(a11, p1, b1);
        }
        float o0, o1, o2, o3;
        size_t base0 = (size_t)(b * Tt + t0) * 300 + coloff + c0;
        unpack2(a00, o0, o1); unpack2(a01, o2, o3);
        g_X[base0 + 0] = o0; g_X[base0 + 1] = o1; g_X[base0 + 2] = o2; g_X[base0 + 3] = o3;
        size_t base1 = (size_t)(b * Tt + t0 + 1) * 300 + coloff + c0;
        unpack2(a10, o0, o1); unpack2(a11, o2, o3);
        g_X[base1 + 0] = o0; g_X[base1 + 1] = o1; g_X[base1 + 2] = o2; g_X[base1 + 3] = o3;
    }
}

// ---------------------------------------------------------------------------
// K5: splice r*h into g_X[:,200:300]
// ---------------------------------------------------------------------------
__global__ void splice_rh_kernel() {
    int i = blockIdx.x * 256 + threadIdx.x;
    if (i >= BT*Dd) return;
    int row = i / Dd;
    int c   = i - row * Dd;
    g_X[(size_t)row * 300 + 200 + c] = g_rh[i];
}

// ---------------------------------------------------------------------------
// K7a: per-batch last vector: rm=sum(mask); last_h=re_emb[b, alias[b,rm-1]];
//      g_last[b] = last_h @ nasr_w1
// ---------------------------------------------------------------------------
__global__ void last_kernel(const float* __restrict__ mask,
                            const int* __restrict__ alias_,
                            const float* __restrict__ w1)
{
    __shared__ float msum[Tt];
    __shared__ float lh[Dd];
    __shared__ int   liS;
    int b = blockIdx.x;
    int tid = threadIdx.x;
    if (tid < Tt) msum[tid] = mask[b * Tt + tid];
    __syncthreads();
    if (tid == 0) {
        float s = 0.0f;
        for (int t = 0; t < Tt; t++) s += msum[t];
        int rm = (int)s;
        liS = alias_[b * Tt + (rm - 1)];
    }
    __syncthreads();
    int li = liS;
    if (tid < Dd) lh[tid] = g_hnew[(size_t)(b * Tt + li) * Dd + tid];
    __syncthreads();
    if (tid < Dd) {
        float acc = 0.0f;
        #pragma unroll 4
        for (int k = 0; k < Dd; k++) acc += lh[k] * w1[k * Dd + tid];
        g_last[b * Dd + tid] = acc;
    }
}

// ---------------------------------------------------------------------------
// K7b: seq_h gather: g_seqh[b,t] = g_hnew[b, alias[b,t]]
// ---------------------------------------------------------------------------
__global__ void seqh_kernel(const int* __restrict__ alias_) {
    int i = blockIdx.x * 256 + threadIdx.x;
    if (i >= BT*Dd) return;
    int row = i / Dd;
    int c   = i - row * Dd;
    int b   = row / Tt;
    int al  = alias_[row];
    g_seqh[i] = g_hnew[(size_t)(b * Tt + al) * Dd + c];
}

// ---------------------------------------------------------------------------
// K9: per-batch attention + readout:
//   m = sigmoid(last + seq + nasr_b); coef = (m.v) * mask
//   ma = [sum_t coef*seq_h , last];  y1 = ma @ B_mat
// Warp-specialized over t (4 warps, shfl reductions, no per-t block syncs).
// ---------------------------------------------------------------------------
__global__ void __launch_bounds__(128)
att_kernel(const float* __restrict__ mask,
           const float* __restrict__ vv,     // nasr_v (100)
           const float* __restrict__ nb,     // nasr_b (100)
           const float* __restrict__ Bmat)   // (200,100)
{
    __shared__ float lastS[Dd], nbS[Dd], vS[Dd];
    __shared__ float acc4[4][Dd];
    __shared__ float maS[2 * Dd];
    int b = blockIdx.x;
    int tid = threadIdx.x;
    int w = tid >> 5, lane = tid & 31;

    if (tid < Dd) { lastS[tid] = g_last[b * Dd + tid]; nbS[tid] = nb[tid]; vS[tid] = vv[tid]; }
    __syncthreads();

    float accR[4] = {0.f, 0.f, 0.f, 0.f};
    for (int t = w; t < Tt; t += 4) {
        const float* seqrow = &g_seq [(size_t)(b * Tt + t) * Dd];
        const float* shrow  = &g_seqh[(size_t)(b * Tt + t) * Dd];
        float part = 0.0f;
        #pragma unroll
        for (int j = 0; j < 4; j++) {
            int c = lane + 32 * j;
            if (c < Dd) {
                float m = sigmoidf_(lastS[c] + seqrow[c] + nbS[c]);
                part += m * vS[c];
            }
        }
        #pragma unroll
        for (int off = 16; off > 0; off >>= 1)
            part += __shfl_xor_sync(0xffffffffu, part, off);
        float coef = part * mask[b * Tt + t];
        #pragma unroll
        for (int j = 0; j < 4; j++) {
            int c = lane + 32 * j;
            if (c < Dd) accR[j] += coef * shrow[c];
        }
    }
    #pragma unroll
    for (int j = 0; j < 4; j++) {
        int c = lane + 32 * j;
        if (c < Dd) acc4[w][c] = accR[j];
    }
    __syncthreads();
    if (tid < Dd) {
        maS[tid]      = acc4[0][tid] + acc4[1][tid] + acc4[2][tid] + acc4[3][tid];
        maS[Dd + tid] = lastS[tid];
    }
    __syncthreads();
    if (tid < Dd) {
        float y = 0.0f;
        #pragma unroll 4
        for (int k = 0; k < 2 * Dd; k++) y += maS[k] * Bmat[k * Dd + tid];
        g_y1[b * Dd + tid] = y;
    }
}

// ---------------------------------------------------------------------------
// Host launcher
// ---------------------------------------------------------------------------
static inline int cdiv(int a, int b) { return (a + b - 1) / b; }

extern "C" void kernel_launch(void* const* d_in, const int* in_sizes, int n_in,
                              void* d_out, int out_size)
{
    // Input order per metadata: adj_in, adj_out, mask, item, alias, step,
    // embedding, W_in, b_in, W_out, b_out, gru_gate_k, gru_gate_b,
    // gru_cand_k, gru_cand_b, nasr_w1, nasr_w2, nasr_v, nasr_b, B_mat.
    // Guard against the scalar `step` being omitted from the input list.
    int o = 0;
    if (n_in < 20 || in_sizes[5] != 1) o = -1;  // step missing -> shift tail down

    const float* adj_in  = (const float*)d_in[0];
    const float* adj_out = (const float*)d_in[1];
    const float* mask    = (const float*)d_in[2];
    const int*   item    = (const int*)  d_in[3];
    const int*   alias_  = (const int*)  d_in[4];
    const float* emb     = (const float*)d_in[6  + o];
    const float* W_in    = (const float*)d_in[7  + o];
    const float* b_in    = (const float*)d_in[8  + o];
    const float* W_out   = (const float*)d_in[9  + o];
    const float* b_out   = (const float*)d_in[10 + o];
    const float* ggk     = (const float*)d_in[11 + o];
    const float* ggb     = (const float*)d_in[12 + o];
    const float* gck     = (const float*)d_in[13 + o];
    const float* gcb     = (const float*)d_in[14 + o];
    const float* w1      = (const float*)d_in[15 + o];
    const float* w2      = (const float*)d_in[16 + o];
    const float* vv      = (const float*)d_in[17 + o];
    const float* nb      = (const float*)d_in[18 + o];
    const float* Bmat    = (const float*)d_in[19 + o];
    float* out = (float*)d_out;

    // Resolve scratch symbol addresses (host API, not stream-ordered: capture-safe)
    void *p;
    cudaGetSymbolAddress(&p, g_h);    float* ph    = (float*)p;
    cudaGetSymbolAddress(&p, g_hin);  float* phin  = (float*)p;
    cudaGetSymbolAddress(&p, g_hout); float* phout = (float*)p;
    cudaGetSymbolAddress(&p, g_X);    float* pX    = (float*)p;
    cudaGetSymbolAddress(&p, g_rh);   float* prh   = (float*)p;
    cudaGetSymbolAddress(&p, g_u);    float* pu    = (float*)p;
    cudaGetSymbolAddress(&p, g_hnew); float* phnew = (float*)p;
    cudaGetSymbolAddress(&p, g_seqh); float* pseqh = (float*)p;
    cudaGetSymbolAddress(&p, g_seq);  float* pseq  = (float*)p;
    cudaGetSymbolAddress(&p, g_y1);   float* py1   = (float*)p;

    const int EW = cdiv(BT * Dd, 256);   // elementwise grid (10000 blocks)

    // ---- GGNN (step = 1 in this dataset) ----
    gather_h_kernel<<<EW, 256>>>(emb, item);

    gemm_kernel<0, false><<<dim3(cdiv(Dd, 64), cdiv(BT, 128)), 256>>>(
        ph, W_in, b_in, phin, BT, Dd, Dd, Dd, Dd, Dd,
        nullptr, nullptr, nullptr, nullptr);
    gemm_kernel<0, false><<<dim3(cdiv(Dd, 64), cdiv(BT, 128)), 256>>>(
        ph, W_out, b_out, phout, BT, Dd, Dd, Dd, Dd, Dd,
        nullptr, nullptr, nullptr, nullptr);

    adj_kernel<<<Bb, 256>>>(adj_in,  phin,  0);
    adj_kernel<<<Bb, 256>>>(adj_out, phout, Dd);

    // gates = sigmoid(X @ ggk + ggb); r*h -> g_rh, u -> g_u
    gemm_kernel<1, false><<<dim3(cdiv(2 * Dd, 64), cdiv(BT, 128)), 256>>>(
        pX, ggk, ggb, nullptr, BT, 2 * Dd, 3 * Dd, 3 * Dd, 2 * Dd, 0,
        ph, nullptr, prh, pu);

    splice_rh_kernel<<<EW, 256>>>();

    // c = tanh(X' @ gck + gcb); h_new = u*h + (1-u)*c
    gemm_kernel<2, false><<<dim3(cdiv(Dd, 64), cdiv(BT, 128)), 256>>>(
        pX, gck, gcb, phnew, BT, Dd, 3 * Dd, 3 * Dd, Dd, Dd,
        ph, pu, nullptr, nullptr);

    // ---- attention readout ----
    last_kernel<<<Bb, 128>>>(mask, alias_, w1);
    seqh_kernel<<<EW, 256>>>(alias_);

    gemm_kernel<0, false><<<dim3(cdiv(Dd, 64), cdiv(BT, 128)), 256>>>(
        pseqh, w2, nullptr, pseq, BT, Dd, Dd, Dd, Dd, Dd,
        nullptr, nullptr, nullptr, nullptr);

    att_kernel<<<Bb, 128>>>(mask, vv, nb, Bmat);

    // ---- logits = y1 @ embedding[1:]^T  (512 x 99999 x 100) ----
    gemm_kernel<0, true><<<dim3(cdiv(NOUT, 64), cdiv(Bb, 128)), 256>>>(
        py1, emb + Dd, nullptr, out, Bb, NOUT, Dd, Dd, Dd, NOUT,
        nullptr, nullptr, nullptr, nullptr);
}

// round 9
// speedup vs baseline: 1.0010x; 1.0010x over previous
#include <cuda_runtime.h>
#include <cstdint>
#include <math.h>

// ---------------------------------------------------------------------------
// Problem constants (fixed by the dataset)
// ---------------------------------------------------------------------------
#define Bb   512
#define Tt   50
#define Dd   100
#define BT   (Bb*Tt)          // 25600
#define NN   100000
#define NOUT (NN-1)           // 99999

typedef unsigned long long ull;

// ---------------------------------------------------------------------------
// f32x2 packed-FMA helpers (sm_100a+/sm_103a FFMA2 path)
// ---------------------------------------------------------------------------
__device__ __forceinline__ ull pack2(float x, float y) {
    ull r; asm("mov.b64 %0, {%1, %2};" : "=l"(r) : "f"(x), "f"(y)); return r;
}
__device__ __forceinline__ void unpack2(ull v, float& x, float& y) {
    asm("mov.b64 {%0, %1}, %2;" : "=f"(x), "=f"(y) : "l"(v));
}
__device__ __forceinline__ void fma2(ull& d, ull a, ull b) {
    asm("fma.rn.f32x2 %0, %1, %2, %3;" : "=l"(d) : "l"(a), "l"(b), "l"(d));
}
__device__ __forceinline__ float sigmoidf_(float x) { return 1.0f / (1.0f + expf(-x)); }

// ---------------------------------------------------------------------------
// Scratch (static device globals: runtime allocation is forbidden)
// ---------------------------------------------------------------------------
__device__ float g_h   [BT*Dd];     // gathered embeddings (h)
__device__ float g_hin [BT*Dd];     // h@W_in + b_in
__device__ float g_hout[BT*Dd];     // h@W_out + b_out
__device__ float g_X   [BT*3*Dd];   // [a_in | a_out | h]  -> later [a_in | a_out | r*h]
__device__ float g_rh  [BT*Dd];     // r * h
__device__ float g_u   [BT*Dd];     // update gate u
__device__ float g_hnew[BT*Dd];     // re_emb
__device__ float g_seqh[BT*Dd];     // seq_h (alias-gathered re_emb)
__device__ float g_seq [BT*Dd];     // seq_h @ nasr_w2
__device__ float g_last[Bb*Dd];     // last_h @ nasr_w1
__device__ float g_y1  [Bb*Dd];     // ma @ B_mat

// ---------------------------------------------------------------------------
// K1: gather h = embedding[item]; also seed g_X[:,200:300] = h
// ---------------------------------------------------------------------------
__global__ void gather_h_kernel(const float* __restrict__ emb,
                                const int* __restrict__ item) {
    int i = blockIdx.x * 256 + threadIdx.x;
    if (i >= BT*Dd) return;
    int row = i / Dd;
    int c   = i - row * Dd;
    float v = emb[(size_t)item[row] * Dd + c];
    g_h[i] = v;
    g_X[(size_t)row * 300 + 200 + c] = v;
}

// ---------------------------------------------------------------------------
// Generic tiled fp32 GEMM with f32x2 accumulators.
//   C[M,N] = epi(A[M,K] @ B + bias)
//   TRANSB=false: B is [K,N] row-major (ldb = row stride)
//   TRANSB=true : B is [N,K] row-major (ldb = row stride), i.e. C = A @ B^T
// Tile: BM=128, BN=64, BK=16; 256 threads; thread tile 8x4 (2 f32x2 col pairs).
// A is stored lane-duplicated in SMEM (ull) so the hot loop is LDS + FFMA2 only.
// EPI: 0 = plain (+bias if non-null)
//      1 = gates: v=sigmoid(v+bias); n<100 -> y1p=r*h ; n>=100 -> y2p=u
//      2 = cand : c=tanh(v+bias); C = u*h + (1-u)*c
// M must be a multiple of 128 (true for all call sites: 25600, 512).
// ---------------------------------------------------------------------------
template<int EPI, bool TRANSB>
__global__ void __launch_bounds__(256)
gemm_kernel(const float* __restrict__ A, const float* __restrict__ Bm,
            const float* __restrict__ bias, float* __restrict__ C,
            int M, int N, int K, int lda, int ldb, int ldc,
            const float* __restrict__ x1,   // EPI1/2: h
            const float* __restrict__ x2,   // EPI2:   u
            float* __restrict__ y1p,        // EPI1:   r*h out
            float* __restrict__ y2p)        // EPI1:   u out
{
    const int BM = 128, BN = 64, BK = 16;
    __shared__ ull   As2[BK][BM];   // 16 KB, value duplicated in both lanes
    __shared__ float Bs [BK][BN];   // 4 KB

    int tid = threadIdx.x;
    int tx  = tid & 15;             // N direction (16 * 4 cols)
    int ty  = tid >> 4;             // M direction (16 * 8 rows)
    int m0  = blockIdx.y * BM;
    int n0  = blockIdx.x * BN;

    // loader indices
    int alr = tid >> 1;             // 0..127 : A row
    int alk = (tid & 1) * 8;        // 0 or 8 : A k-offset
    int blk = tid >> 4;             // 0..15  : B k (non-trans)
    int bln = (tid & 15) * 4;       //        : B n (non-trans)
    int bnt = tid >> 2;             // 0..63  : B n (trans)
    int bkt = (tid & 3) * 4;        //        : B k (trans)

    ull acc[8][2];
    #pragma unroll
    for (int i = 0; i < 8; i++) { acc[i][0] = 0ULL; acc[i][1] = 0ULL; }

    for (int k0 = 0; k0 < K; k0 += BK) {
        // --- load A tile (transposed + lane-duplicated) ---
        const float* Arow = A + (size_t)(m0 + alr) * lda;
        #pragma unroll
        for (int j = 0; j < 8; j++) {
            int k = k0 + alk + j;
            float v = (k < K) ? Arow[k] : 0.0f;
            As2[alk + j][alr] = pack2(v, v);
        }
        // --- load B tile ---
        if (!TRANSB) {
            #pragma unroll
            for (int j = 0; j < 4; j++) {
                int k = k0 + blk, n = n0 + bln + j;
                Bs[blk][bln + j] = (k < K && n < N) ? Bm[(size_t)k * ldb + n] : 0.0f;
            }
        } else {
            const float* Brow = Bm + (size_t)(n0 + bnt) * ldb;
            bool nok = (n0 + bnt) < N;
            #pragma unroll
            for (int j = 0; j < 4; j++) {
                int k = k0 + bkt + j;
                Bs[bkt + j][bnt] = (nok && k < K) ? Brow[k] : 0.0f;
            }
        }
        __syncthreads();

        #pragma unroll
        for (int kk = 0; kk < BK; kk++) {
            const ull* bp = reinterpret_cast<const ull*>(&Bs[kk][tx * 4]);
            ull b0 = bp[0], b1 = bp[1];
            const ulonglong2* ap = reinterpret_cast<const ulonglong2*>(&As2[kk][ty * 8]);
            ulonglong2 a01 = ap[0], a23 = ap[1], a45 = ap[2], a67 = ap[3];
            ull av[8] = {a01.x, a01.y, a23.x, a23.y, a45.x, a45.y, a67.x, a67.y};
            #pragma unroll
            for (int i = 0; i < 8; i++) {
                fma2(acc[i][0], av[i], b0);
                fma2(acc[i][1], av[i], b1);
            }
        }
        __syncthreads();
    }

    // --- epilogue ---
    #pragma unroll
    for (int i = 0; i < 8; i++) {
        int gm = m0 + ty * 8 + i;
        if (gm >= M) continue;
        #pragma unroll
        for (int p = 0; p < 2; p++) {
            float v0, v1;
            unpack2(acc[i][p], v0, v1);
            int gn0 = n0 + tx * 4 + p * 2;
            float vs[2] = {v0, v1};
            #pragma unroll
            for (int q = 0; q < 2; q++) {
                int gn = gn0 + q;
                if (gn >= N) continue;
                float v = vs[q];
                if (EPI == 0) {
                    if (bias) v += bias[gn];
                    C[(size_t)gm * ldc + gn] = v;
                } else if (EPI == 1) {
                    float g = sigmoidf_(v + bias[gn]);
                    if (gn < Dd) {
                        y1p[(size_t)gm * Dd + gn] = g * x1[(size_t)gm * Dd + gn];
                    } else {
                        y2p[(size_t)gm * Dd + (gn - Dd)] = g;
                    }
                } else { // EPI == 2
                    float cc = tanhf(v + bias[gn]);
                    float uu = x2[(size_t)gm * Dd + gn];
                    float hh = x1[(size_t)gm * Dd + gn];
                    C[(size_t)gm * ldc + gn] = uu * hh + (1.0f - uu) * cc;
                }
            }
        }
    }
}

// ---------------------------------------------------------------------------
// K3: per-batch adjacency propagation  a[t,c] = sum_s adj[b,t,s] * hv[b,s,c]
// One block per batch; writes into g_X at column offset coloff.
// 2x4 register tile via f32x2.
// ---------------------------------------------------------------------------
__global__ void __launch_bounds__(256)
adj_kernel(const float* __restrict__ adj, const float* __restrict__ hv, int coloff)
{
    __shared__ float adjS[Tt*Tt];   // 10 KB
    __shared__ float hS[Tt*Dd];     // 20 KB
    int b = blockIdx.x;
    int tid = threadIdx.x;
    for (int i = tid; i < Tt*Tt; i += 256) adjS[i] = adj[(size_t)b*Tt*Tt + i];
    for (int i = tid; i < Tt*Dd; i += 256) hS[i]   = hv[(size_t)b*Tt*Dd + i];
    __syncthreads();

    // tasks: 25 t-pairs x 25 col-quads = 625
    for (int task = tid; task < 625; task += 256) {
        int tg = task / 25, cg = task - tg * 25;
        int t0 = tg * 2, c0 = cg * 4;
        ull a00 = 0, a01 = 0, a10 = 0, a11 = 0;
        #pragma unroll 5
        for (int s = 0; s < Tt; s++) {
            const ull* hp = reinterpret_cast<const ull*>(&hS[s * Dd + c0]);
            ull b0 = hp[0], b1 = hp[1];
            float w0 = adjS[t0 * Tt + s];
            float w1 = adjS[(t0 + 1) * Tt + s];
            ull p0 = pack2(w0, w0), p1 = pack2(w1, w1);
            fma2(a00, p0, b0); fma2(a01, p0, b1);
            fma2(a10, p1, b0); fma2(a11, p1, b1);
        }
        float o0, o1, o2, o3;
        size_t base0 = (size_t)(b * Tt + t0) * 300 + coloff + c0;
        unpack2(a00, o0, o1); unpack2(a01, o2, o3);
        g_X[base0 + 0] = o0; g_X[base0 + 1] = o1; g_X[base0 + 2] = o2; g_X[base0 + 3] = o3;
        size_t base1 = (size_t)(b * Tt + t0 + 1) * 300 + coloff + c0;
        unpack2(a10, o0, o1); unpack2(a11, o2, o3);
        g_X[base1 + 0] = o0; g_X[base1 + 1] = o1; g_X[base1 + 2] = o2; g_X[base1 + 3] = o3;
    }
}

// ---------------------------------------------------------------------------
// K5: splice r*h into g_X[:,200:300]
// ---------------------------------------------------------------------------
__global__ void splice_rh_kernel() {
    int i = blockIdx.x * 256 + threadIdx.x;
    if (i >= BT*Dd) return;
    int row = i / Dd;
    int c   = i - row * Dd;
    g_X[(size_t)row * 300 + 200 + c] = g_rh[i];
}

// ---------------------------------------------------------------------------
// K7a: per-batch last vector: rm=sum(mask); last_h=re_emb[b, alias[b,rm-1]];
//      g_last[b] = last_h @ nasr_w1
// ---------------------------------------------------------------------------
__global__ void last_kernel(const float* __restrict__ mask,
                            const int* __restrict__ alias_,
                            const float* __restrict__ w1)
{
    __shared__ float msum[Tt];
    __shared__ float lh[Dd];
    __shared__ int   liS;
    int b = blockIdx.x;
    int tid = threadIdx.x;
    if (tid < Tt) msum[tid] = mask[b * Tt + tid];
    __syncthreads();
    if (tid == 0) {
        float s = 0.0f;
        for (int t = 0; t < Tt; t++) s += msum[t];
        int rm = (int)s;
        liS = alias_[b * Tt + (rm - 1)];
    }
    __syncthreads();
    int li = liS;
    if (tid < Dd) lh[tid] = g_hnew[(size_t)(b * Tt + li) * Dd + tid];
    __syncthreads();
    if (tid < Dd) {
        float acc = 0.0f;
        #pragma unroll 4
        for (int k = 0; k < Dd; k++) acc += lh[k] * w1[k * Dd + tid];
        g_last[b * Dd + tid] = acc;
    }
}

// ---------------------------------------------------------------------------
// K7b: seq_h gather: g_seqh[b,t] = g_hnew[b, alias[b,t]]
// ---------------------------------------------------------------------------
__global__ void seqh_kernel(const int* __restrict__ alias_) {
    int i = blockIdx.x * 256 + threadIdx.x;
    if (i >= BT*Dd) return;
    int row = i / Dd;
    int c   = i - row * Dd;
    int b   = row / Tt;
    int al  = alias_[row];
    g_seqh[i] = g_hnew[(size_t)(b * Tt + al) * Dd + c];
}

// ---------------------------------------------------------------------------
// K9: per-batch attention + readout:
//   m = sigmoid(last + seq + nasr_b); coef = (m.v) * mask
//   ma = [sum_t coef*seq_h , last];  y1 = ma @ B_mat
// Warp-specialized over t (4 warps, shfl reductions, no per-t block syncs).
// ---------------------------------------------------------------------------
__global__ void __launch_bounds__(128)
att_kernel(const float* __restrict__ mask,
           const float* __restrict__ vv,     // nasr_v (100)
           const float* __restrict__ nb,     // nasr_b (100)
           const float* __restrict__ Bmat)   // (200,100)
{
    __shared__ float lastS[Dd], nbS[Dd], vS[Dd];
    __shared__ float acc4[4][Dd];
    __shared__ float maS[2 * Dd];
    int b = blockIdx.x;
    int tid = threadIdx.x;
    int w = tid >> 5, lane = tid & 31;

    if (tid < Dd) { lastS[tid] = g_last[b * Dd + tid]; nbS[tid] = nb[tid]; vS[tid] = vv[tid]; }
    __syncthreads();

    float accR[4] = {0.f, 0.f, 0.f, 0.f};
    for (int t = w; t < Tt; t += 4) {
        const float* seqrow = &g_seq [(size_t)(b * Tt + t) * Dd];
        const float* shrow  = &g_seqh[(size_t)(b * Tt + t) * Dd];
        float part = 0.0f;
        #pragma unroll
        for (int j = 0; j < 4; j++) {
            int c = lane + 32 * j;
            if (c < Dd) {
                float m = sigmoidf_(lastS[c] + seqrow[c] + nbS[c]);
                part += m * vS[c];
            }
        }
        #pragma unroll
        for (int off = 16; off > 0; off >>= 1)
            part += __shfl_xor_sync(0xffffffffu, part, off);
        float coef = part * mask[b * Tt + t];
        #pragma unroll
        for (int j = 0; j < 4; j++) {
            int c = lane + 32 * j;
            if (c < Dd) accR[j] += coef * shrow[c];
        }
    }
    #pragma unroll
    for (int j = 0; j < 4; j++) {
        int c = lane + 32 * j;
        if (c < Dd) acc4[w][c] = accR[j];
    }
    __syncthreads();
    if (tid < Dd) {
        maS[tid]      = acc4[0][tid] + acc4[1][tid] + acc4[2][tid] + acc4[3][tid];
        maS[Dd + tid] = lastS[tid];
    }
    __syncthreads();
    if (tid < Dd) {
        float y = 0.0f;
        #pragma unroll 4
        for (int k = 0; k < 2 * Dd; k++) y += maS[k] * Bmat[k * Dd + tid];
        g_y1[b * Dd + tid] = y;
    }
}

// ---------------------------------------------------------------------------
// Host launcher
// ---------------------------------------------------------------------------
static inline int cdiv(int a, int b) { return (a + b - 1) / b; }

extern "C" void kernel_launch(void* const* d_in, const int* in_sizes, int n_in,
                              void* d_out, int out_size)
{
    // Input order per metadata: adj_in, adj_out, mask, item, alias, step,
    // embedding, W_in, b_in, W_out, b_out, gru_gate_k, gru_gate_b,
    // gru_cand_k, gru_cand_b, nasr_w1, nasr_w2, nasr_v, nasr_b, B_mat.
    // Guard against the scalar `step` being omitted from the input list.
    int o = 0;
    if (n_in < 20 || in_sizes[5] != 1) o = -1;  // step missing -> shift tail down

    const float* adj_in  = (const float*)d_in[0];
    const float* adj_out = (const float*)d_in[1];
    const float* mask    = (const float*)d_in[2];
    const int*   item    = (const int*)  d_in[3];
    const int*   alias_  = (const int*)  d_in[4];
    const float* emb     = (const float*)d_in[6  + o];
    const float* W_in    = (const float*)d_in[7  + o];
    const float* b_in    = (const float*)d_in[8  + o];
    const float* W_out   = (const float*)d_in[9  + o];
    const float* b_out   = (const float*)d_in[10 + o];
    const float* ggk     = (const float*)d_in[11 + o];
    const float* ggb     = (const float*)d_in[12 + o];
    const float* gck     = (const float*)d_in[13 + o];
    const float* gcb     = (const float*)d_in[14 + o];
    const float* w1      = (const float*)d_in[15 + o];
    const float* w2      = (const float*)d_in[16 + o];
    const float* vv      = (const float*)d_in[17 + o];
    const float* nb      = (const float*)d_in[18 + o];
    const float* Bmat    = (const float*)d_in[19 + o];
    float* out = (float*)d_out;

    // Resolve scratch symbol addresses (host API, not stream-ordered: capture-safe)
    void *p;
    cudaGetSymbolAddress(&p, g_h);    float* ph    = (float*)p;
    cudaGetSymbolAddress(&p, g_hin);  float* phin  = (float*)p;
    cudaGetSymbolAddress(&p, g_hout); float* phout = (float*)p;
    cudaGetSymbolAddress(&p, g_X);    float* pX    = (float*)p;
    cudaGetSymbolAddress(&p, g_rh);   float* prh   = (float*)p;
    cudaGetSymbolAddress(&p, g_u);    float* pu    = (float*)p;
    cudaGetSymbolAddress(&p, g_hnew); float* phnew = (float*)p;
    cudaGetSymbolAddress(&p, g_seqh); float* pseqh = (float*)p;
    cudaGetSymbolAddress(&p, g_seq);  float* pseq  = (float*)p;
    cudaGetSymbolAddress(&p, g_y1);   float* py1   = (float*)p;

    const int EW = cdiv(BT * Dd, 256);   // elementwise grid (10000 blocks)

    // ---- GGNN (step = 1 in this dataset) ----
    gather_h_kernel<<<EW, 256>>>(emb, item);

    gemm_kernel<0, false><<<dim3(cdiv(Dd, 64), cdiv(BT, 128)), 256>>>(
        ph, W_in, b_in, phin, BT, Dd, Dd, Dd, Dd, Dd,
        nullptr, nullptr, nullptr, nullptr);
    gemm_kernel<0, false><<<dim3(cdiv(Dd, 64), cdiv(BT, 128)), 256>>>(
        ph, W_out, b_out, phout, BT, Dd, Dd, Dd, Dd, Dd,
        nullptr, nullptr, nullptr, nullptr);

    adj_kernel<<<Bb, 256>>>(adj_in,  phin,  0);
    adj_kernel<<<Bb, 256>>>(adj_out, phout, Dd);

    // gates = sigmoid(X @ ggk + ggb); r*h -> g_rh, u -> g_u
    gemm_kernel<1, false><<<dim3(cdiv(2 * Dd, 64), cdiv(BT, 128)), 256>>>(
        pX, ggk, ggb, nullptr, BT, 2 * Dd, 3 * Dd, 3 * Dd, 2 * Dd, 0,
        ph, nullptr, prh, pu);

    splice_rh_kernel<<<EW, 256>>>();

    // c = tanh(X' @ gck + gcb); h_new = u*h + (1-u)*c
    gemm_kernel<2, false><<<dim3(cdiv(Dd, 64), cdiv(BT, 128)), 256>>>(
        pX, gck, gcb, phnew, BT, Dd, 3 * Dd, 3 * Dd, Dd, Dd,
        ph, pu, nullptr, nullptr);

    // ---- attention readout ----
    last_kernel<<<Bb, 128>>>(mask, alias_, w1);
    seqh_kernel<<<EW, 256>>>(alias_);

    gemm_kernel<0, false><<<dim3(cdiv(Dd, 64), cdiv(BT, 128)), 256>>>(
        pseqh, w2, nullptr, pseq, BT, Dd, Dd, Dd, Dd, Dd,
        nullptr, nullptr, nullptr, nullptr);

    att_kernel<<<Bb, 128>>>(mask, vv, nb, Bmat);

    // ---- logits = y1 @ embedding[1:]^T  (512 x 99999 x 100) ----
    gemm_kernel<0, true><<<dim3(cdiv(NOUT, 64), cdiv(Bb, 128)), 256>>>(
        py1, emb + Dd, nullptr, out, Bb, NOUT, Dd, Dd, Dd, NOUT,
        nullptr, nullptr, nullptr, nullptr);
}

// round 10
// speedup vs baseline: 1.4670x; 1.4656x over previous
#include <cuda_runtime.h>
#include <cuda_bf16.h>
#include <cstdint>
#include <math.h>

// ---------------------------------------------------------------------------
// Problem constants
// ---------------------------------------------------------------------------
#define Bb   512
#define Tt   50
#define Dd   100
#define BT   (Bb*Tt)          // 25600
#define NN   100000
#define NOUT (NN-1)           // 99999
#define KP1  112              // padded K for d=100 operands (7 chunks of 16)
#define KP3  304              // padded K for 3d=300 operands (19 chunks)

typedef unsigned long long ull;

// ---------------------------------------------------------------------------
// helpers
// ---------------------------------------------------------------------------
__device__ __forceinline__ ull pack2(float x, float y) {
    ull r; asm("mov.b64 %0, {%1, %2};" : "=l"(r) : "f"(x), "f"(y)); return r;
}
__device__ __forceinline__ void unpack2(ull v, float& x, float& y) {
    asm("mov.b64 {%0, %1}, %2;" : "=f"(x), "=f"(y) : "l"(v));
}
__device__ __forceinline__ void fma2(ull& d, ull a, ull b) {
    asm("fma.rn.f32x2 %0, %1, %2, %3;" : "=l"(d) : "l"(a), "l"(b), "l"(d));
}
__device__ __forceinline__ float sigmoidf_(float x) { return 1.0f / (1.0f + expf(-x)); }

__device__ __forceinline__ void split_bf16(float x, __nv_bfloat16& hi, __nv_bfloat16& lo) {
    __nv_bfloat16 h = __float2bfloat16(x);
    hi = h;
    lo = __float2bfloat16(x - __bfloat162float(h));
}
__device__ __forceinline__ uint32_t smem_u32a(const void* p) {
    return (uint32_t)__cvta_generic_to_shared(p);
}
__device__ __forceinline__ void ldsm4(unsigned r[4], uint32_t a) {
    asm volatile("ldmatrix.sync.aligned.m8n8.x4.shared.b16 {%0,%1,%2,%3},[%4];"
                 : "=r"(r[0]), "=r"(r[1]), "=r"(r[2]), "=r"(r[3]) : "r"(a));
}
__device__ __forceinline__ void ldsm2(unsigned r[2], uint32_t a) {
    asm volatile("ldmatrix.sync.aligned.m8n8.x2.shared.b16 {%0,%1},[%2];"
                 : "=r"(r[0]), "=r"(r[1]) : "r"(a));
}
__device__ __forceinline__ void mma_bf16(float c[4], const unsigned a[4], const unsigned b[2]) {
    asm volatile("mma.sync.aligned.m16n8k16.row.col.f32.bf16.bf16.f32 "
                 "{%0,%1,%2,%3},{%4,%5,%6,%7},{%8,%9},{%0,%1,%2,%3};"
                 : "+f"(c[0]), "+f"(c[1]), "+f"(c[2]), "+f"(c[3])
                 : "r"(a[0]), "r"(a[1]), "r"(a[2]), "r"(a[3]), "r"(b[0]), "r"(b[1]));
}

// ---------------------------------------------------------------------------
// Scratch (static device globals)
// ---------------------------------------------------------------------------
__device__ float g_h   [BT*Dd];
__device__ float g_X   [BT*3*Dd];
__device__ float g_hio [BT*2*Dd];   // [hin | hout] per row (ldc=200)
__device__ float g_rh  [BT*Dd];
__device__ float g_u   [BT*Dd];
__device__ float g_hnew[BT*Dd];
__device__ float g_seqh[BT*Dd];
__device__ float g_seq [BT*Dd];
__device__ float g_last[Bb*Dd];
__device__ float g_y1  [Bb*Dd];
__device__ float g_bio [2*Dd];

// split-bf16 operands (hi/lo), k-major, k padded
__device__ __nv_bfloat16 g_eH[(size_t)NN*KP1],  g_eL[(size_t)NN*KP1];   // embedding
__device__ __nv_bfloat16 g_hH[BT*KP1],  g_hL[BT*KP1];                   // h
__device__ __nv_bfloat16 g_XH[BT*KP3],  g_XL[BT*KP3];                   // X
__device__ __nv_bfloat16 g_sH[BT*KP1],  g_sL[BT*KP1];                   // seq_h
__device__ __nv_bfloat16 g_yH[Bb*KP1],  g_yL[Bb*KP1];                   // y1
__device__ __nv_bfloat16 g_WioH[2*Dd*KP1], g_WioL[2*Dd*KP1];            // [W_in|W_out]^T
__device__ __nv_bfloat16 g_ggkH[2*Dd*KP3], g_ggkL[2*Dd*KP3];            // ggk^T
__device__ __nv_bfloat16 g_gckH[Dd*KP3],   g_gckL[Dd*KP3];              // gck^T
__device__ __nv_bfloat16 g_w2H[Dd*KP1],    g_w2L[Dd*KP1];               // w2^T

// ---------------------------------------------------------------------------
// Conversion / gather kernels
// ---------------------------------------------------------------------------
__global__ void conv_emb_kernel(const float* __restrict__ emb) {
    size_t i = (size_t)blockIdx.x * 256 + threadIdx.x;
    if (i >= (size_t)NN * KP1) return;
    size_t r = i / KP1; int k = (int)(i - r * KP1);
    float x = (k < Dd) ? emb[r * Dd + k] : 0.0f;
    split_bf16(x, g_eH[i], g_eL[i]);
}

// transpose+split: W[K][N] -> out[N][KP]
__global__ void conv_wT_kernel(const float* __restrict__ W,
                               __nv_bfloat16* __restrict__ oh, __nv_bfloat16* __restrict__ ol,
                               int K, int N, int KPp) {
    int i = blockIdx.x * 256 + threadIdx.x;
    if (i >= N * KPp) return;
    int n = i / KPp, k = i - n * KPp;
    float x = (k < K) ? W[k * N + n] : 0.0f;
    split_bf16(x, oh[i], ol[i]);
}

__global__ void conv_wio_kernel(const float* __restrict__ W_in, const float* __restrict__ W_out,
                                const float* __restrict__ b_in, const float* __restrict__ b_out) {
    int i = blockIdx.x * 256 + threadIdx.x;
    if (i >= 2 * Dd * KP1) return;
    int n = i / KP1, k = i - n * KP1;
    float x = 0.0f;
    if (k < Dd) x = (n < Dd) ? W_in[k * Dd + n] : W_out[k * Dd + (n - Dd)];
    split_bf16(x, g_WioH[i], g_WioL[i]);
    if (i < 2 * Dd) g_bio[i] = (i < Dd) ? b_in[i] : b_out[i - Dd];
}

__global__ void gather_h_kernel(const float* __restrict__ emb, const int* __restrict__ item) {
    int i = blockIdx.x * 256 + threadIdx.x;
    if (i >= BT * KP1) return;
    int r = i / KP1, k = i - r * KP1;
    float x = 0.0f;
    if (k < Dd) {
        x = emb[(size_t)item[r] * Dd + k];
        g_h[r * Dd + k] = x;
        g_X[(size_t)r * 300 + 200 + k] = x;
    }
    split_bf16(x, g_hH[i], g_hL[i]);
}

__global__ void conv_X_kernel() {
    int i = blockIdx.x * 256 + threadIdx.x;
    if (i >= BT * KP3) return;
    int r = i / KP3, k = i - r * KP3;
    float x = (k < 300) ? g_X[(size_t)r * 300 + k] : 0.0f;
    split_bf16(x, g_XH[i], g_XL[i]);
}

__global__ void splice_rh_kernel() {
    int i = blockIdx.x * 256 + threadIdx.x;
    if (i >= BT * Dd) return;
    int r = i / Dd, k = i - r * Dd;
    size_t o = (size_t)r * KP3 + 200 + k;
    split_bf16(g_rh[i], g_XH[o], g_XL[o]);
}

__global__ void seqh_kernel(const int* __restrict__ alias_) {
    int i = blockIdx.x * 256 + threadIdx.x;
    if (i >= BT * KP1) return;
    int r = i / KP1, k = i - r * KP1;
    float x = 0.0f;
    if (k < Dd) {
        int b = r / Tt;
        int al = alias_[r];
        x = g_hnew[(size_t)(b * Tt + al) * Dd + k];
        g_seqh[r * Dd + k] = x;
    }
    split_bf16(x, g_sH[i], g_sL[i]);
}

__global__ void conv_y1_kernel() {
    int i = blockIdx.x * 256 + threadIdx.x;
    if (i >= Bb * KP1) return;
    int r = i / KP1, k = i - r * KP1;
    float x = (k < Dd) ? g_y1[r * Dd + k] : 0.0f;
    split_bf16(x, g_yH[i], g_yL[i]);
}

// ---------------------------------------------------------------------------
// Split-bf16 tensor-core GEMM: C[M,N] = epi(A @ B^T + bias)
// A: hi/lo bf16 [M][KP] (M multiple of 128). B: hi/lo bf16 [N][KP] (k-major).
// Block tile 128x128, 8 warps (2x4), warp tile 64x32, mma m16n8k16.
// 3-term split: Ah*Bh + Ah*Bl + Al*Bh.
// EPI: 0 plain(+bias), 1 gates(sigmoid->r*h,u), 2 cand(tanh->GRU update)
// ---------------------------------------------------------------------------
template<int EPI>
__global__ void __launch_bounds__(256, 1)
mma_gemm(const __nv_bfloat16* __restrict__ Ahi, const __nv_bfloat16* __restrict__ Alo,
         const __nv_bfloat16* __restrict__ Bhi, const __nv_bfloat16* __restrict__ Blo,
         const float* __restrict__ bias, float* __restrict__ C,
         int N, int KPp, int ldc,
         const float* __restrict__ x1, const float* __restrict__ x2,
         float* __restrict__ y1p, float* __restrict__ y2p)
{
    __shared__ __align__(16) __nv_bfloat16 sAh[128*24], sAl[128*24], sBh[128*24], sBl[128*24];
    const int tid = threadIdx.x, lane = tid & 31, warp = tid >> 5;
    const int wm = warp >> 2, wn = warp & 3;
    const int m0 = blockIdx.y * 128, n0 = blockIdx.x * 128;

    const int lrow = tid >> 1, lhalf = tid & 1;
    const size_t aoff = (size_t)(m0 + lrow) * KPp + lhalf * 8;
    int br = n0 + lrow; if (br >= N) br = N - 1;      // clamp (zero A-pad kills bogus terms)
    const size_t boff = (size_t)br * KPp + lhalf * 8;
    const int sdst = lrow * 24 + lhalf * 8;

    const uint32_t arow = ((wm * 64 + (lane & 15)) * 48) + ((lane >> 4) * 16);
    const uint32_t brow = ((wn * 32 + (lane & 7)) * 48) + (((lane >> 3) & 1) * 16);
    const uint32_t aBaseH = smem_u32a(sAh) + arow;
    const uint32_t aBaseL = smem_u32a(sAl) + arow;
    const uint32_t bBaseH = smem_u32a(sBh) + brow;
    const uint32_t bBaseL = smem_u32a(sBl) + brow;

    float acc[4][4][4];
    #pragma unroll
    for (int i = 0; i < 4; i++)
        #pragma unroll
        for (int j = 0; j < 4; j++)
            #pragma unroll
            for (int e = 0; e < 4; e++) acc[i][j][e] = 0.0f;

    for (int k0 = 0; k0 < KPp; k0 += 16) {
        *(uint4*)(sAh + sdst) = *(const uint4*)(Ahi + aoff + k0);
        *(uint4*)(sAl + sdst) = *(const uint4*)(Alo + aoff + k0);
        *(uint4*)(sBh + sdst) = *(const uint4*)(Bhi + boff + k0);
        *(uint4*)(sBl + sdst) = *(const uint4*)(Blo + boff + k0);
        __syncthreads();

        unsigned Af[4][4], Bf[4][2];
        // Ah * Bh
        #pragma unroll
        for (int mf = 0; mf < 4; mf++) ldsm4(Af[mf], aBaseH + mf * 768);
        #pragma unroll
        for (int nf = 0; nf < 4; nf++) ldsm2(Bf[nf], bBaseH + nf * 384);
        #pragma unroll
        for (int mf = 0; mf < 4; mf++)
            #pragma unroll
            for (int nf = 0; nf < 4; nf++) mma_bf16(acc[mf][nf], Af[mf], Bf[nf]);
        // Ah * Bl (reuse A frags)
        #pragma unroll
        for (int nf = 0; nf < 4; nf++) ldsm2(Bf[nf], bBaseL + nf * 384);
        #pragma unroll
        for (int mf = 0; mf < 4; mf++)
            #pragma unroll
            for (int nf = 0; nf < 4; nf++) mma_bf16(acc[mf][nf], Af[mf], Bf[nf]);
        // Al * Bh
        #pragma unroll
        for (int mf = 0; mf < 4; mf++) ldsm4(Af[mf], aBaseL + mf * 768);
        #pragma unroll
        for (int nf = 0; nf < 4; nf++) ldsm2(Bf[nf], bBaseH + nf * 384);
        #pragma unroll
        for (int mf = 0; mf < 4; mf++)
            #pragma unroll
            for (int nf = 0; nf < 4; nf++) mma_bf16(acc[mf][nf], Af[mf], Bf[nf]);
        __syncthreads();
    }

    const int gID = lane >> 2, tg = lane & 3;
    #pragma unroll
    for (int mf = 0; mf < 4; mf++) {
        const int gmb = m0 + wm * 64 + mf * 16 + gID;
        #pragma unroll
        for (int nf = 0; nf < 4; nf++) {
            const int gnb = n0 + wn * 32 + nf * 8 + tg * 2;
            #pragma unroll
            for (int e = 0; e < 4; e++) {
                int gm = gmb + (e >> 1) * 8;
                int gn = gnb + (e & 1);
                if (gn >= N) continue;
                float v = acc[mf][nf][e];
                if (EPI == 0) {
                    if (bias) v += bias[gn];
                    C[(size_t)gm * ldc + gn] = v;
                } else if (EPI == 1) {
                    float g = sigmoidf_(v + bias[gn]);
                    if (gn < Dd) y1p[(size_t)gm * Dd + gn] = g * x1[(size_t)gm * Dd + gn];
                    else         y2p[(size_t)gm * Dd + (gn - Dd)] = g;
                } else {
                    float cc = tanhf(v + bias[gn]);
                    float uu = x2[(size_t)gm * Dd + gn];
                    float hh = x1[(size_t)gm * Dd + gn];
                    C[(size_t)gm * ldc + gn] = uu * hh + (1.0f - uu) * cc;
                }
            }
        }
    }
}

// ---------------------------------------------------------------------------
// adj propagation, both directions in one launch: grid (512, 2)
//   a[t,c] = sum_s adj[b,t,s] * hio[b,s, off+c] -> g_X[:, off+c]
// ---------------------------------------------------------------------------
__global__ void __launch_bounds__(256)
adj_both_kernel(const float* __restrict__ adj_in, const float* __restrict__ adj_out)
{
    __shared__ float adjS[Tt*Tt];
    __shared__ float hS[Tt*Dd];
    int b = blockIdx.x, io = blockIdx.y;
    const float* adj = io ? adj_out : adj_in;
    int off = io * Dd;
    int tid = threadIdx.x;
    for (int i = tid; i < Tt*Tt; i += 256) adjS[i] = adj[(size_t)b*Tt*Tt + i];
    for (int i = tid; i < Tt*Dd; i += 256) {
        int s = i / Dd, c = i - s * Dd;
        hS[i] = g_hio[(size_t)(b*Tt + s) * 200 + off + c];
    }
    __syncthreads();

    for (int task = tid; task < 625; task += 256) {
        int tg = task / 25, cg = task - tg * 25;
        int t0 = tg * 2, c0 = cg * 4;
        ull a00=0, a01=0, a10=0, a11=0;   // even s
        ull e00=0, e01=0, e10=0, e11=0;   // odd s
        #pragma unroll 5
        for (int s = 0; s < Tt; s += 2) {
            const ull* hp = reinterpret_cast<const ull*>(&hS[s * Dd + c0]);
            ull b0 = hp[0], b1 = hp[1];
            float w0 = adjS[t0 * Tt + s], w1 = adjS[(t0+1) * Tt + s];
            ull p0 = pack2(w0, w0), p1 = pack2(w1, w1);
            fma2(a00, p0, b0); fma2(a01, p0, b1);
            fma2(a10, p1, b0); fma2(a11, p1, b1);
            const ull* hq = reinterpret_cast<const ull*>(&hS[(s+1) * Dd + c0]);
            ull c0v = hq[0], c1v = hq[1];
            float v0 = adjS[t0 * Tt + s + 1], v1 = adjS[(t0+1) * Tt + s + 1];
            ull q0 = pack2(v0, v0), q1 = pack2(v1, v1);
            fma2(e00, q0, c0v); fma2(e01, q0, c1v);
            fma2(e10, q1, c0v); fma2(e11, q1, c1v);
        }
        float x0,x1,x2,x3,y0,y1,y2,y3;
        size_t base0 = (size_t)(b*Tt + t0) * 300 + off + c0;
        unpack2(a00,x0,x1); unpack2(a01,x2,x3);
        unpack2(e00,y0,y1); unpack2(e01,y2,y3);
        g_X[base0+0]=x0+y0; g_X[base0+1]=x1+y1; g_X[base0+2]=x2+y2; g_X[base0+3]=x3+y3;
        size_t base1 = (size_t)(b*Tt + t0 + 1) * 300 + off + c0;
        unpack2(a10,x0,x1); unpack2(a11,x2,x3);
        unpack2(e10,y0,y1); unpack2(e11,y2,y3);
        g_X[base1+0]=x0+y0; g_X[base1+1]=x1+y1; g_X[base1+2]=x2+y2; g_X[base1+3]=x3+y3;
    }
}

// ---------------------------------------------------------------------------
// last vector: rm=sum(mask); last_h = re_emb[b, alias[b,rm-1]]; g_last = last_h @ w1
// ---------------------------------------------------------------------------
__global__ void last_kernel(const float* __restrict__ mask,
                            const int* __restrict__ alias_,
                            const float* __restrict__ w1)
{
    __shared__ float msum[Tt];
    __shared__ float lh[Dd];
    __shared__ int   liS;
    int b = blockIdx.x, tid = threadIdx.x;
    if (tid < Tt) msum[tid] = mask[b * Tt + tid];
    __syncthreads();
    if (tid == 0) {
        float s = 0.0f;
        for (int t = 0; t < Tt; t++) s += msum[t];
        liS = alias_[b * Tt + ((int)s - 1)];
    }
    __syncthreads();
    int li = liS;
    if (tid < Dd) lh[tid] = g_hnew[(size_t)(b * Tt + li) * Dd + tid];
    __syncthreads();
    if (tid < Dd) {
        float acc = 0.0f;
        #pragma unroll 4
        for (int k = 0; k < Dd; k++) acc += lh[k] * w1[k * Dd + tid];
        g_last[b * Dd + tid] = acc;
    }
}

// ---------------------------------------------------------------------------
// attention + readout
// ---------------------------------------------------------------------------
__global__ void __launch_bounds__(128)
att_kernel(const float* __restrict__ mask, const float* __restrict__ vv,
           const float* __restrict__ nb, const float* __restrict__ Bmat)
{
    __shared__ float lastS[Dd], nbS[Dd], vS[Dd];
    __shared__ float acc4[4][Dd];
    __shared__ float maS[2 * Dd];
    int b = blockIdx.x, tid = threadIdx.x;
    int w = tid >> 5, lane = tid & 31;

    if (tid < Dd) { lastS[tid] = g_last[b * Dd + tid]; nbS[tid] = nb[tid]; vS[tid] = vv[tid]; }
    __syncthreads();

    float accR[4] = {0.f, 0.f, 0.f, 0.f};
    for (int t = w; t < Tt; t += 4) {
        const float* seqrow = &g_seq [(size_t)(b * Tt + t) * Dd];
        const float* shrow  = &g_seqh[(size_t)(b * Tt + t) * Dd];
        float part = 0.0f;
        #pragma unroll
        for (int j = 0; j < 4; j++) {
            int c = lane + 32 * j;
            if (c < Dd) part += sigmoidf_(lastS[c] + seqrow[c] + nbS[c]) * vS[c];
        }
        #pragma unroll
        for (int off = 16; off > 0; off >>= 1)
            part += __shfl_xor_sync(0xffffffffu, part, off);
        float coef = part * mask[b * Tt + t];
        #pragma unroll
        for (int j = 0; j < 4; j++) {
            int c = lane + 32 * j;
            if (c < Dd) accR[j] += coef * shrow[c];
        }
    }
    #pragma unroll
    for (int j = 0; j < 4; j++) {
        int c = lane + 32 * j;
        if (c < Dd) acc4[w][c] = accR[j];
    }
    __syncthreads();
    if (tid < Dd) {
        maS[tid]      = acc4[0][tid] + acc4[1][tid] + acc4[2][tid] + acc4[3][tid];
        maS[Dd + tid] = lastS[tid];
    }
    __syncthreads();
    if (tid < Dd) {
        float y = 0.0f;
        #pragma unroll 4
        for (int k = 0; k < 2 * Dd; k++) y += maS[k] * Bmat[k * Dd + tid];
        g_y1[b * Dd + tid] = y;
    }
}

// ---------------------------------------------------------------------------
// Host launcher
// ---------------------------------------------------------------------------
static inline int cdiv(int a, int b) { return (a + b - 1) / b; }

extern "C" void kernel_launch(void* const* d_in, const int* in_sizes, int n_in,
                              void* d_out, int out_size)
{
    int o = 0;
    if (n_in < 20 || in_sizes[5] != 1) o = -1;  // step scalar possibly omitted

    const float* adj_in  = (const float*)d_in[0];
    const float* adj_out = (const float*)d_in[1];
    const float* mask    = (const float*)d_in[2];
    const int*   item    = (const int*)  d_in[3];
    const int*   alias_  = (const int*)  d_in[4];
    const float* emb     = (const float*)d_in[6  + o];
    const float* W_in    = (const float*)d_in[7  + o];
    const float* b_in    = (const float*)d_in[8  + o];
    const float* W_out   = (const float*)d_in[9  + o];
    const float* b_out   = (const float*)d_in[10 + o];
    const float* ggk     = (const float*)d_in[11 + o];
    const float* ggb     = (const float*)d_in[12 + o];
    const float* gck     = (const float*)d_in[13 + o];
    const float* gcb     = (const float*)d_in[14 + o];
    const float* w1      = (const float*)d_in[15 + o];
    const float* w2      = (const float*)d_in[16 + o];
    const float* vv      = (const float*)d_in[17 + o];
    const float* nb      = (const float*)d_in[18 + o];
    const float* Bmat    = (const float*)d_in[19 + o];
    float* out = (float*)d_out;

    void* p;
    #define SYM(T, var, sym) cudaGetSymbolAddress(&p, sym); T* var = (T*)p
    SYM(float, ph,    g_h);    SYM(float, phio,  g_hio);
    SYM(float, prh,   g_rh);   SYM(float, pu,    g_u);
    SYM(float, phnew, g_hnew); SYM(float, pseq,  g_seq);
    SYM(float, pbio,  g_bio);  SYM(float, py1,   g_y1);
    (void)py1;
    SYM(__nv_bfloat16, peH, g_eH);   SYM(__nv_bfloat16, peL, g_eL);
    SYM(__nv_bfloat16, phH, g_hH);   SYM(__nv_bfloat16, phL, g_hL);
    SYM(__nv_bfloat16, pXH, g_XH);   SYM(__nv_bfloat16, pXL, g_XL);
    SYM(__nv_bfloat16, psH, g_sH);   SYM(__nv_bfloat16, psL, g_sL);
    SYM(__nv_bfloat16, pyH, g_yH);   SYM(__nv_bfloat16, pyL, g_yL);
    SYM(__nv_bfloat16, pWioH, g_WioH); SYM(__nv_bfloat16, pWioL, g_WioL);
    SYM(__nv_bfloat16, pggkH, g_ggkH); SYM(__nv_bfloat16, pggkL, g_ggkL);
    SYM(__nv_bfloat16, pgckH, g_gckH); SYM(__nv_bfloat16, pgckL, g_gckL);
    SYM(__nv_bfloat16, pw2H, g_w2H);   SYM(__nv_bfloat16, pw2L, g_w2L);
    #undef SYM

    // ---- operand conversions ----
    conv_emb_kernel<<<cdiv(NN * KP1, 256), 256>>>(emb);
    conv_wio_kernel<<<cdiv(2 * Dd * KP1, 256), 256>>>(W_in, W_out, b_in, b_out);
    conv_wT_kernel<<<cdiv(2 * Dd * KP3, 256), 256>>>(ggk, pggkH, pggkL, 3 * Dd, 2 * Dd, KP3);
    conv_wT_kernel<<<cdiv(Dd * KP3, 256), 256>>>(gck, pgckH, pgckL, 3 * Dd, Dd, KP3);
    conv_wT_kernel<<<cdiv(Dd * KP1, 256), 256>>>(w2, pw2H, pw2L, Dd, Dd, KP1);

    // ---- GGNN (step = 1) ----
    gather_h_kernel<<<cdiv(BT * KP1, 256), 256>>>(emb, item);

    // [hin | hout] = h @ [W_in | W_out] + [b_in | b_out]
    mma_gemm<0><<<dim3(2, BT / 128), 256>>>(phH, phL, pWioH, pWioL, pbio, phio,
                                            2 * Dd, KP1, 2 * Dd,
                                            nullptr, nullptr, nullptr, nullptr);
    adj_both_kernel<<<dim3(Bb, 2), 256>>>(adj_in, adj_out);
    conv_X_kernel<<<cdiv(BT * KP3, 256), 256>>>();

    // gates = sigmoid(X @ ggk + ggb) -> r*h, u
    mma_gemm<1><<<dim3(2, BT / 128), 256>>>(pXH, pXL, pggkH, pggkL, ggb, nullptr,
                                            2 * Dd, KP3, 0,
                                            ph, nullptr, prh, pu);
    splice_rh_kernel<<<cdiv(BT * Dd, 256), 256>>>();

    // c = tanh(X' @ gck + gcb); h_new = u*h + (1-u)*c
    mma_gemm<2><<<dim3(1, BT / 128), 256>>>(pXH, pXL, pgckH, pgckL, gcb, phnew,
                                            Dd, KP3, Dd,
                                            ph, pu, nullptr, nullptr);

    // ---- attention readout ----
    last_kernel<<<Bb, 128>>>(mask, alias_, w1);
    seqh_kernel<<<cdiv(BT * KP1, 256), 256>>>(alias_);

    mma_gemm<0><<<dim3(1, BT / 128), 256>>>(psH, psL, pw2H, pw2L, nullptr, pseq,
                                            Dd, KP1, Dd,
                                            nullptr, nullptr, nullptr, nullptr);

    att_kernel<<<Bb, 128>>>(mask, vv, nb, Bmat);
    conv_y1_kernel<<<cdiv(Bb * KP1, 256), 256>>>();

    // ---- logits = y1 @ embedding[1:]^T ----
    mma_gemm<0><<<dim3(cdiv(NOUT, 128), Bb / 128), 256>>>(
        pyH, pyL, peH + KP1, peL + KP1, nullptr, out,
        NOUT, KP1, NOUT,
        nullptr, nullptr, nullptr, nullptr);
}

// round 11
// speedup vs baseline: 1.4693x; 1.0015x over previous
#include <cuda_runtime.h>
#include <cuda_bf16.h>
#include <cstdint>
#include <math.h>

// ---------------------------------------------------------------------------
// Problem constants
// ---------------------------------------------------------------------------
#define Bb   512
#define Tt   50
#define Dd   100
#define BT   (Bb*Tt)          // 25600
#define NN   100000
#define NOUT (NN-1)           // 99999
#define KP1  112              // padded K for d=100 operands (7 chunks of 16)
#define KP3  304              // padded K for 3d=300 operands (19 chunks)

typedef unsigned long long ull;

// ---------------------------------------------------------------------------
// helpers
// ---------------------------------------------------------------------------
__device__ __forceinline__ ull pack2(float x, float y) {
    ull r; asm("mov.b64 %0, {%1, %2};" : "=l"(r) : "f"(x), "f"(y)); return r;
}
__device__ __forceinline__ void unpack2(ull v, float& x, float& y) {
    asm("mov.b64 {%0, %1}, %2;" : "=f"(x), "=f"(y) : "l"(v));
}
__device__ __forceinline__ void fma2(ull& d, ull a, ull b) {
    asm("fma.rn.f32x2 %0, %1, %2, %3;" : "=l"(d) : "l"(a), "l"(b), "l"(d));
}
__device__ __forceinline__ float sigmoidf_(float x) { return 1.0f / (1.0f + expf(-x)); }

__device__ __forceinline__ void split_bf16(float x, __nv_bfloat16& hi, __nv_bfloat16& lo) {
    __nv_bfloat16 h = __float2bfloat16(x);
    hi = h;
    lo = __float2bfloat16(x - __bfloat162float(h));
}
__device__ __forceinline__ uint32_t smem_u32a(const void* p) {
    return (uint32_t)__cvta_generic_to_shared(p);
}
__device__ __forceinline__ void ldsm4(unsigned r[4], uint32_t a) {
    asm volatile("ldmatrix.sync.aligned.m8n8.x4.shared.b16 {%0,%1,%2,%3},[%4];"
                 : "=r"(r[0]), "=r"(r[1]), "=r"(r[2]), "=r"(r[3]) : "r"(a));
}
__device__ __forceinline__ void ldsm2(unsigned r[2], uint32_t a) {
    asm volatile("ldmatrix.sync.aligned.m8n8.x2.shared.b16 {%0,%1},[%2];"
                 : "=r"(r[0]), "=r"(r[1]) : "r"(a));
}
__device__ __forceinline__ void mma_bf16(float c[4], const unsigned a[4], const unsigned b[2]) {
    asm volatile("mma.sync.aligned.m16n8k16.row.col.f32.bf16.bf16.f32 "
                 "{%0,%1,%2,%3},{%4,%5,%6,%7},{%8,%9},{%0,%1,%2,%3};"
                 : "+f"(c[0]), "+f"(c[1]), "+f"(c[2]), "+f"(c[3])
                 : "r"(a[0]), "r"(a[1]), "r"(a[2]), "r"(a[3]), "r"(b[0]), "r"(b[1]));
}

// ---------------------------------------------------------------------------
// Scratch (static device globals)
// ---------------------------------------------------------------------------
__device__ float g_h   [BT*Dd];
__device__ float g_X   [BT*3*Dd];
__device__ float g_hio [BT*2*Dd];   // [hin | hout] per row (ldc=200)
__device__ float g_rh  [BT*Dd];
__device__ float g_u   [BT*Dd];
__device__ float g_hnew[BT*Dd];
__device__ float g_seqh[BT*Dd];
__device__ float g_seq [BT*Dd];
__device__ float g_last[Bb*Dd];
__device__ float g_y1  [Bb*Dd];
__device__ float g_bio [2*Dd];

// split-bf16 operands (hi/lo), k-major, k padded
__device__ __nv_bfloat16 g_eH[(size_t)NN*KP1],  g_eL[(size_t)NN*KP1];   // embedding
__device__ __nv_bfloat16 g_hH[BT*KP1],  g_hL[BT*KP1];                   // h
__device__ __nv_bfloat16 g_XH[BT*KP3],  g_XL[BT*KP3];                   // X
__device__ __nv_bfloat16 g_sH[BT*KP1],  g_sL[BT*KP1];                   // seq_h
__device__ __nv_bfloat16 g_yH[Bb*KP1],  g_yL[Bb*KP1];                   // y1
__device__ __nv_bfloat16 g_WioH[2*Dd*KP1], g_WioL[2*Dd*KP1];            // [W_in|W_out]^T
__device__ __nv_bfloat16 g_ggkH[2*Dd*KP3], g_ggkL[2*Dd*KP3];            // ggk^T
__device__ __nv_bfloat16 g_gckH[Dd*KP3],   g_gckL[Dd*KP3];              // gck^T
__device__ __nv_bfloat16 g_w2H[Dd*KP1],    g_w2L[Dd*KP1];               // w2^T

// ---------------------------------------------------------------------------
// Conversion / gather kernels
// ---------------------------------------------------------------------------
__global__ void conv_emb_kernel(const float* __restrict__ emb) {
    size_t i = (size_t)blockIdx.x * 256 + threadIdx.x;
    if (i >= (size_t)NN * KP1) return;
    size_t r = i / KP1; int k = (int)(i - r * KP1);
    float x = (k < Dd) ? emb[r * Dd + k] : 0.0f;
    split_bf16(x, g_eH[i], g_eL[i]);
}

// transpose+split: W[K][N] -> out[N][KP]
__global__ void conv_wT_kernel(const float* __restrict__ W,
                               __nv_bfloat16* __restrict__ oh, __nv_bfloat16* __restrict__ ol,
                               int K, int N, int KPp) {
    int i = blockIdx.x * 256 + threadIdx.x;
    if (i >= N * KPp) return;
    int n = i / KPp, k = i - n * KPp;
    float x = (k < K) ? W[k * N + n] : 0.0f;
    split_bf16(x, oh[i], ol[i]);
}

__global__ void conv_wio_kernel(const float* __restrict__ W_in, const float* __restrict__ W_out,
                                const float* __restrict__ b_in, const float* __restrict__ b_out) {
    int i = blockIdx.x * 256 + threadIdx.x;
    if (i >= 2 * Dd * KP1) return;
    int n = i / KP1, k = i - n * KP1;
    float x = 0.0f;
    if (k < Dd) x = (n < Dd) ? W_in[k * Dd + n] : W_out[k * Dd + (n - Dd)];
    split_bf16(x, g_WioH[i], g_WioL[i]);
    if (i < 2 * Dd) g_bio[i] = (i < Dd) ? b_in[i] : b_out[i - Dd];
}

__global__ void gather_h_kernel(const float* __restrict__ emb, const int* __restrict__ item) {
    int i = blockIdx.x * 256 + threadIdx.x;
    if (i >= BT * KP1) return;
    int r = i / KP1, k = i - r * KP1;
    float x = 0.0f;
    if (k < Dd) {
        x = emb[(size_t)item[r] * Dd + k];
        g_h[r * Dd + k] = x;
        g_X[(size_t)r * 300 + 200 + k] = x;
    }
    split_bf16(x, g_hH[i], g_hL[i]);
}

__global__ void conv_X_kernel() {
    int i = blockIdx.x * 256 + threadIdx.x;
    if (i >= BT * KP3) return;
    int r = i / KP3, k = i - r * KP3;
    float x = (k < 300) ? g_X[(size_t)r * 300 + k] : 0.0f;
    split_bf16(x, g_XH[i], g_XL[i]);
}

__global__ void splice_rh_kernel() {
    int i = blockIdx.x * 256 + threadIdx.x;
    if (i >= BT * Dd) return;
    int r = i / Dd, k = i - r * Dd;
    size_t o = (size_t)r * KP3 + 200 + k;
    split_bf16(g_rh[i], g_XH[o], g_XL[o]);
}

__global__ void seqh_kernel(const int* __restrict__ alias_) {
    int i = blockIdx.x * 256 + threadIdx.x;
    if (i >= BT * KP1) return;
    int r = i / KP1, k = i - r * KP1;
    float x = 0.0f;
    if (k < Dd) {
        int b = r / Tt;
        int al = alias_[r];
        x = g_hnew[(size_t)(b * Tt + al) * Dd + k];
        g_seqh[r * Dd + k] = x;
    }
    split_bf16(x, g_sH[i], g_sL[i]);
}

__global__ void conv_y1_kernel() {
    int i = blockIdx.x * 256 + threadIdx.x;
    if (i >= Bb * KP1) return;
    int r = i / KP1, k = i - r * KP1;
    float x = (k < Dd) ? g_y1[r * Dd + k] : 0.0f;
    split_bf16(x, g_yH[i], g_yL[i]);
}

// ---------------------------------------------------------------------------
// Split-bf16 tensor-core GEMM: C[M,N] = epi(A @ B^T + bias)
// A: hi/lo bf16 [M][KP] (M multiple of 128). B: hi/lo bf16 [N][KP] (k-major).
// Block tile 128x128, 8 warps (2x4), warp tile 64x32, mma m16n8k16.
// 3-term split: Ah*Bh + Ah*Bl + Al*Bh.
// EPI: 0 plain(+bias), 1 gates(sigmoid->r*h,u), 2 cand(tanh->GRU update)
// ---------------------------------------------------------------------------
template<int EPI>
__global__ void __launch_bounds__(256, 1)
mma_gemm(const __nv_bfloat16* __restrict__ Ahi, const __nv_bfloat16* __restrict__ Alo,
         const __nv_bfloat16* __restrict__ Bhi, const __nv_bfloat16* __restrict__ Blo,
         const float* __restrict__ bias, float* __restrict__ C,
         int N, int KPp, int ldc,
         const float* __restrict__ x1, const float* __restrict__ x2,
         float* __restrict__ y1p, float* __restrict__ y2p)
{
    __shared__ __align__(16) __nv_bfloat16 sAh[128*24], sAl[128*24], sBh[128*24], sBl[128*24];
    const int tid = threadIdx.x, lane = tid & 31, warp = tid >> 5;
    const int wm = warp >> 2, wn = warp & 3;
    const int m0 = blockIdx.y * 128, n0 = blockIdx.x * 128;

    const int lrow = tid >> 1, lhalf = tid & 1;
    const size_t aoff = (size_t)(m0 + lrow) * KPp + lhalf * 8;
    int br = n0 + lrow; if (br >= N) br = N - 1;      // clamp (zero A-pad kills bogus terms)
    const size_t boff = (size_t)br * KPp + lhalf * 8;
    const int sdst = lrow * 24 + lhalf * 8;

    const uint32_t arow = ((wm * 64 + (lane & 15)) * 48) + ((lane >> 4) * 16);
    const uint32_t brow = ((wn * 32 + (lane & 7)) * 48) + (((lane >> 3) & 1) * 16);
    const uint32_t aBaseH = smem_u32a(sAh) + arow;
    const uint32_t aBaseL = smem_u32a(sAl) + arow;
    const uint32_t bBaseH = smem_u32a(sBh) + brow;
    const uint32_t bBaseL = smem_u32a(sBl) + brow;

    float acc[4][4][4];
    #pragma unroll
    for (int i = 0; i < 4; i++)
        #pragma unroll
        for (int j = 0; j < 4; j++)
            #pragma unroll
            for (int e = 0; e < 4; e++) acc[i][j][e] = 0.0f;

    for (int k0 = 0; k0 < KPp; k0 += 16) {
        *(uint4*)(sAh + sdst) = *(const uint4*)(Ahi + aoff + k0);
        *(uint4*)(sAl + sdst) = *(const uint4*)(Alo + aoff + k0);
        *(uint4*)(sBh + sdst) = *(const uint4*)(Bhi + boff + k0);
        *(uint4*)(sBl + sdst) = *(const uint4*)(Blo + boff + k0);
        __syncthreads();

        unsigned Af[4][4], Bf[4][2];
        // Ah * Bh
        #pragma unroll
        for (int mf = 0; mf < 4; mf++) ldsm4(Af[mf], aBaseH + mf * 768);
        #pragma unroll
        for (int nf = 0; nf < 4; nf++) ldsm2(Bf[nf], bBaseH + nf * 384);
        #pragma unroll
        for (int mf = 0; mf < 4; mf++)
            #pragma unroll
            for (int nf = 0; nf < 4; nf++) mma_bf16(acc[mf][nf], Af[mf], Bf[nf]);
        // Ah * Bl (reuse A frags)
        #pragma unroll
        for (int nf = 0; nf < 4; nf++) ldsm2(Bf[nf], bBaseL + nf * 384);
        #pragma unroll
        for (int mf = 0; mf < 4; mf++)
            #pragma unroll
            for (int nf = 0; nf < 4; nf++) mma_bf16(acc[mf][nf], Af[mf], Bf[nf]);
        // Al * Bh
        #pragma unroll
        for (int mf = 0; mf < 4; mf++) ldsm4(Af[mf], aBaseL + mf * 768);
        #pragma unroll
        for (int nf = 0; nf < 4; nf++) ldsm2(Bf[nf], bBaseH + nf * 384);
        #pragma unroll
        for (int mf = 0; mf < 4; mf++)
            #pragma unroll
            for (int nf = 0; nf < 4; nf++) mma_bf16(acc[mf][nf], Af[mf], Bf[nf]);
        __syncthreads();
    }

    const int gID = lane >> 2, tg = lane & 3;
    #pragma unroll
    for (int mf = 0; mf < 4; mf++) {
        const int gmb = m0 + wm * 64 + mf * 16 + gID;
        #pragma unroll
        for (int nf = 0; nf < 4; nf++) {
            const int gnb = n0 + wn * 32 + nf * 8 + tg * 2;
            #pragma unroll
            for (int e = 0; e < 4; e++) {
                int gm = gmb + (e >> 1) * 8;
                int gn = gnb + (e & 1);
                if (gn >= N) continue;
                float v = acc[mf][nf][e];
                if (EPI == 0) {
                    if (bias) v += bias[gn];
                    C[(size_t)gm * ldc + gn] = v;
                } else if (EPI == 1) {
                    float g = sigmoidf_(v + bias[gn]);
                    if (gn < Dd) y1p[(size_t)gm * Dd + gn] = g * x1[(size_t)gm * Dd + gn];
                    else         y2p[(size_t)gm * Dd + (gn - Dd)] = g;
                } else {
                    float cc = tanhf(v + bias[gn]);
                    float uu = x2[(size_t)gm * Dd + gn];
                    float hh = x1[(size_t)gm * Dd + gn];
                    C[(size_t)gm * ldc + gn] = uu * hh + (1.0f - uu) * cc;
                }
            }
        }
    }
}

// ---------------------------------------------------------------------------
// adj propagation, both directions in one launch: grid (512, 2)
//   a[t,c] = sum_s adj[b,t,s] * hio[b,s, off+c] -> g_X[:, off+c]
// ---------------------------------------------------------------------------
__global__ void __launch_bounds__(256)
adj_both_kernel(const float* __restrict__ adj_in, const float* __restrict__ adj_out)
{
    __shared__ float adjS[Tt*Tt];
    __shared__ float hS[Tt*Dd];
    int b = blockIdx.x, io = blockIdx.y;
    const float* adj = io ? adj_out : adj_in;
    int off = io * Dd;
    int tid = threadIdx.x;
    for (int i = tid; i < Tt*Tt; i += 256) adjS[i] = adj[(size_t)b*Tt*Tt + i];
    for (int i = tid; i < Tt*Dd; i += 256) {
        int s = i / Dd, c = i - s * Dd;
        hS[i] = g_hio[(size_t)(b*Tt + s) * 200 + off + c];
    }
    __syncthreads();

    for (int task = tid; task < 625; task += 256) {
        int tg = task / 25, cg = task - tg * 25;
        int t0 = tg * 2, c0 = cg * 4;
        ull a00=0, a01=0, a10=0, a11=0;   // even s
        ull e00=0, e01=0, e10=0, e11=0;   // odd s
        #pragma unroll 5
        for (int s = 0; s < Tt; s += 2) {
            const ull* hp = reinterpret_cast<const ull*>(&hS[s * Dd + c0]);
            ull b0 = hp[0], b1 = hp[1];
            float w0 = adjS[t0 * Tt + s], w1 = adjS[(t0+1) * Tt + s];
            ull p0 = pack2(w0, w0), p1 = pack2(w1, w1);
            fma2(a00, p0, b0); fma2(a01, p0, b1);
            fma2(a10, p1, b0); fma2(a11, p1, b1);
            const ull* hq = reinterpret_cast<const ull*>(&hS[(s+1) * Dd + c0]);
            ull c0v = hq[0], c1v = hq[1];
            float v0 = adjS[t0 * Tt + s + 1], v1 = adjS[(t0+1) * Tt + s + 1];
            ull q0 = pack2(v0, v0), q1 = pack2(v1, v1);
            fma2(e00, q0, c0v); fma2(e01, q0, c1v);
            fma2(e10, q1, c0v); fma2(e11, q1, c1v);
        }
        float x0,x1,x2,x3,y0,y1,y2,y3;
        size_t base0 = (size_t)(b*Tt + t0) * 300 + off + c0;
        unpack2(a00,x0,x1); unpack2(a01,x2,x3);
        unpack2(e00,y0,y1); unpack2(e01,y2,y3);
        g_X[base0+0]=x0+y0; g_X[base0+1]=x1+y1; g_X[base0+2]=x2+y2; g_X[base0+3]=x3+y3;
        size_t base1 = (size_t)(b*Tt + t0 + 1) * 300 + off + c0;
        unpack2(a10,x0,x1); unpack2(a11,x2,x3);
        unpack2(e10,y0,y1); unpack2(e11,y2,y3);
        g_X[base1+0]=x0+y0; g_X[base1+1]=x1+y1; g_X[base1+2]=x2+y2; g_X[base1+3]=x3+y3;
    }
}

// ---------------------------------------------------------------------------
// last vector: rm=sum(mask); last_h = re_emb[b, alias[b,rm-1]]; g_last = last_h @ w1
// ---------------------------------------------------------------------------
__global__ void last_kernel(const float* __restrict__ mask,
                            const int* __restrict__ alias_,
                            const float* __restrict__ w1)
{
    __shared__ float msum[Tt];
    __shared__ float lh[Dd];
    __shared__ int   liS;
    int b = blockIdx.x, tid = threadIdx.x;
    if (tid < Tt) msum[tid] = mask[b * Tt + tid];
    __syncthreads();
    if (tid == 0) {
        float s = 0.0f;
        for (int t = 0; t < Tt; t++) s += msum[t];
        liS = alias_[b * Tt + ((int)s - 1)];
    }
    __syncthreads();
    int li = liS;
    if (tid < Dd) lh[tid] = g_hnew[(size_t)(b * Tt + li) * Dd + tid];
    __syncthreads();
    if (tid < Dd) {
        float acc = 0.0f;
        #pragma unroll 4
        for (int k = 0; k < Dd; k++) acc += lh[k] * w1[k * Dd + tid];
        g_last[b * Dd + tid] = acc;
    }
}

// ---------------------------------------------------------------------------
// attention + readout
// ---------------------------------------------------------------------------
__global__ void __launch_bounds__(128)
att_kernel(const float* __restrict__ mask, const float* __restrict__ vv,
           const float* __restrict__ nb, const float* __restrict__ Bmat)
{
    __shared__ float lastS[Dd], nbS[Dd], vS[Dd];
    __shared__ float acc4[4][Dd];
    __shared__ float maS[2 * Dd];
    int b = blockIdx.x, tid = threadIdx.x;
    int w = tid >> 5, lane = tid & 31;

    if (tid < Dd) { lastS[tid] = g_last[b * Dd + tid]; nbS[tid] = nb[tid]; vS[tid] = vv[tid]; }
    __syncthreads();

    float accR[4] = {0.f, 0.f, 0.f, 0.f};
    for (int t = w; t < Tt; t += 4) {
        const float* seqrow = &g_seq [(size_t)(b * Tt + t) * Dd];
        const float* shrow  = &g_seqh[(size_t)(b * Tt + t) * Dd];
        float part = 0.0f;
        #pragma unroll
        for (int j = 0; j < 4; j++) {
            int c = lane + 32 * j;
            if (c < Dd) part += sigmoidf_(lastS[c] + seqrow[c] + nbS[c]) * vS[c];
        }
        #pragma unroll
        for (int off = 16; off > 0; off >>= 1)
            part += __shfl_xor_sync(0xffffffffu, part, off);
        float coef = part * mask[b * Tt + t];
        #pragma unroll
        for (int j = 0; j < 4; j++) {
            int c = lane + 32 * j;
            if (c < Dd) accR[j] += coef * shrow[c];
        }
    }
    #pragma unroll
    for (int j = 0; j < 4; j++) {
        int c = lane + 32 * j;
        if (c < Dd) acc4[w][c] = accR[j];
    }
    __syncthreads();
    if (tid < Dd) {
        maS[tid]      = acc4[0][tid] + acc4[1][tid] + acc4[2][tid] + acc4[3][tid];
        maS[Dd + tid] = lastS[tid];
    }
    __syncthreads();
    if (tid < Dd) {
        float y = 0.0f;
        #pragma unroll 4
        for (int k = 0; k < 2 * Dd; k++) y += maS[k] * Bmat[k * Dd + tid];
        g_y1[b * Dd + tid] = y;
    }
}

// ---------------------------------------------------------------------------
// Host launcher
// ---------------------------------------------------------------------------
static inline int cdiv(int a, int b) { return (a + b - 1) / b; }

extern "C" void kernel_launch(void* const* d_in, const int* in_sizes, int n_in,
                              void* d_out, int out_size)
{
    int o = 0;
    if (n_in < 20 || in_sizes[5] != 1) o = -1;  // step scalar possibly omitted

    const float* adj_in  = (const float*)d_in[0];
    const float* adj_out = (const float*)d_in[1];
    const float* mask    = (const float*)d_in[2];
    const int*   item    = (const int*)  d_in[3];
    const int*   alias_  = (const int*)  d_in[4];
    const float* emb     = (const float*)d_in[6  + o];
    const float* W_in    = (const float*)d_in[7  + o];
    const float* b_in    = (const float*)d_in[8  + o];
    const float* W_out   = (const float*)d_in[9  + o];
    const float* b_out   = (const float*)d_in[10 + o];
    const float* ggk     = (const float*)d_in[11 + o];
    const float* ggb     = (const float*)d_in[12 + o];
    const float* gck     = (const float*)d_in[13 + o];
    const float* gcb     = (const float*)d_in[14 + o];
    const float* w1      = (const float*)d_in[15 + o];
    const float* w2      = (const float*)d_in[16 + o];
    const float* vv      = (const float*)d_in[17 + o];
    const float* nb      = (const float*)d_in[18 + o];
    const float* Bmat    = (const float*)d_in[19 + o];
    float* out = (float*)d_out;

    void* p;
    #define SYM(T, var, sym) cudaGetSymbolAddress(&p, sym); T* var = (T*)p
    SYM(float, ph,    g_h);    SYM(float, phio,  g_hio);
    SYM(float, prh,   g_rh);   SYM(float, pu,    g_u);
    SYM(float, phnew, g_hnew); SYM(float, pseq,  g_seq);
    SYM(float, pbio,  g_bio);  SYM(float, py1,   g_y1);
    (void)py1;
    SYM(__nv_bfloat16, peH, g_eH);   SYM(__nv_bfloat16, peL, g_eL);
    SYM(__nv_bfloat16, phH, g_hH);   SYM(__nv_bfloat16, phL, g_hL);
    SYM(__nv_bfloat16, pXH, g_XH);   SYM(__nv_bfloat16, pXL, g_XL);
    SYM(__nv_bfloat16, psH, g_sH);   SYM(__nv_bfloat16, psL, g_sL);
    SYM(__nv_bfloat16, pyH, g_yH);   SYM(__nv_bfloat16, pyL, g_yL);
    SYM(__nv_bfloat16, pWioH, g_WioH); SYM(__nv_bfloat16, pWioL, g_WioL);
    SYM(__nv_bfloat16, pggkH, g_ggkH); SYM(__nv_bfloat16, pggkL, g_ggkL);
    SYM(__nv_bfloat16, pgckH, g_gckH); SYM(__nv_bfloat16, pgckL, g_gckL);
    SYM(__nv_bfloat16, pw2H, g_w2H);   SYM(__nv_bfloat16, pw2L, g_w2L);
    #undef SYM

    // ---- operand conversions ----
    conv_emb_kernel<<<cdiv(NN * KP1, 256), 256>>>(emb);
    conv_wio_kernel<<<cdiv(2 * Dd * KP1, 256), 256>>>(W_in, W_out, b_in, b_out);
    conv_wT_kernel<<<cdiv(2 * Dd * KP3, 256), 256>>>(ggk, pggkH, pggkL, 3 * Dd, 2 * Dd, KP3);
    conv_wT_kernel<<<cdiv(Dd * KP3, 256), 256>>>(gck, pgckH, pgckL, 3 * Dd, Dd, KP3);
    conv_wT_kernel<<<cdiv(Dd * KP1, 256), 256>>>(w2, pw2H, pw2L, Dd, Dd, KP1);

    // ---- GGNN (step = 1) ----
    gather_h_kernel<<<cdiv(BT * KP1, 256), 256>>>(emb, item);

    // [hin | hout] = h @ [W_in | W_out] + [b_in | b_out]
    mma_gemm<0><<<dim3(2, BT / 128), 256>>>(phH, phL, pWioH, pWioL, pbio, phio,
                                            2 * Dd, KP1, 2 * Dd,
                                            nullptr, nullptr, nullptr, nullptr);
    adj_both_kernel<<<dim3(Bb, 2), 256>>>(adj_in, adj_out);
    conv_X_kernel<<<cdiv(BT * KP3, 256), 256>>>();

    // gates = sigmoid(X @ ggk + ggb) -> r*h, u
    mma_gemm<1><<<dim3(2, BT / 128), 256>>>(pXH, pXL, pggkH, pggkL, ggb, nullptr,
                                            2 * Dd, KP3, 0,
                                            ph, nullptr, prh, pu);
    splice_rh_kernel<<<cdiv(BT * Dd, 256), 256>>>();

    // c = tanh(X' @ gck + gcb); h_new = u*h + (1-u)*c
    mma_gemm<2><<<dim3(1, BT / 128), 256>>>(pXH, pXL, pgckH, pgckL, gcb, phnew,
                                            Dd, KP3, Dd,
                                            ph, pu, nullptr, nullptr);

    // ---- attention readout ----
    last_kernel<<<Bb, 128>>>(mask, alias_, w1);
    seqh_kernel<<<cdiv(BT * KP1, 256), 256>>>(alias_);

    mma_gemm<0><<<dim3(1, BT / 128), 256>>>(psH, psL, pw2H, pw2L, nullptr, pseq,
                                            Dd, KP1, Dd,
                                            nullptr, nullptr, nullptr, nullptr);

    att_kernel<<<Bb, 128>>>(mask, vv, nb, Bmat);
    conv_y1_kernel<<<cdiv(Bb * KP1, 256), 256>>>();

    // ---- logits = y1 @ embedding[1:]^T ----
    mma_gemm<0><<<dim3(cdiv(NOUT, 128), Bb / 128), 256>>>(
        pyH, pyL, peH + KP1, peL + KP1, nullptr, out,
        NOUT, KP1, NOUT,
        nullptr, nullptr, nullptr, nullptr);
}

// round 12
// speedup vs baseline: 1.6496x; 1.1227x over previous
#include <cuda_runtime.h>
#include <cuda_bf16.h>
#include <cstdint>
#include <math.h>

// ---------------------------------------------------------------------------
// Problem constants
// ---------------------------------------------------------------------------
#define Bb   512
#define Tt   50
#define Dd   100
#define BT   (Bb*Tt)          // 25600
#define NN   100000
#define NOUT (NN-1)           // 99999
#define KP1  112              // padded segment width (7 chunks of 16)
#define KP3  336              // 3 padded segments

typedef unsigned long long ull;
typedef __nv_bfloat16 bf16;

// ---------------------------------------------------------------------------
// helpers
// ---------------------------------------------------------------------------
__device__ __forceinline__ ull pack2(float x, float y) {
    ull r; asm("mov.b64 %0, {%1, %2};" : "=l"(r) : "f"(x), "f"(y)); return r;
}
__device__ __forceinline__ void unpack2(ull v, float& x, float& y) {
    asm("mov.b64 {%0, %1}, %2;" : "=f"(x), "=f"(y) : "l"(v));
}
__device__ __forceinline__ void fma2(ull& d, ull a, ull b) {
    asm("fma.rn.f32x2 %0, %1, %2, %3;" : "=l"(d) : "l"(a), "l"(b), "l"(d));
}
__device__ __forceinline__ float sigmoidf_(float x) { return 1.0f / (1.0f + expf(-x)); }

__device__ __forceinline__ void split_bf16(float x, bf16& hi, bf16& lo) {
    bf16 h = __float2bfloat16(x);
    hi = h;
    lo = __float2bfloat16(x - __bfloat162float(h));
}
__device__ __forceinline__ uint32_t smem_u32a(const void* p) {
    return (uint32_t)__cvta_generic_to_shared(p);
}
__device__ __forceinline__ void ldsm4(unsigned r[4], uint32_t a) {
    asm volatile("ldmatrix.sync.aligned.m8n8.x4.shared.b16 {%0,%1,%2,%3},[%4];"
                 : "=r"(r[0]), "=r"(r[1]), "=r"(r[2]), "=r"(r[3]) : "r"(a));
}
__device__ __forceinline__ void ldsm2(unsigned r[2], uint32_t a) {
    asm volatile("ldmatrix.sync.aligned.m8n8.x2.shared.b16 {%0,%1},[%2];"
                 : "=r"(r[0]), "=r"(r[1]) : "r"(a));
}
__device__ __forceinline__ void mma_bf16(float c[4], const unsigned a[4], const unsigned b[2]) {
    asm volatile("mma.sync.aligned.m16n8k16.row.col.f32.bf16.bf16.f32 "
                 "{%0,%1,%2,%3},{%4,%5,%6,%7},{%8,%9},{%0,%1,%2,%3};"
                 : "+f"(c[0]), "+f"(c[1]), "+f"(c[2]), "+f"(c[3])
                 : "r"(a[0]), "r"(a[1]), "r"(a[2]), "r"(a[3]), "r"(b[0]), "r"(b[1]));
}
#define CP16(dst, src) \
    asm volatile("cp.async.cg.shared.global [%0], [%1], 16;" :: "r"(dst), "l"(src))
#define CPCOMMIT() asm volatile("cp.async.commit_group;")
#define CPWAIT0()  asm volatile("cp.async.wait_group 0;")

// ---------------------------------------------------------------------------
// Scratch (static device globals; zero-initialized at load — segment pads
// k in [100,112) are NEVER written by any kernel, so they stay zero forever)
// ---------------------------------------------------------------------------
__device__ float g_hio [BT*2*Dd];   // [hin | hout] fp32 (adj input)
__device__ float g_h   [BT*Dd];
__device__ float g_u   [BT*Dd];
__device__ float g_hnew[BT*Dd];
__device__ float g_seqh[BT*Dd];
__device__ float g_seq [BT*Dd];
__device__ float g_last[Bb*Dd];
__device__ float g_bio [2*Dd];

// split-bf16 operands (hi/lo), k-major, per-segment padded
__device__ __align__(16) bf16 g_eH[(size_t)NN*KP1], g_eL[(size_t)NN*KP1];  // embedding
__device__ __align__(16) bf16 g_XH[(size_t)BT*KP3], g_XL[(size_t)BT*KP3];  // [h|a_in|a_out]
__device__ __align__(16) bf16 g_rhH[BT*KP1], g_rhL[BT*KP1];                // r*h
__device__ __align__(16) bf16 g_sH[BT*KP1],  g_sL[BT*KP1];                 // seq_h
__device__ __align__(16) bf16 g_yH[Bb*KP1],  g_yL[Bb*KP1];                 // y1
__device__ __align__(16) bf16 g_WioH[2*Dd*KP1], g_WioL[2*Dd*KP1];          // [W_in|W_out]^T
__device__ __align__(16) bf16 g_ggkH[2*Dd*KP3], g_ggkL[2*Dd*KP3];          // ggk^T (seg-permuted)
__device__ __align__(16) bf16 g_gckH[Dd*KP3],   g_gckL[Dd*KP3];            // gck^T (seg-permuted)
__device__ __align__(16) bf16 g_w2H[Dd*KP1],    g_w2L[Dd*KP1];             // w2^T

// ---------------------------------------------------------------------------
// Conversions / gathers
// ---------------------------------------------------------------------------
__global__ void conv_emb_kernel(const float* __restrict__ emb) {
    size_t i = (size_t)blockIdx.x * 256 + threadIdx.x;      // over NN * 56 pairs
    if (i >= (size_t)NN * 56) return;
    size_t r = i / 56; int kp = (int)(i - r * 56) * 2;
    float x0 = 0.f, x1 = 0.f;
    if (kp < Dd) { float2 v = *(const float2*)(emb + r * Dd + kp); x0 = v.x; x1 = v.y; }
    bf16 h0, l0, h1, l1; split_bf16(x0, h0, l0); split_bf16(x1, h1, l1);
    __nv_bfloat162 hh; hh.x = h0; hh.y = h1;
    __nv_bfloat162 ll; ll.x = l0; ll.y = l1;
    *(__nv_bfloat162*)(g_eH + r * KP1 + kp) = hh;
    *(__nv_bfloat162*)(g_eL + r * KP1 + kp) = ll;
}

// transpose + split + segment-permute: W[nseg*100][Norig] -> out[Norig][nseg*112]
// output seg s holds original row block [2,0,1][s] (for nseg=3), identity for nseg=1
__global__ void conv_wT_kernel(const float* __restrict__ W,
                               bf16* __restrict__ oh, bf16* __restrict__ ol,
                               int Norig, int nseg) {
    int KPp = nseg * KP1;
    int i = blockIdx.x * 256 + threadIdx.x;
    if (i >= Norig * KPp) return;
    int n = i / KPp, kp = i - n * KPp;
    int seg = kp / KP1, off = kp - seg * KP1;
    int blk = (seg + nseg - 1) % nseg;
    float x = (off < Dd) ? W[(blk * Dd + off) * Norig + n] : 0.0f;
    split_bf16(x, oh[i], ol[i]);
}

__global__ void conv_wio_kernel(const float* __restrict__ W_in, const float* __restrict__ W_out,
                                const float* __restrict__ b_in, const float* __restrict__ b_out) {
    int i = blockIdx.x * 256 + threadIdx.x;
    if (i >= 2 * Dd * KP1) return;
    int n = i / KP1, k = i - n * KP1;
    float x = 0.0f;
    if (k < Dd) x = (n < Dd) ? W_in[k * Dd + n] : W_out[k * Dd + (n - Dd)];
    split_bf16(x, g_WioH[i], g_WioL[i]);
    if (i < 2 * Dd) g_bio[i] = (i < Dd) ? b_in[i] : b_out[i - Dd];
}

// gather h = embedding[item]: fp32 g_h + split into X segment 0
__global__ void gather_h_kernel(const float* __restrict__ emb, const int* __restrict__ item) {
    int i = blockIdx.x * 256 + threadIdx.x;
    if (i >= BT * KP1) return;
    int r = i / KP1, k = i - r * KP1;
    if (k >= Dd) return;                       // pads stay zero (never written)
    float x = emb[(size_t)item[r] * Dd + k];
    g_h[r * Dd + k] = x;
    size_t o = (size_t)r * KP3 + k;
    split_bf16(x, g_XH[o], g_XL[o]);
}

// seq_h gather: fp32 g_seqh + split into sH/sL
__global__ void seqh_kernel(const int* __restrict__ alias_) {
    int i = blockIdx.x * 256 + threadIdx.x;
    if (i >= BT * KP1) return;
    int r = i / KP1, k = i - r * KP1;
    if (k >= Dd) return;
    int b = r / Tt;
    int al = alias_[r];
    float x = g_hnew[(size_t)(b * Tt + al) * Dd + k];
    g_seqh[r * Dd + k] = x;
    split_bf16(x, g_sH[(size_t)r * KP1 + k], g_sL[(size_t)r * KP1 + k]);
}

// ---------------------------------------------------------------------------
// Split-bf16 tensor-core GEMM, cp.async double-buffered.
//   C[M,N] = epi(A @ B^T + bias);  A: [M][ldA] hi/lo bf16, B: [N][NKCH*16] hi/lo
//   Block 128x128, 8 warps (2x4), warp tile 64x32, mma m16n8k16, 3-term split.
//   USE_RH: for k0 < 112 read A from g_rhH/g_rhL (row stride KP1) instead.
//   EPI: 0 plain(+bias), 1 gates (sigmoid -> split r*h + fp32 u), 2 cand (GRU)
// Smem per tile: 128 rows x 32B, XOR swizzle (c ^= (row>>2)&1) -> conflict-free.
// ---------------------------------------------------------------------------
template<int EPI, int NKCH, bool USE_RH>
__global__ void __launch_bounds__(256)
mma_gemm(const bf16* __restrict__ Ahi, const bf16* __restrict__ Alo, int ldA,
         const bf16* __restrict__ Bhi, const bf16* __restrict__ Blo,
         const float* __restrict__ bias, float* __restrict__ C, int N, int ldc,
         const float* __restrict__ x1, const float* __restrict__ x2,
         float* __restrict__ y2p)
{
    __shared__ __align__(16) bf16 smem[2 * 4 * 128 * 16];   // 32 KB
    const int tid = threadIdx.x, lane = tid & 31, warp = tid >> 5;
    const int wm = warp >> 2, wn = warp & 3;
    const int m0 = blockIdx.y * 128, n0 = blockIdx.x * 128;
    const uint32_t sbase = smem_u32a(smem);

    // loader: thread -> (row, k-half)
    const int lrow = tid >> 1, lc = tid & 1;
    const uint32_t dstoff = lrow * 32 + ((lc ^ ((lrow >> 2) & 1)) * 16);

    const size_t aRow = (size_t)(m0 + lrow);
    int br = n0 + lrow; if (br >= N) br = N - 1;   // clamp; epilogue guards
    const bf16* aH0 = Ahi + aRow * ldA + lc * 8;
    const bf16* aL0 = Alo + aRow * ldA + lc * 8;
    const bf16* rH0 = g_rhH + aRow * KP1 + lc * 8;
    const bf16* rL0 = g_rhL + aRow * KP1 + lc * 8;
    const bf16* bH0 = Bhi + (size_t)br * (NKCH * 16) + lc * 8;
    const bf16* bL0 = Blo + (size_t)br * (NKCH * 16) + lc * 8;

    auto load_chunk = [&](int k0, int st) {
        uint32_t d = sbase + st * 16384 + dstoff;
        const bf16 *ah, *al;
        if (USE_RH && k0 < KP1) { ah = rH0 + k0; al = rL0 + k0; }
        else                    { ah = aH0 + k0; al = aL0 + k0; }
        CP16(d,         ah);
        CP16(d + 4096,  al);
        CP16(d + 8192,  bH0 + k0);
        CP16(d + 12288, bL0 + k0);
        CPCOMMIT();
    };

    // reader bases (swizzle bit invariant under mf*16 / nf*8 row offsets)
    const int ra = wm * 64 + (lane & 15); const int ca = lane >> 4;
    const uint32_t aoff = ra * 32 + ((ca ^ ((ra >> 2) & 1)) * 16);
    const int rb = wn * 32 + (lane & 7);  const int cb = (lane >> 3) & 1;
    const uint32_t boff = rb * 32 + ((cb ^ ((rb >> 2) & 1)) * 16);

    float acc[4][4][4];
    #pragma unroll
    for (int i = 0; i < 4; i++)
        #pragma unroll
        for (int j = 0; j < 4; j++)
            #pragma unroll
            for (int e = 0; e < 4; e++) acc[i][j][e] = 0.0f;

    load_chunk(0, 0);
    #pragma unroll
    for (int ch = 0; ch < NKCH; ch++) {
        CPWAIT0();
        __syncthreads();
        if (ch + 1 < NKCH) load_chunk((ch + 1) * 16, (ch + 1) & 1);

        const uint32_t base = sbase + (ch & 1) * 16384;
        const uint32_t aH = base + aoff,        aL = base + 4096  + aoff;
        const uint32_t bH = base + 8192 + boff, bL = base + 12288 + boff;
        unsigned Af[4][4], Bf[4][2];
        // Ah * Bh
        #pragma unroll
        for (int mf = 0; mf < 4; mf++) ldsm4(Af[mf], aH + mf * 512);
        #pragma unroll
        for (int nf = 0; nf < 4; nf++) ldsm2(Bf[nf], bH + nf * 256);
        #pragma unroll
        for (int mf = 0; mf < 4; mf++)
            #pragma unroll
            for (int nf = 0; nf < 4; nf++) mma_bf16(acc[mf][nf], Af[mf], Bf[nf]);
        // Ah * Bl
        #pragma unroll
        for (int nf = 0; nf < 4; nf++) ldsm2(Bf[nf], bL + nf * 256);
        #pragma unroll
        for (int mf = 0; mf < 4; mf++)
            #pragma unroll
            for (int nf = 0; nf < 4; nf++) mma_bf16(acc[mf][nf], Af[mf], Bf[nf]);
        // Al * Bh
        #pragma unroll
        for (int mf = 0; mf < 4; mf++) ldsm4(Af[mf], aL + mf * 512);
        #pragma unroll
        for (int nf = 0; nf < 4; nf++) ldsm2(Bf[nf], bH + nf * 256);
        #pragma unroll
        for (int mf = 0; mf < 4; mf++)
            #pragma unroll
            for (int nf = 0; nf < 4; nf++) mma_bf16(acc[mf][nf], Af[mf], Bf[nf]);
    }

    const int gID = lane >> 2, tg = lane & 3;
    #pragma unroll
    for (int mf = 0; mf < 4; mf++) {
        const int gmb = m0 + wm * 64 + mf * 16 + gID;
        #pragma unroll
        for (int nf = 0; nf < 4; nf++) {
            const int gnb = n0 + wn * 32 + nf * 8 + tg * 2;
            #pragma unroll
            for (int e = 0; e < 4; e++) {
                int gm = gmb + (e >> 1) * 8;
                int gn = gnb + (e & 1);
                if (gn >= N) continue;
                float v = acc[mf][nf][e];
                if (EPI == 0) {
                    if (bias) v += bias[gn];
                    C[(size_t)gm * ldc + gn] = v;
                } else if (EPI == 1) {
                    float g = sigmoidf_(v + bias[gn]);
                    if (gn < Dd) {
                        float rh = g * x1[(size_t)gm * Dd + gn];
                        size_t o = (size_t)gm * KP1 + gn;
                        split_bf16(rh, g_rhH[o], g_rhL[o]);
                    } else {
                        y2p[(size_t)gm * Dd + (gn - Dd)] = g;
                    }
                } else {
                    float cc = tanhf(v + bias[gn]);
                    float uu = x2[(size_t)gm * Dd + gn];
                    float hh = x1[(size_t)gm * Dd + gn];
                    C[(size_t)gm * ldc + gn] = uu * hh + (1.0f - uu) * cc;
                }
            }
        }
    }
}

// ---------------------------------------------------------------------------
// adj propagation (both dirs, grid (512,2), 640 threads = single task pass):
//   a[t,c] = sum_s adj[b,t,s] * hio[b,s,off+c]  -> split into X seg 1/2
// ---------------------------------------------------------------------------
__device__ __forceinline__ void store_split4(size_t o, float a, float b, float c, float d) {
    __nv_bfloat162 h01, h23, l01, l23;
    bf16 h, l;
    split_bf16(a, h, l); h01.x = h; l01.x = l;
    split_bf16(b, h, l); h01.y = h; l01.y = l;
    split_bf16(c, h, l); h23.x = h; l23.x = l;
    split_bf16(d, h, l); h23.y = h; l23.y = l;
    *(__nv_bfloat162*)(g_XH + o)     = h01;
    *(__nv_bfloat162*)(g_XH + o + 2) = h23;
    *(__nv_bfloat162*)(g_XL + o)     = l01;
    *(__nv_bfloat162*)(g_XL + o + 2) = l23;
}

__global__ void __launch_bounds__(640)
adj_kernel(const float* __restrict__ adj_in, const float* __restrict__ adj_out)
{
    __shared__ float adjS[Tt*Tt];
    __shared__ float hS[Tt*Dd];
    int b = blockIdx.x, io = blockIdx.y;
    const float* adj = io ? adj_out : adj_in;
    int tid = threadIdx.x;
    for (int i = tid; i < Tt*Tt; i += 640) adjS[i] = adj[(size_t)b*Tt*Tt + i];
    for (int i = tid; i < Tt*Dd; i += 640) {
        int s = i / Dd, c = i - s * Dd;
        hS[i] = g_hio[(size_t)(b*Tt + s) * 200 + io * Dd + c];
    }
    __syncthreads();

    if (tid < 625) {
        int tg = tid / 25, cg = tid - tg * 25;
        int t0 = tg * 2, c0 = cg * 4;
        ull a00=0, a01=0, a10=0, a11=0;
        ull e00=0, e01=0, e10=0, e11=0;
        #pragma unroll 5
        for (int s = 0; s < Tt; s += 2) {
            const ull* hp = reinterpret_cast<const ull*>(&hS[s * Dd + c0]);
            ull b0 = hp[0], b1 = hp[1];
            float w0 = adjS[t0 * Tt + s], w1 = adjS[(t0+1) * Tt + s];
            ull p0 = pack2(w0, w0), p1 = pack2(w1, w1);
            fma2(a00, p0, b0); fma2(a01, p0, b1);
            fma2(a10, p1, b0); fma2(a11, p1, b1);
            const ull* hq = reinterpret_cast<const ull*>(&hS[(s+1) * Dd + c0]);
            ull c0v = hq[0], c1v = hq[1];
            float v0 = adjS[t0 * Tt + s + 1], v1 = adjS[(t0+1) * Tt + s + 1];
            ull q0 = pack2(v0, v0), q1 = pack2(v1, v1);
            fma2(e00, q0, c0v); fma2(e01, q0, c1v);
            fma2(e10, q1, c0v); fma2(e11, q1, c1v);
        }
        float x0,x1,x2,x3,y0,y1,y2,y3;
        size_t base0 = (size_t)(b*Tt + t0) * KP3 + KP1 + io * KP1 + c0;
        unpack2(a00,x0,x1); unpack2(a01,x2,x3);
        unpack2(e00,y0,y1); unpack2(e01,y2,y3);
        store_split4(base0, x0+y0, x1+y1, x2+y2, x3+y3);
        size_t base1 = base0 + KP3;
        unpack2(a10,x0,x1); unpack2(a11,x2,x3);
        unpack2(e10,y0,y1); unpack2(e11,y2,y3);
        store_split4(base1, x0+y0, x1+y1, x2+y2, x3+y3);
    }
}

// ---------------------------------------------------------------------------
// last vector: rm=sum(mask); last_h = re_emb[b, alias[b,rm-1]]; g_last = last_h @ w1
// ---------------------------------------------------------------------------
__global__ void last_kernel(const float* __restrict__ mask,
                            const int* __restrict__ alias_,
                            const float* __restrict__ w1)
{
    __shared__ float msum[Tt];
    __shared__ float lh[Dd];
    __shared__ int   liS;
    int b = blockIdx.x, tid = threadIdx.x;
    if (tid < Tt) msum[tid] = mask[b * Tt + tid];
    __syncthreads();
    if (tid == 0) {
        float s = 0.0f;
        for (int t = 0; t < Tt; t++) s += msum[t];
        liS = alias_[b * Tt + ((int)s - 1)];
    }
    __syncthreads();
    int li = liS;
    if (tid < Dd) lh[tid] = g_hnew[(size_t)(b * Tt + li) * Dd + tid];
    __syncthreads();
    if (tid < Dd) {
        float acc = 0.0f;
        #pragma unroll 4
        for (int k = 0; k < Dd; k++) acc += lh[k] * w1[k * Dd + tid];
        g_last[b * Dd + tid] = acc;
    }
}

// ---------------------------------------------------------------------------
// attention + readout; writes split y1 directly
// ---------------------------------------------------------------------------
__global__ void __launch_bounds__(128)
att_kernel(const float* __restrict__ mask, const float* __restrict__ vv,
           const float* __restrict__ nb, const float* __restrict__ Bmat)
{
    __shared__ float lastS[Dd], nbS[Dd], vS[Dd];
    __shared__ float acc4[4][Dd];
    __shared__ float maS[2 * Dd];
    int b = blockIdx.x, tid = threadIdx.x;
    int w = tid >> 5, lane = tid & 31;

    if (tid < Dd) { lastS[tid] = g_last[b * Dd + tid]; nbS[tid] = nb[tid]; vS[tid] = vv[tid]; }
    __syncthreads();

    float accR[4] = {0.f, 0.f, 0.f, 0.f};
    for (int t = w; t < Tt; t += 4) {
        const float* seqrow = &g_seq [(size_t)(b * Tt + t) * Dd];
        const float* shrow  = &g_seqh[(size_t)(b * Tt + t) * Dd];
        float part = 0.0f;
        #pragma unroll
        for (int j = 0; j < 4; j++) {
            int c = lane + 32 * j;
            if (c < Dd) part += sigmoidf_(lastS[c] + seqrow[c] + nbS[c]) * vS[c];
        }
        #pragma unroll
        for (int off = 16; off > 0; off >>= 1)
            part += __shfl_xor_sync(0xffffffffu, part, off);
        float coef = part * mask[b * Tt + t];
        #pragma unroll
        for (int j = 0; j < 4; j++) {
            int c = lane + 32 * j;
            if (c < Dd) accR[j] += coef * shrow[c];
        }
    }
    #pragma unroll
    for (int j = 0; j < 4; j++) {
        int c = lane + 32 * j;
        if (c < Dd) acc4[w][c] = accR[j];
    }
    __syncthreads();
    if (tid < Dd) {
        maS[tid]      = acc4[0][tid] + acc4[1][tid] + acc4[2][tid] + acc4[3][tid];
        maS[Dd + tid] = lastS[tid];
    }
    __syncthreads();
    if (tid < Dd) {
        float y = 0.0f;
        #pragma unroll 4
        for (int k = 0; k < 2 * Dd; k++) y += maS[k] * Bmat[k * Dd + tid];
        split_bf16(y, g_yH[b * KP1 + tid], g_yL[b * KP1 + tid]);
    }
}

// ---------------------------------------------------------------------------
// Host launcher
// ---------------------------------------------------------------------------
static inline int cdiv(int a, int b) { return (a + b - 1) / b; }

extern "C" void kernel_launch(void* const* d_in, const int* in_sizes, int n_in,
                              void* d_out, int out_size)
{
    int o = 0;
    if (n_in < 20 || in_sizes[5] != 1) o = -1;  // step scalar possibly omitted

    const float* adj_in  = (const float*)d_in[0];
    const float* adj_out = (const float*)d_in[1];
    const float* mask    = (const float*)d_in[2];
    const int*   item    = (const int*)  d_in[3];
    const int*   alias_  = (const int*)  d_in[4];
    const float* emb     = (const float*)d_in[6  + o];
    const float* W_in    = (const float*)d_in[7  + o];
    const float* b_in    = (const float*)d_in[8  + o];
    const float* W_out   = (const float*)d_in[9  + o];
    const float* b_out   = (const float*)d_in[10 + o];
    const float* ggk     = (const float*)d_in[11 + o];
    const float* ggb     = (const float*)d_in[12 + o];
    const float* gck     = (const float*)d_in[13 + o];
    const float* gcb     = (const float*)d_in[14 + o];
    const float* w1      = (const float*)d_in[15 + o];
    const float* w2      = (const float*)d_in[16 + o];
    const float* vv      = (const float*)d_in[17 + o];
    const float* nb      = (const float*)d_in[18 + o];
    const float* Bmat    = (const float*)d_in[19 + o];
    float* out = (float*)d_out;

    void* p;
    #define SYM(T, var, sym) cudaGetSymbolAddress(&p, sym); T* var = (T*)p
    SYM(float, ph,    g_h);    SYM(float, phio,  g_hio);
    SYM(float, pu,    g_u);    SYM(float, phnew, g_hnew);
    SYM(float, pseq,  g_seq);  SYM(float, pbio,  g_bio);
    SYM(bf16, peH, g_eH);   SYM(bf16, peL, g_eL);
    SYM(bf16, pXH, g_XH);   SYM(bf16, pXL, g_XL);
    SYM(bf16, psH, g_sH);   SYM(bf16, psL, g_sL);
    SYM(bf16, pyH, g_yH);   SYM(bf16, pyL, g_yL);
    SYM(bf16, pWioH, g_WioH); SYM(bf16, pWioL, g_WioL);
    SYM(bf16, pggkH, g_ggkH); SYM(bf16, pggkL, g_ggkL);
    SYM(bf16, pgckH, g_gckH); SYM(bf16, pgckL, g_gckL);
    SYM(bf16, pw2H, g_w2H);   SYM(bf16, pw2L, g_w2L);
    #undef SYM

    // ---- operand conversions ----
    conv_emb_kernel<<<cdiv(NN * 56, 256), 256>>>(emb);
    conv_wio_kernel<<<cdiv(2 * Dd * KP1, 256), 256>>>(W_in, W_out, b_in, b_out);
    conv_wT_kernel<<<cdiv(2 * Dd * KP3, 256), 256>>>(ggk, pggkH, pggkL, 2 * Dd, 3);
    conv_wT_kernel<<<cdiv(Dd * KP3, 256), 256>>>(gck, pgckH, pgckL, Dd, 3);
    conv_wT_kernel<<<cdiv(Dd * KP1, 256), 256>>>(w2, pw2H, pw2L, Dd, 1);

    // ---- GGNN (step = 1) ----
    gather_h_kernel<<<cdiv(BT * KP1, 256), 256>>>(emb, item);

    // [hin | hout] = h @ [W_in | W_out] + bio   (A = X segment 0, ldA = KP3)
    mma_gemm<0, 7, false><<<dim3(2, BT / 128), 256>>>(
        pXH, pXL, KP3, pWioH, pWioL, pbio, phio, 2 * Dd, 2 * Dd,
        nullptr, nullptr, nullptr);

    adj_kernel<<<dim3(Bb, 2), 640>>>(adj_in, adj_out);

    // gates = sigmoid(X @ ggk + ggb) -> split(r*h) into rh buf, fp32 u
    mma_gemm<1, 21, false><<<dim3(2, BT / 128), 256>>>(
        pXH, pXL, KP3, pggkH, pggkL, ggb, nullptr, 2 * Dd, 0,
        ph, nullptr, pu);

    // c = tanh(X' @ gck + gcb); h_new = u*h + (1-u)*c   (X' = rh for k<112)
    mma_gemm<2, 21, true><<<dim3(1, BT / 128), 256>>>(
        pXH, pXL, KP3, pgckH, pgckL, gcb, phnew, Dd, Dd,
        ph, pu, nullptr);

    // ---- attention readout ----
    last_kernel<<<Bb, 128>>>(mask, alias_, w1);
    seqh_kernel<<<cdiv(BT * KP1, 256), 256>>>(alias_);

    mma_gemm<0, 7, false><<<dim3(1, BT / 128), 256>>>(
        psH, psL, KP1, pw2H, pw2L, nullptr, pseq, Dd, Dd,
        nullptr, nullptr, nullptr);

    att_kernel<<<Bb, 128>>>(mask, vv, nb, Bmat);

    // ---- logits = y1 @ embedding[1:]^T ----
    mma_gemm<0, 7, false><<<dim3(cdiv(NOUT, 128), Bb / 128), 256>>>(
        pyH, pyL, KP1, peH + KP1, peL + KP1, nullptr, out, NOUT, NOUT,
        nullptr, nullptr, nullptr);
}

// round 15
// speedup vs baseline: 1.8420x; 1.1167x over previous
#include <cuda_runtime.h>
#include <cuda_bf16.h>
#include <cstdint>
#include <math.h>

// ---------------------------------------------------------------------------
// Problem constants
// ---------------------------------------------------------------------------
#define Bb   512
#define Tt   50
#define Dd   100
#define BT   (Bb*Tt)          // 25600
#define NN   100000
#define NOUT (NN-1)           // 99999
#define KP1  112              // padded segment width (7 chunks of 16)
#define KP3  336              // 3 padded segments

typedef unsigned long long ull;
typedef __nv_bfloat16 bf16;

// ---------------------------------------------------------------------------
// helpers
// ---------------------------------------------------------------------------
__device__ __forceinline__ ull pack2(float x, float y) {
    ull r; asm("mov.b64 %0, {%1, %2};" : "=l"(r) : "f"(x), "f"(y)); return r;
}
__device__ __forceinline__ void unpack2(ull v, float& x, float& y) {
    asm("mov.b64 {%0, %1}, %2;" : "=f"(x), "=f"(y) : "l"(v));
}
__device__ __forceinline__ void fma2(ull& d, ull a, ull b) {
    asm("fma.rn.f32x2 %0, %1, %2, %3;" : "=l"(d) : "l"(a), "l"(b), "l"(d));
}
__device__ __forceinline__ float sigmoidf_(float x) { return 1.0f / (1.0f + expf(-x)); }

__device__ __forceinline__ void split_bf16(float x, bf16& hi, bf16& lo) {
    bf16 h = __float2bfloat16(x);
    hi = h;
    lo = __float2bfloat16(x - __bfloat162float(h));
}
__device__ __forceinline__ uint32_t smem_u32a(const void* p) {
    return (uint32_t)__cvta_generic_to_shared(p);
}
__device__ __forceinline__ void ldsm4(unsigned r[4], uint32_t a) {
    asm volatile("ldmatrix.sync.aligned.m8n8.x4.shared.b16 {%0,%1,%2,%3},[%4];"
                 : "=r"(r[0]), "=r"(r[1]), "=r"(r[2]), "=r"(r[3]) : "r"(a));
}
__device__ __forceinline__ void ldsm2(unsigned r[2], uint32_t a) {
    asm volatile("ldmatrix.sync.aligned.m8n8.x2.shared.b16 {%0,%1},[%2];"
                 : "=r"(r[0]), "=r"(r[1]) : "r"(a));
}
__device__ __forceinline__ void mma_bf16(float c[4], const unsigned a[4], const unsigned b[2]) {
    asm volatile("mma.sync.aligned.m16n8k16.row.col.f32.bf16.bf16.f32 "
                 "{%0,%1,%2,%3},{%4,%5,%6,%7},{%8,%9},{%0,%1,%2,%3};"
                 : "+f"(c[0]), "+f"(c[1]), "+f"(c[2]), "+f"(c[3])
                 : "r"(a[0]), "r"(a[1]), "r"(a[2]), "r"(a[3]), "r"(b[0]), "r"(b[1]));
}
#define CP16(dst, src) \
    asm volatile("cp.async.cg.shared.global [%0], [%1], 16;" :: "r"(dst), "l"(src))
#define CPCOMMIT() asm volatile("cp.async.commit_group;")
#define CPWAIT0()  asm volatile("cp.async.wait_group 0;")

// ---------------------------------------------------------------------------
// Scratch (static device globals; zero-initialized at load — segment pads
// k in [100,112) are NEVER written by any kernel, so they stay zero forever)
// ---------------------------------------------------------------------------
__device__ float g_hio [BT*2*Dd];   // [hin | hout] fp32 (adj input)
__device__ float g_h   [BT*Dd];
__device__ float g_u   [BT*Dd];
__device__ float g_hnew[BT*Dd];
__device__ float g_seqh[BT*Dd];
__device__ float g_seq [BT*Dd];
__device__ float g_last[Bb*Dd];
__device__ float g_bio [2*Dd];

// split-bf16 operands (hi/lo), k-major, per-segment padded
__device__ __align__(16) bf16 g_eH[(size_t)NN*KP1], g_eL[(size_t)NN*KP1];  // embedding
__device__ __align__(16) bf16 g_XH[(size_t)BT*KP3], g_XL[(size_t)BT*KP3];  // [h|a_in|a_out]
__device__ __align__(16) bf16 g_rhH[BT*KP1], g_rhL[BT*KP1];                // r*h
__device__ __align__(16) bf16 g_sH[BT*KP1],  g_sL[BT*KP1];                 // seq_h
__device__ __align__(16) bf16 g_yH[Bb*KP1],  g_yL[Bb*KP1];                 // y1
__device__ __align__(16) bf16 g_WioH[2*Dd*KP1], g_WioL[2*Dd*KP1];          // [W_in|W_out]^T
__device__ __align__(16) bf16 g_ggkH[2*Dd*KP3], g_ggkL[2*Dd*KP3];          // ggk^T (seg-permuted)
__device__ __align__(16) bf16 g_gckH[Dd*KP3],   g_gckL[Dd*KP3];            // gck^T (seg-permuted)
__device__ __align__(16) bf16 g_w2H[Dd*KP1],    g_w2L[Dd*KP1];             // w2^T

// ---------------------------------------------------------------------------
// Conversions / gathers
// ---------------------------------------------------------------------------
__global__ void conv_emb_kernel(const float* __restrict__ emb) {
    size_t i = (size_t)blockIdx.x * 256 + threadIdx.x;      // over NN * 56 pairs
    if (i >= (size_t)NN * 56) return;
    size_t r = i / 56; int kp = (int)(i - r * 56) * 2;
    float x0 = 0.f, x1 = 0.f;
    if (kp < Dd) { float2 v = *(const float2*)(emb + r * Dd + kp); x0 = v.x; x1 = v.y; }
    bf16 h0, l0, h1, l1; split_bf16(x0, h0, l0); split_bf16(x1, h1, l1);
    __nv_bfloat162 hh; hh.x = h0; hh.y = h1;
    __nv_bfloat162 ll; ll.x = l0; ll.y = l1;
    *(__nv_bfloat162*)(g_eH + r * KP1 + kp) = hh;
    *(__nv_bfloat162*)(g_eL + r * KP1 + kp) = ll;
}

// transpose + split + segment-permute: W[nseg*100][Norig] -> out[Norig][nseg*112]
__global__ void conv_wT_kernel(const float* __restrict__ W,
                               bf16* __restrict__ oh, bf16* __restrict__ ol,
                               int Norig, int nseg) {
    int KPp = nseg * KP1;
    int i = blockIdx.x * 256 + threadIdx.x;
    if (i >= Norig * KPp) return;
    int n = i / KPp, kp = i - n * KPp;
    int seg = kp / KP1, off = kp - seg * KP1;
    int blk = (seg + nseg - 1) % nseg;
    float x = (off < Dd) ? W[(blk * Dd + off) * Norig + n] : 0.0f;
    split_bf16(x, oh[i], ol[i]);
}

__global__ void conv_wio_kernel(const float* __restrict__ W_in, const float* __restrict__ W_out,
                                const float* __restrict__ b_in, const float* __restrict__ b_out) {
    int i = blockIdx.x * 256 + threadIdx.x;
    if (i >= 2 * Dd * KP1) return;
    int n = i / KP1, k = i - n * KP1;
    float x = 0.0f;
    if (k < Dd) x = (n < Dd) ? W_in[k * Dd + n] : W_out[k * Dd + (n - Dd)];
    split_bf16(x, g_WioH[i], g_WioL[i]);
    if (i < 2 * Dd) g_bio[i] = (i < Dd) ? b_in[i] : b_out[i - Dd];
}

// gather h = embedding[item]: fp32 g_h + split into X segment 0
__global__ void gather_h_kernel(const float* __restrict__ emb, const int* __restrict__ item) {
    int i = blockIdx.x * 256 + threadIdx.x;
    if (i >= BT * KP1) return;
    int r = i / KP1, k = i - r * KP1;
    if (k >= Dd) return;                       // pads stay zero (never written)
    float x = emb[(size_t)item[r] * Dd + k];
    g_h[r * Dd + k] = x;
    size_t o = (size_t)r * KP3 + k;
    split_bf16(x, g_XH[o], g_XL[o]);
}

// seq_h gather: fp32 g_seqh + split into sH/sL
__global__ void seqh_kernel(const int* __restrict__ alias_) {
    int i = blockIdx.x * 256 + threadIdx.x;
    if (i >= BT * KP1) return;
    int r = i / KP1, k = i - r * KP1;
    if (k >= Dd) return;
    int b = r / Tt;
    int al = alias_[r];
    float x = g_hnew[(size_t)(b * Tt + al) * Dd + k];
    g_seqh[r * Dd + k] = x;
    split_bf16(x, g_sH[(size_t)r * KP1 + k], g_sL[(size_t)r * KP1 + k]);
}

// ---------------------------------------------------------------------------
// Split-bf16 legacy tensor-core GEMM, cp.async double-buffered (R12 proven).
// Block 128x128, 8 warps (2x4), warp tile 64x32, mma m16n8k16, 3-term split.
// ---------------------------------------------------------------------------
template<int EPI, int NKCH, bool USE_RH>
__global__ void __launch_bounds__(256)
mma_gemm(const bf16* __restrict__ Ahi, const bf16* __restrict__ Alo, int ldA,
         const bf16* __restrict__ Bhi, const bf16* __restrict__ Blo,
         const float* __restrict__ bias, float* __restrict__ C, int N, int ldc,
         const float* __restrict__ x1, const float* __restrict__ x2,
         float* __restrict__ y2p)
{
    __shared__ __align__(16) bf16 smem[2 * 4 * 128 * 16];   // 32 KB
    const int tid = threadIdx.x, lane = tid & 31, warp = tid >> 5;
    const int wm = warp >> 2, wn = warp & 3;
    const int m0 = blockIdx.y * 128, n0 = blockIdx.x * 128;
    const uint32_t sbase = smem_u32a(smem);

    const int lrow = tid >> 1, lc = tid & 1;
    const uint32_t dstoff = lrow * 32 + ((lc ^ ((lrow >> 2) & 1)) * 16);

    const size_t aRow = (size_t)(m0 + lrow);
    int br = n0 + lrow; if (br >= N) br = N - 1;   // clamp; epilogue guards
    const bf16* aH0 = Ahi + aRow * ldA + lc * 8;
    const bf16* aL0 = Alo + aRow * ldA + lc * 8;
    const bf16* rH0 = g_rhH + aRow * KP1 + lc * 8;
    const bf16* rL0 = g_rhL + aRow * KP1 + lc * 8;
    const bf16* bH0 = Bhi + (size_t)br * (NKCH * 16) + lc * 8;
    const bf16* bL0 = Blo + (size_t)br * (NKCH * 16) + lc * 8;

    auto load_chunk = [&](int k0, int st) {
        uint32_t d = sbase + st * 16384 + dstoff;
        const bf16 *ah, *al;
        if (USE_RH && k0 < KP1) { ah = rH0 + k0; al = rL0 + k0; }
        else                    { ah = aH0 + k0; al = aL0 + k0; }
        CP16(d,         ah);
        CP16(d + 4096,  al);
        CP16(d + 8192,  bH0 + k0);
        CP16(d + 12288, bL0 + k0);
        CPCOMMIT();
    };

    const int ra = wm * 64 + (lane & 15); const int ca = lane >> 4;
    const uint32_t aoff = ra * 32 + ((ca ^ ((ra >> 2) & 1)) * 16);
    const int rb = wn * 32 + (lane & 7);  const int cb = (lane >> 3) & 1;
    const uint32_t boff = rb * 32 + ((cb ^ ((rb >> 2) & 1)) * 16);

    float acc[4][4][4];
    #pragma unroll
    for (int i = 0; i < 4; i++)
        #pragma unroll
        for (int j = 0; j < 4; j++)
            #pragma unroll
            for (int e = 0; e < 4; e++) acc[i][j][e] = 0.0f;

    load_chunk(0, 0);
    #pragma unroll
    for (int ch = 0; ch < NKCH; ch++) {
        CPWAIT0();
        __syncthreads();
        if (ch + 1 < NKCH) load_chunk((ch + 1) * 16, (ch + 1) & 1);

        const uint32_t base = sbase + (ch & 1) * 16384;
        const uint32_t aH = base + aoff,        aL = base + 4096  + aoff;
        const uint32_t bH = base + 8192 + boff, bL = base + 12288 + boff;
        unsigned Af[4][4], Bf[4][2];
        #pragma unroll
        for (int mf = 0; mf < 4; mf++) ldsm4(Af[mf], aH + mf * 512);
        #pragma unroll
        for (int nf = 0; nf < 4; nf++) ldsm2(Bf[nf], bH + nf * 256);
        #pragma unroll
        for (int mf = 0; mf < 4; mf++)
            #pragma unroll
            for (int nf = 0; nf < 4; nf++) mma_bf16(acc[mf][nf], Af[mf], Bf[nf]);
        #pragma unroll
        for (int nf = 0; nf < 4; nf++) ldsm2(Bf[nf], bL + nf * 256);
        #pragma unroll
        for (int mf = 0; mf < 4; mf++)
            #pragma unroll
            for (int nf = 0; nf < 4; nf++) mma_bf16(acc[mf][nf], Af[mf], Bf[nf]);
        #pragma unroll
        for (int mf = 0; mf < 4; mf++) ldsm4(Af[mf], aL + mf * 512);
        #pragma unroll
        for (int nf = 0; nf < 4; nf++) ldsm2(Bf[nf], bH + nf * 256);
        #pragma unroll
        for (int mf = 0; mf < 4; mf++)
            #pragma unroll
            for (int nf = 0; nf < 4; nf++) mma_bf16(acc[mf][nf], Af[mf], Bf[nf]);
    }

    const int gID = lane >> 2, tg = lane & 3;
    #pragma unroll
    for (int mf = 0; mf < 4; mf++) {
        const int gmb = m0 + wm * 64 + mf * 16 + gID;
        #pragma unroll
        for (int nf = 0; nf < 4; nf++) {
            const int gnb = n0 + wn * 32 + nf * 8 + tg * 2;
            #pragma unroll
            for (int e = 0; e < 4; e++) {
                int gm = gmb + (e >> 1) * 8;
                int gn = gnb + (e & 1);
                if (gn >= N) continue;
                float v = acc[mf][nf][e];
                if (EPI == 0) {
                    if (bias) v += bias[gn];
                    C[(size_t)gm * ldc + gn] = v;
                } else if (EPI == 1) {
                    float g = sigmoidf_(v + bias[gn]);
                    if (gn < Dd) {
                        float rh = g * x1[(size_t)gm * Dd + gn];
                        size_t o = (size_t)gm * KP1 + gn;
                        split_bf16(rh, g_rhH[o], g_rhL[o]);
                    } else {
                        y2p[(size_t)gm * Dd + (gn - Dd)] = g;
                    }
                } else {
                    float cc = tanhf(v + bias[gn]);
                    float uu = x2[(size_t)gm * Dd + gn];
                    float hh = x1[(size_t)gm * Dd + gn];
                    C[(size_t)gm * ldc + gn] = uu * hh + (1.0f - uu) * cc;
                }
            }
        }
    }
}

// ---------------------------------------------------------------------------
// Logits GEMM: out[512, NOUT] = y1 @ embedding[1:]^T, 3-term split.
// Block 256x128 (512 threads, warp grid 4x4, warp tile 64x32), K = 7 chunks.
// Grid (2, 782) x-fastest: both M-halves reuse the L2-hot B tile.
// B pointers are the UNSHIFTED embedding bases; the 1-row offset of
// embedding[1:] is applied exactly once here via er = 1 + n0 + row.
// Epilogue: smem-staged (133-pad, conflict-free) -> fully coalesced STG.32.
// ---------------------------------------------------------------------------
#define LG_STAGE 24576   // per-stage bytes: AH 8K | AL 8K | BH 4K | BL 4K

__global__ void __launch_bounds__(512)
logits_gemm(const bf16* __restrict__ Ahi, const bf16* __restrict__ Alo,
            const bf16* __restrict__ Bhi, const bf16* __restrict__ Blo,
            float* __restrict__ out)
{
    __shared__ __align__(16) char smem[2 * LG_STAGE];   // 48 KB
    const int tid = threadIdx.x, lane = tid & 31, warp = tid >> 5;
    const int wm = warp >> 2, wn = warp & 3;
    const int m0 = blockIdx.x * 256, n0 = blockIdx.y * 128;
    const uint32_t sbase = smem_u32a(smem);

    // loader: 3 x 16B per thread per stage
    uint32_t ldst[3]; const bf16* lsrc[3];
    #pragma unroll
    for (int j = 0; j < 3; j++) {
        int c = tid + j * 512;       // [0,1536)
        int reg, row;
        if (c < 1024) { reg = c >> 9;              row = (c & 511) >> 1; }
        else          { reg = 2 + ((c >> 8) & 1);  row = (c & 255) >> 1; }
        int half = c & 1;
        uint32_t rb = (reg < 2) ? reg * 8192u : 16384u + (reg - 2) * 4096u;
        ldst[j] = sbase + rb + row * 32 + ((half ^ ((row >> 2) & 1)) * 16);
        if (reg < 2) {
            lsrc[j] = (reg ? Alo : Ahi) + (size_t)(m0 + row) * KP1 + half * 8;
        } else {
            int er = 1 + n0 + row;                  // embedding[1:] offset, applied ONCE
            if (er > NN - 1) er = NN - 1;           // clamp; stores guarded by gn < NOUT
            lsrc[j] = (reg == 3 ? Blo : Bhi) + (size_t)er * KP1 + half * 8;
        }
    }
    auto load_chunk = [&](int k0, int st) {
        uint32_t o = st * LG_STAGE;
        CP16(ldst[0] + o, lsrc[0] + k0);
        CP16(ldst[1] + o, lsrc[1] + k0);
        CP16(ldst[2] + o, lsrc[2] + k0);
        CPCOMMIT();
    };

    const int ra = wm * 64 + (lane & 15); const int ca = lane >> 4;
    const uint32_t aoff = ra * 32 + ((ca ^ ((ra >> 2) & 1)) * 16);
    const int rb2 = wn * 32 + (lane & 7); const int cb = (lane >> 3) & 1;
    const uint32_t boff = rb2 * 32 + ((cb ^ ((rb2 >> 2) & 1)) * 16);

    float acc[4][4][4];
    #pragma unroll
    for (int i = 0; i < 4; i++)
        #pragma unroll
        for (int j = 0; j < 4; j++)
            #pragma unroll
            for (int e = 0; e < 4; e++) acc[i][j][e] = 0.0f;

    load_chunk(0, 0);
    #pragma unroll
    for (int ch = 0; ch < 7; ch++) {
        CPWAIT0();
        __syncthreads();
        if (ch + 1 < 7) load_chunk((ch + 1) * 16, (ch + 1) & 1);

        const uint32_t base = sbase + (ch & 1) * LG_STAGE;
        const uint32_t aH = base + aoff,         aL = base + 8192  + aoff;
        const uint32_t bH = base + 16384 + boff, bL = base + 20480 + boff;
        unsigned Af[4][4], Bf[4][2];
        #pragma unroll
        for (int mf = 0; mf < 4; mf++) ldsm4(Af[mf], aH + mf * 512);
        #pragma unroll
        for (int nf = 0; nf < 4; nf++) ldsm2(Bf[nf], bH + nf * 256);
        #pragma unroll
        for (int mf = 0; mf < 4; mf++)
            #pragma unroll
            for (int nf = 0; nf < 4; nf++) mma_bf16(acc[mf][nf], Af[mf], Bf[nf]);
        #pragma unroll
        for (int nf = 0; nf < 4; nf++) ldsm2(Bf[nf], bL + nf * 256);
        #pragma unroll
        for (int mf = 0; mf < 4; mf++)
            #pragma unroll
            for (int nf = 0; nf < 4; nf++) mma_bf16(acc[mf][nf], Af[mf], Bf[nf]);
        #pragma unroll
        for (int mf = 0; mf < 4; mf++) ldsm4(Af[mf], aL + mf * 512);
        #pragma unroll
        for (int nf = 0; nf < 4; nf++) ldsm2(Bf[nf], bH + nf * 256);
        #pragma unroll
        for (int mf = 0; mf < 4; mf++)
            #pragma unroll
            for (int nf = 0; nf < 4; nf++) mma_bf16(acc[mf][nf], Af[mf], Bf[nf]);
    }

    // ---- staged epilogue: 4 passes of 64 rows x 128 cols ----
    float* stg = (float*)smem;                     // 64*133*4 = 34 KB
    const int gID = lane >> 2, tg = lane & 3;
    #pragma unroll 1
    for (int p = 0; p < 4; p++) {
        __syncthreads();
        if (wm == p) {
            #pragma unroll
            for (int mf = 0; mf < 4; mf++)
                #pragma unroll
                for (int nf = 0; nf < 4; nf++)
                    #pragma unroll
                    for (int e = 0; e < 4; e++) {
                        int lr = mf * 16 + gID + (e >> 1) * 8;
                        int lcc = wn * 32 + nf * 8 + tg * 2 + (e & 1);
                        stg[lr * 133 + lcc] = acc[mf][nf][e];
                    }
        }
        __syncthreads();
        const size_t rowbase = (size_t)(m0 + p * 64);
        #pragma unroll
        for (int i = 0; i < 16; i++) {
            int linear = tid + i * 512;            // [0, 8192)
            int fr = linear >> 7, fc = linear & 127;
            int gn = n0 + fc;
            if (gn < NOUT)
                out[(rowbase + fr) * NOUT + gn] = stg[fr * 133 + fc];
        }
    }
}

// ---------------------------------------------------------------------------
// adj propagation (both dirs, grid (512,2), 640 threads)
// ---------------------------------------------------------------------------
__device__ __forceinline__ void store_split4(size_t o, float a, float b, float c, float d) {
    __nv_bfloat162 h01, h23, l01, l23;
    bf16 h, l;
    split_bf16(a, h, l); h01.x = h; l01.x = l;
    split_bf16(b, h, l); h01.y = h; l01.y = l;
    split_bf16(c, h, l); h23.x = h; l23.x = l;
    split_bf16(d, h, l); h23.y = h; l23.y = l;
    *(__nv_bfloat162*)(g_XH + o)     = h01;
    *(__nv_bfloat162*)(g_XH + o + 2) = h23;
    *(__nv_bfloat162*)(g_XL + o)     = l01;
    *(__nv_bfloat162*)(g_XL + o + 2) = l23;
}

__global__ void __launch_bounds__(640)
adj_kernel(const float* __restrict__ adj_in, const float* __restrict__ adj_out)
{
    __shared__ float adjS[Tt*Tt];
    __shared__ float hS[Tt*Dd];
    int b = blockIdx.x, io = blockIdx.y;
    const float* adj = io ? adj_out : adj_in;
    int tid = threadIdx.x;
    for (int i = tid; i < Tt*Tt; i += 640) adjS[i] = adj[(size_t)b*Tt*Tt + i];
    for (int i = tid; i < Tt*Dd; i += 640) {
        int s = i / Dd, c = i - s * Dd;
        hS[i] = g_hio[(size_t)(b*Tt + s) * 200 + io * Dd + c];
    }
    __syncthreads();

    if (tid < 625) {
        int tg = tid / 25, cg = tid - tg * 25;
        int t0 = tg * 2, c0 = cg * 4;
        ull a00=0, a01=0, a10=0, a11=0;
        ull e00=0, e01=0, e10=0, e11=0;
        #pragma unroll 5
        for (int s = 0; s < Tt; s += 2) {
            const ull* hp = reinterpret_cast<const ull*>(&hS[s * Dd + c0]);
            ull b0 = hp[0], b1 = hp[1];
            float w0 = adjS[t0 * Tt + s], w1 = adjS[(t0+1) * Tt + s];
            ull p0 = pack2(w0, w0), p1 = pack2(w1, w1);
            fma2(a00, p0, b0); fma2(a01, p0, b1);
            fma2(a10, p1, b0); fma2(a11, p1, b1);
            const ull* hq = reinterpret_cast<const ull*>(&hS[(s+1) * Dd + c0]);
            ull c0v = hq[0], c1v = hq[1];
            float v0 = adjS[t0 * Tt + s + 1], v1 = adjS[(t0+1) * Tt + s + 1];
            ull q0 = pack2(v0, v0), q1 = pack2(v1, v1);
            fma2(e00, q0, c0v); fma2(e01, q0, c1v);
            fma2(e10, q1, c0v); fma2(e11, q1, c1v);
        }
        float x0,x1,x2,x3,y0,y1,y2,y3;
        size_t base0 = (size_t)(b*Tt + t0) * KP3 + KP1 + io * KP1 + c0;
        unpack2(a00,x0,x1); unpack2(a01,x2,x3);
        unpack2(e00,y0,y1); unpack2(e01,y2,y3);
        store_split4(base0, x0+y0, x1+y1, x2+y2, x3+y3);
        size_t base1 = base0 + KP3;
        unpack2(a10,x0,x1); unpack2(a11,x2,x3);
        unpack2(e10,y0,y1); unpack2(e11,y2,y3);
        store_split4(base1, x0+y0, x1+y1, x2+y2, x3+y3);
    }
}

// ---------------------------------------------------------------------------
// last vector
// ---------------------------------------------------------------------------
__global__ void last_kernel(const float* __restrict__ mask,
                            const int* __restrict__ alias_,
                            const float* __restrict__ w1)
{
    __shared__ float msum[Tt];
    __shared__ float lh[Dd];
    __shared__ int   liS;
    int b = blockIdx.x, tid = threadIdx.x;
    if (tid < Tt) msum[tid] = mask[b * Tt + tid];
    __syncthreads();
    if (tid == 0) {
        float s = 0.0f;
        for (int t = 0; t < Tt; t++) s += msum[t];
        liS = alias_[b * Tt + ((int)s - 1)];
    }
    __syncthreads();
    int li = liS;
    if (tid < Dd) lh[tid] = g_hnew[(size_t)(b * Tt + li) * Dd + tid];
    __syncthreads();
    if (tid < Dd) {
        float acc = 0.0f;
        #pragma unroll 4
        for (int k = 0; k < Dd; k++) acc += lh[k] * w1[k * Dd + tid];
        g_last[b * Dd + tid] = acc;
    }
}

// ---------------------------------------------------------------------------
// attention + readout; writes split y1 directly
// ---------------------------------------------------------------------------
__global__ void __launch_bounds__(128)
att_kernel(const float* __restrict__ mask, const float* __restrict__ vv,
           const float* __restrict__ nb, const float* __restrict__ Bmat)
{
    __shared__ float lastS[Dd], nbS[Dd], vS[Dd];
    __shared__ float acc4[4][Dd];
    __shared__ float maS[2 * Dd];
    int b = blockIdx.x, tid = threadIdx.x;
    int w = tid >> 5, lane = tid & 31;

    if (tid < Dd) { lastS[tid] = g_last[b * Dd + tid]; nbS[tid] = nb[tid]; vS[tid] = vv[tid]; }
    __syncthreads();

    float accR[4] = {0.f, 0.f, 0.f, 0.f};
    for (int t = w; t < Tt; t += 4) {
        const float* seqrow = &g_seq [(size_t)(b * Tt + t) * Dd];
        const float* shrow  = &g_seqh[(size_t)(b * Tt + t) * Dd];
        float part = 0.0f;
        #pragma unroll
        for (int j = 0; j < 4; j++) {
            int c = lane + 32 * j;
            if (c < Dd) part += sigmoidf_(lastS[c] + seqrow[c] + nbS[c]) * vS[c];
        }
        #pragma unroll
        for (int off = 16; off > 0; off >>= 1)
            part += __shfl_xor_sync(0xffffffffu, part, off);
        float coef = part * mask[b * Tt + t];
        #pragma unroll
        for (int j = 0; j < 4; j++) {
            int c = lane + 32 * j;
            if (c < Dd) accR[j] += coef * shrow[c];
        }
    }
    #pragma unroll
    for (int j = 0; j < 4; j++) {
        int c = lane + 32 * j;
        if (c < Dd) acc4[w][c] = accR[j];
    }
    __syncthreads();
    if (tid < Dd) {
        maS[tid]      = acc4[0][tid] + acc4[1][tid] + acc4[2][tid] + acc4[3][tid];
        maS[Dd + tid] = lastS[tid];
    }
    __syncthreads();
    if (tid < Dd) {
        float y = 0.0f;
        #pragma unroll 4
        for (int k = 0; k < 2 * Dd; k++) y += maS[k] * Bmat[k * Dd + tid];
        split_bf16(y, g_yH[b * KP1 + tid], g_yL[b * KP1 + tid]);
    }
}

// ---------------------------------------------------------------------------
// Host launcher
// ---------------------------------------------------------------------------
static inline int cdiv(int a, int b) { return (a + b - 1) / b; }

extern "C" void kernel_launch(void* const* d_in, const int* in_sizes, int n_in,
                              void* d_out, int out_size)
{
    int o = 0;
    if (n_in < 20 || in_sizes[5] != 1) o = -1;  // step scalar possibly omitted

    const float* adj_in  = (const float*)d_in[0];
    const float* adj_out = (const float*)d_in[1];
    const float* mask    = (const float*)d_in[2];
    const int*   item    = (const int*)  d_in[3];
    const int*   alias_  = (const int*)  d_in[4];
    const float* emb     = (const float*)d_in[6  + o];
    const float* W_in    = (const float*)d_in[7  + o];
    const float* b_in    = (const float*)d_in[8  + o];
    const float* W_out   = (const float*)d_in[9  + o];
    const float* b_out   = (const float*)d_in[10 + o];
    const float* ggk     = (const float*)d_in[11 + o];
    const float* ggb     = (const float*)d_in[12 + o];
    const float* gck     = (const float*)d_in[13 + o];
    const float* gcb     = (const float*)d_in[14 + o];
    const float* w1      = (const float*)d_in[15 + o];
    const float* w2      = (const float*)d_in[16 + o];
    const float* vv      = (const float*)d_in[17 + o];
    const float* nb      = (const float*)d_in[18 + o];
    const float* Bmat    = (const float*)d_in[19 + o];
    float* out = (float*)d_out;

    void* p;
    #define SYM(T, var, sym) cudaGetSymbolAddress(&p, sym); T* var = (T*)p
    SYM(float, ph,    g_h);    SYM(float, phio,  g_hio);
    SYM(float, pu,    g_u);    SYM(float, phnew, g_hnew);
    SYM(float, pseq,  g_seq);  SYM(float, pbio,  g_bio);
    SYM(bf16, peH, g_eH);   SYM(bf16, peL, g_eL);
    SYM(bf16, pXH, g_XH);   SYM(bf16, pXL, g_XL);
    SYM(bf16, psH, g_sH);   SYM(bf16, psL, g_sL);
    SYM(bf16, pyH, g_yH);   SYM(bf16, pyL, g_yL);
    SYM(bf16, pWioH, g_WioH); SYM(bf16, pWioL, g_WioL);
    SYM(bf16, pggkH, g_ggkH); SYM(bf16, pggkL, g_ggkL);
    SYM(bf16, pgckH, g_gckH); SYM(bf16, pgckL, g_gckL);
    SYM(bf16, pw2H, g_w2H);   SYM(bf16, pw2L, g_w2L);
    #undef SYM

    // Launch order puts the first mma_gemm at slot 6 so the ncu capture
    // (-s 5 -c 1) profiles a real GEMM instead of a conversion kernel.
    gather_h_kernel<<<cdiv(BT * KP1, 256), 256>>>(emb, item);                     // 1
    conv_wio_kernel<<<cdiv(2 * Dd * KP1, 256), 256>>>(W_in, W_out, b_in, b_out);  // 2
    conv_wT_kernel<<<cdiv(2 * Dd * KP3, 256), 256>>>(ggk, pggkH, pggkL, 2*Dd, 3); // 3
    conv_wT_kernel<<<cdiv(Dd * KP3, 256), 256>>>(gck, pgckH, pgckL, Dd, 3);       // 4
    conv_wT_kernel<<<cdiv(Dd * KP1, 256), 256>>>(w2, pw2H, pw2L, Dd, 1);          // 5

    // [hin | hout] = h @ [W_in | W_out] + bio   (A = X segment 0, ldA = KP3)
    mma_gemm<0, 7, false><<<dim3(2, BT / 128), 256>>>(                            // 6 (profiled)
        pXH, pXL, KP3, pWioH, pWioL, pbio, phio, 2 * Dd, 2 * Dd,
        nullptr, nullptr, nullptr);

    conv_emb_kernel<<<cdiv(NN * 56, 256), 256>>>(emb);                            // 7

    adj_kernel<<<dim3(Bb, 2), 640>>>(adj_in, adj_out);

    mma_gemm<1, 21, false><<<dim3(2, BT / 128), 256>>>(
        pXH, pXL, KP3, pggkH, pggkL, ggb, nullptr, 2 * Dd, 0,
        ph, nullptr, pu);

    mma_gemm<2, 21, true><<<dim3(1, BT / 128), 256>>>(
        pXH, pXL, KP3, pgckH, pgckL, gcb, phnew, Dd, Dd,
        ph, pu, nullptr);

    // ---- attention readout ----
    last_kernel<<<Bb, 128>>>(mask, alias_, w1);
    seqh_kernel<<<cdiv(BT * KP1, 256), 256>>>(alias_);

    mma_gemm<0, 7, false><<<dim3(1, BT / 128), 256>>>(
        psH, psL, KP1, pw2H, pw2L, nullptr, pseq, Dd, Dd,
        nullptr, nullptr, nullptr);

    att_kernel<<<Bb, 128>>>(mask, vv, nb, Bmat);

    // ---- logits: BM=256 tile, staged coalesced epilogue ----
    // NOTE: pass UNSHIFTED embedding bases; kernel applies the [1:] offset once.
    logits_gemm<<<dim3(2, cdiv(NOUT, 128)), 512>>>(pyH, pyL, peH, peL, out);
}

// round 16
// speedup vs baseline: 1.9197x; 1.0422x over previous
#include <cuda_runtime.h>
#include <cuda_bf16.h>
#include <cstdint>
#include <math.h>

// ---------------------------------------------------------------------------
// Problem constants
// ---------------------------------------------------------------------------
#define Bb   512
#define Tt   50
#define Dd   100
#define BT   (Bb*Tt)          // 25600
#define NN   100000
#define NOUT (NN-1)           // 99999
#define KP1  112              // padded segment width (7 chunks of 16)
#define KP3  336              // 3 padded segments

typedef unsigned long long ull;
typedef __nv_bfloat16 bf16;

// ---------------------------------------------------------------------------
// helpers
// ---------------------------------------------------------------------------
__device__ __forceinline__ ull pack2(float x, float y) {
    ull r; asm("mov.b64 %0, {%1, %2};" : "=l"(r) : "f"(x), "f"(y)); return r;
}
__device__ __forceinline__ void unpack2(ull v, float& x, float& y) {
    asm("mov.b64 {%0, %1}, %2;" : "=f"(x), "=f"(y) : "l"(v));
}
__device__ __forceinline__ void fma2(ull& d, ull a, ull b) {
    asm("fma.rn.f32x2 %0, %1, %2, %3;" : "=l"(d) : "l"(a), "l"(b), "l"(d));
}
__device__ __forceinline__ float sigmoidf_(float x) { return 1.0f / (1.0f + expf(-x)); }

__device__ __forceinline__ void split_bf16(float x, bf16& hi, bf16& lo) {
    bf16 h = __float2bfloat16(x);
    hi = h;
    lo = __float2bfloat16(x - __bfloat162float(h));
}
__device__ __forceinline__ uint32_t smem_u32a(const void* p) {
    return (uint32_t)__cvta_generic_to_shared(p);
}
__device__ __forceinline__ void ldsm4(unsigned r[4], uint32_t a) {
    asm volatile("ldmatrix.sync.aligned.m8n8.x4.shared.b16 {%0,%1,%2,%3},[%4];"
                 : "=r"(r[0]), "=r"(r[1]), "=r"(r[2]), "=r"(r[3]) : "r"(a));
}
__device__ __forceinline__ void ldsm2(unsigned r[2], uint32_t a) {
    asm volatile("ldmatrix.sync.aligned.m8n8.x2.shared.b16 {%0,%1},[%2];"
                 : "=r"(r[0]), "=r"(r[1]) : "r"(a));
}
__device__ __forceinline__ void mma_bf16(float c[4], const unsigned a[4], const unsigned b[2]) {
    asm volatile("mma.sync.aligned.m16n8k16.row.col.f32.bf16.bf16.f32 "
                 "{%0,%1,%2,%3},{%4,%5,%6,%7},{%8,%9},{%0,%1,%2,%3};"
                 : "+f"(c[0]), "+f"(c[1]), "+f"(c[2]), "+f"(c[3])
                 : "r"(a[0]), "r"(a[1]), "r"(a[2]), "r"(a[3]), "r"(b[0]), "r"(b[1]));
}
#define CP16(dst, src) \
    asm volatile("cp.async.cg.shared.global [%0], [%1], 16;" :: "r"(dst), "l"(src))
#define CPCOMMIT() asm volatile("cp.async.commit_group;")
#define CPWAIT0()  asm volatile("cp.async.wait_group 0;")
#define CPWAIT1()  asm volatile("cp.async.wait_group 1;")

// ---------------------------------------------------------------------------
// Scratch (static device globals; zero-initialized at load — segment pads
// k in [100,112) are NEVER written by any kernel, so they stay zero forever)
// ---------------------------------------------------------------------------
__device__ float g_hio [BT*2*Dd];   // [hin | hout] fp32 (adj input)
__device__ float g_h   [BT*Dd];
__device__ float g_u   [BT*Dd];
__device__ float g_hnew[BT*Dd];
__device__ float g_seqh[BT*Dd];
__device__ float g_seq [BT*Dd];
__device__ float g_last[Bb*Dd];
__device__ float g_bio [2*Dd];

// split-bf16 operands (hi/lo), k-major, per-segment padded
__device__ __align__(16) bf16 g_eH[(size_t)NN*KP1], g_eL[(size_t)NN*KP1];  // embedding
__device__ __align__(16) bf16 g_XH[(size_t)BT*KP3], g_XL[(size_t)BT*KP3];  // [h|a_in|a_out]
__device__ __align__(16) bf16 g_rhH[BT*KP1], g_rhL[BT*KP1];                // r*h
__device__ __align__(16) bf16 g_sH[BT*KP1],  g_sL[BT*KP1];                 // seq_h
__device__ __align__(16) bf16 g_yH[Bb*KP1],  g_yL[Bb*KP1];                 // y1
__device__ __align__(16) bf16 g_WioH[2*Dd*KP1], g_WioL[2*Dd*KP1];          // [W_in|W_out]^T
__device__ __align__(16) bf16 g_ggkH[2*Dd*KP3], g_ggkL[2*Dd*KP3];          // ggk^T (seg-permuted)
__device__ __align__(16) bf16 g_gckH[Dd*KP3],   g_gckL[Dd*KP3];            // gck^T (seg-permuted)
__device__ __align__(16) bf16 g_w2H[Dd*KP1],    g_w2L[Dd*KP1];             // w2^T

// ---------------------------------------------------------------------------
// Conversions / gathers
// ---------------------------------------------------------------------------
__global__ void conv_emb_kernel(const float* __restrict__ emb) {
    size_t i = (size_t)blockIdx.x * 256 + threadIdx.x;      // over NN * 56 pairs
    if (i >= (size_t)NN * 56) return;
    size_t r = i / 56; int kp = (int)(i - r * 56) * 2;
    float x0 = 0.f, x1 = 0.f;
    if (kp < Dd) { float2 v = *(const float2*)(emb + r * Dd + kp); x0 = v.x; x1 = v.y; }
    bf16 h0, l0, h1, l1; split_bf16(x0, h0, l0); split_bf16(x1, h1, l1);
    __nv_bfloat162 hh; hh.x = h0; hh.y = h1;
    __nv_bfloat162 ll; ll.x = l0; ll.y = l1;
    *(__nv_bfloat162*)(g_eH + r * KP1 + kp) = hh;
    *(__nv_bfloat162*)(g_eL + r * KP1 + kp) = ll;
}

// transpose + split + segment-permute: W[nseg*100][Norig] -> out[Norig][nseg*112]
__device__ __forceinline__ void conv_wT_one(const float* __restrict__ W,
                                            bf16* __restrict__ oh, bf16* __restrict__ ol,
                                            int Norig, int nseg, int i) {
    int KPp = nseg * KP1;
    int n = i / KPp, kp = i - n * KPp;
    int seg = kp / KP1, off = kp - seg * KP1;
    int blk = (seg + nseg - 1) % nseg;
    float x = (off < Dd) ? W[(blk * Dd + off) * Norig + n] : 0.0f;
    split_bf16(x, oh[i], ol[i]);
}

__global__ void conv_wT_kernel(const float* __restrict__ W,
                               bf16* __restrict__ oh, bf16* __restrict__ ol,
                               int Norig, int nseg) {
    int i = blockIdx.x * 256 + threadIdx.x;
    if (i >= Norig * nseg * KP1) return;
    conv_wT_one(W, oh, ol, Norig, nseg, i);
}

// merged gck (nseg=3) + w2 (nseg=1) conversion
__global__ void conv_wT2_kernel(const float* __restrict__ gck, const float* __restrict__ w2) {
    int i = blockIdx.x * 256 + threadIdx.x;
    if (i < Dd * KP3)                  conv_wT_one(gck, g_gckH, g_gckL, Dd, 3, i);
    else if (i < Dd * KP3 + Dd * KP1)  conv_wT_one(w2,  g_w2H,  g_w2L,  Dd, 1, i - Dd * KP3);
}

__global__ void conv_wio_kernel(const float* __restrict__ W_in, const float* __restrict__ W_out,
                                const float* __restrict__ b_in, const float* __restrict__ b_out) {
    int i = blockIdx.x * 256 + threadIdx.x;
    if (i >= 2 * Dd * KP1) return;
    int n = i / KP1, k = i - n * KP1;
    float x = 0.0f;
    if (k < Dd) x = (n < Dd) ? W_in[k * Dd + n] : W_out[k * Dd + (n - Dd)];
    split_bf16(x, g_WioH[i], g_WioL[i]);
    if (i < 2 * Dd) g_bio[i] = (i < Dd) ? b_in[i] : b_out[i - Dd];
}

// gather h = embedding[item]: fp32 g_h + split into X segment 0
__global__ void gather_h_kernel(const float* __restrict__ emb, const int* __restrict__ item) {
    int i = blockIdx.x * 256 + threadIdx.x;
    if (i >= BT * KP1) return;
    int r = i / KP1, k = i - r * KP1;
    if (k >= Dd) return;                       // pads stay zero (never written)
    float x = emb[(size_t)item[r] * Dd + k];
    g_h[r * Dd + k] = x;
    size_t o = (size_t)r * KP3 + k;
    split_bf16(x, g_XH[o], g_XL[o]);
}

// seq_h gather: fp32 g_seqh + split into sH/sL
__global__ void seqh_kernel(const int* __restrict__ alias_) {
    int i = blockIdx.x * 256 + threadIdx.x;
    if (i >= BT * KP1) return;
    int r = i / KP1, k = i - r * KP1;
    if (k >= Dd) return;
    int b = r / Tt;
    int al = alias_[r];
    float x = g_hnew[(size_t)(b * Tt + al) * Dd + k];
    g_seqh[r * Dd + k] = x;
    split_bf16(x, g_sH[(size_t)r * KP1 + k], g_sL[(size_t)r * KP1 + k]);
}

// ---------------------------------------------------------------------------
// Split-bf16 legacy tensor-core GEMM, cp.async 3-stage pipelined.
// Block 128x128, 8 warps (2x4), warp tile 64x32, mma m16n8k16, 3-term split.
// Mainloop keeps both A fragment sets resident so B-hi is ldsm'd only once:
//   Ah*Bh -> Al*Bh -> Ah*Bl.
// ---------------------------------------------------------------------------
template<int EPI, int NKCH, bool USE_RH>
__global__ void __launch_bounds__(256)
mma_gemm(const bf16* __restrict__ Ahi, const bf16* __restrict__ Alo, int ldA,
         const bf16* __restrict__ Bhi, const bf16* __restrict__ Blo,
         const float* __restrict__ bias, float* __restrict__ C, int N, int ldc,
         const float* __restrict__ x1, const float* __restrict__ x2,
         float* __restrict__ y2p)
{
    __shared__ __align__(16) bf16 smem[3 * 4 * 128 * 16];   // 48 KB (3 stages)
    const int tid = threadIdx.x, lane = tid & 31, warp = tid >> 5;
    const int wm = warp >> 2, wn = warp & 3;
    const int m0 = blockIdx.y * 128, n0 = blockIdx.x * 128;
    const uint32_t sbase = smem_u32a(smem);

    const int lrow = tid >> 1, lc = tid & 1;
    const uint32_t dstoff = lrow * 32 + ((lc ^ ((lrow >> 2) & 1)) * 16);

    const size_t aRow = (size_t)(m0 + lrow);
    int br = n0 + lrow; if (br >= N) br = N - 1;   // clamp; epilogue guards
    const bf16* aH0 = Ahi + aRow * ldA + lc * 8;
    const bf16* aL0 = Alo + aRow * ldA + lc * 8;
    const bf16* rH0 = g_rhH + aRow * KP1 + lc * 8;
    const bf16* rL0 = g_rhL + aRow * KP1 + lc * 8;
    const bf16* bH0 = Bhi + (size_t)br * (NKCH * 16) + lc * 8;
    const bf16* bL0 = Blo + (size_t)br * (NKCH * 16) + lc * 8;

    auto load_chunk = [&](int k0, int st) {
        uint32_t d = sbase + st * 16384 + dstoff;
        const bf16 *ah, *al;
        if (USE_RH && k0 < KP1) { ah = rH0 + k0; al = rL0 + k0; }
        else                    { ah = aH0 + k0; al = aL0 + k0; }
        CP16(d,         ah);
        CP16(d + 4096,  al);
        CP16(d + 8192,  bH0 + k0);
        CP16(d + 12288, bL0 + k0);
        CPCOMMIT();
    };

    const int ra = wm * 64 + (lane & 15); const int ca = lane >> 4;
    const uint32_t aoff = ra * 32 + ((ca ^ ((ra >> 2) & 1)) * 16);
    const int rb = wn * 32 + (lane & 7);  const int cb = (lane >> 3) & 1;
    const uint32_t boff = rb * 32 + ((cb ^ ((rb >> 2) & 1)) * 16);

    float acc[4][4][4];
    #pragma unroll
    for (int i = 0; i < 4; i++)
        #pragma unroll
        for (int j = 0; j < 4; j++)
            #pragma unroll
            for (int e = 0; e < 4; e++) acc[i][j][e] = 0.0f;

    load_chunk(0, 0);
    if (NKCH > 1) load_chunk(16, 1);
    #pragma unroll
    for (int ch = 0; ch < NKCH; ch++) {
        if (ch == NKCH - 1) { CPWAIT0(); } else { CPWAIT1(); }
        __syncthreads();
        if (ch + 2 < NKCH) load_chunk((ch + 2) * 16, (ch + 2) % 3);

        const uint32_t base = sbase + (ch % 3) * 16384;
        const uint32_t aH = base + aoff,        aL = base + 4096  + aoff;
        const uint32_t bH = base + 8192 + boff, bL = base + 12288 + boff;
        unsigned Ahf[4][4], Alf[4][4], Bf[4][2];
        #pragma unroll
        for (int mf = 0; mf < 4; mf++) ldsm4(Ahf[mf], aH + mf * 512);
        #pragma unroll
        for (int mf = 0; mf < 4; mf++) ldsm4(Alf[mf], aL + mf * 512);
        #pragma unroll
        for (int nf = 0; nf < 4; nf++) ldsm2(Bf[nf], bH + nf * 256);
        #pragma unroll
        for (int mf = 0; mf < 4; mf++)
            #pragma unroll
            for (int nf = 0; nf < 4; nf++) mma_bf16(acc[mf][nf], Ahf[mf], Bf[nf]);
        #pragma unroll
        for (int mf = 0; mf < 4; mf++)
            #pragma unroll
            for (int nf = 0; nf < 4; nf++) mma_bf16(acc[mf][nf], Alf[mf], Bf[nf]);
        #pragma unroll
        for (int nf = 0; nf < 4; nf++) ldsm2(Bf[nf], bL + nf * 256);
        #pragma unroll
        for (int mf = 0; mf < 4; mf++)
            #pragma unroll
            for (int nf = 0; nf < 4; nf++) mma_bf16(acc[mf][nf], Ahf[mf], Bf[nf]);
    }

    const int gID = lane >> 2, tg = lane & 3;
    #pragma unroll
    for (int mf = 0; mf < 4; mf++) {
        const int gmb = m0 + wm * 64 + mf * 16 + gID;
        #pragma unroll
        for (int nf = 0; nf < 4; nf++) {
            const int gnb = n0 + wn * 32 + nf * 8 + tg * 2;
            #pragma unroll
            for (int e = 0; e < 4; e++) {
                int gm = gmb + (e >> 1) * 8;
                int gn = gnb + (e & 1);
                if (gn >= N) continue;
                float v = acc[mf][nf][e];
                if (EPI == 0) {
                    if (bias) v += bias[gn];
                    C[(size_t)gm * ldc + gn] = v;
                } else if (EPI == 1) {
                    float g = sigmoidf_(v + bias[gn]);
                    if (gn < Dd) {
                        float rh = g * x1[(size_t)gm * Dd + gn];
                        size_t o = (size_t)gm * KP1 + gn;
                        split_bf16(rh, g_rhH[o], g_rhL[o]);
                    } else {
                        y2p[(size_t)gm * Dd + (gn - Dd)] = g;
                    }
                } else {
                    float cc = tanhf(v + bias[gn]);
                    float uu = x2[(size_t)gm * Dd + gn];
                    float hh = x1[(size_t)gm * Dd + gn];
                    C[(size_t)gm * ldc + gn] = uu * hh + (1.0f - uu) * cc;
                }
            }
        }
    }
}

// ---------------------------------------------------------------------------
// Logits GEMM: out[512, NOUT] = y1 @ embedding[1:]^T, 3-term split.
// Block 256x128 (512 threads, warp grid 4x4, warp tile 64x32), K = 7 chunks,
// 3-stage cp.async (72 KB dynamic smem). Grid (2, 782) x-fastest.
// B pointers are the UNSHIFTED embedding bases; the [1:] offset applied once
// via er = 1 + n0 + row. Epilogue: smem-staged -> fully coalesced STG.32.
// ---------------------------------------------------------------------------
#define LG_STAGE 24576   // per-stage bytes: AH 8K | AL 8K | BH 4K | BL 4K
#define LG_SMEM  (3 * LG_STAGE)

__global__ void __launch_bounds__(512)
logits_gemm(const bf16* __restrict__ Ahi, const bf16* __restrict__ Alo,
            const bf16* __restrict__ Bhi, const bf16* __restrict__ Blo,
            float* __restrict__ out)
{
    extern __shared__ __align__(16) char smem[];   // 72 KB dynamic
    const int tid = threadIdx.x, lane = tid & 31, warp = tid >> 5;
    const int wm = warp >> 2, wn = warp & 3;
    const int m0 = blockIdx.x * 256, n0 = blockIdx.y * 128;
    const uint32_t sbase = smem_u32a(smem);

    // loader: 3 x 16B per thread per stage
    uint32_t ldst[3]; const bf16* lsrc[3];
    #pragma unroll
    for (int j = 0; j < 3; j++) {
        int c = tid + j * 512;       // [0,1536)
        int reg, row;
        if (c < 1024) { reg = c >> 9;              row = (c & 511) >> 1; }
        else          { reg = 2 + ((c >> 8) & 1);  row = (c & 255) >> 1; }
        int half = c & 1;
        uint32_t rb = (reg < 2) ? reg * 8192u : 16384u + (reg - 2) * 4096u;
        ldst[j] = sbase + rb + row * 32 + ((half ^ ((row >> 2) & 1)) * 16);
        if (reg < 2) {
            lsrc[j] = (reg ? Alo : Ahi) + (size_t)(m0 + row) * KP1 + half * 8;
        } else {
            int er = 1 + n0 + row;                  // embedding[1:] offset, applied ONCE
            if (er > NN - 1) er = NN - 1;           // clamp; stores guarded by gn < NOUT
            lsrc[j] = (reg == 3 ? Blo : Bhi) + (size_t)er * KP1 + half * 8;
        }
    }
    auto load_chunk = [&](int k0, int st) {
        uint32_t o = st * LG_STAGE;
        CP16(ldst[0] + o, lsrc[0] + k0);
        CP16(ldst[1] + o, lsrc[1] + k0);
        CP16(ldst[2] + o, lsrc[2] + k0);
        CPCOMMIT();
    };

    const int ra = wm * 64 + (lane & 15); const int ca = lane >> 4;
    const uint32_t aoff = ra * 32 + ((ca ^ ((ra >> 2) & 1)) * 16);
    const int rb2 = wn * 32 + (lane & 7); const int cb = (lane >> 3) & 1;
    const uint32_t boff = rb2 * 32 + ((cb ^ ((rb2 >> 2) & 1)) * 16);

    float acc[4][4][4];
    #pragma unroll
    for (int i = 0; i < 4; i++)
        #pragma unroll
        for (int j = 0; j < 4; j++)
            #pragma unroll
            for (int e = 0; e < 4; e++) acc[i][j][e] = 0.0f;

    load_chunk(0, 0);
    load_chunk(16, 1);
    #pragma unroll
    for (int ch = 0; ch < 7; ch++) {
        if (ch == 6) { CPWAIT0(); } else { CPWAIT1(); }
        __syncthreads();
        if (ch + 2 < 7) load_chunk((ch + 2) * 16, (ch + 2) % 3);

        const uint32_t base = sbase + (ch % 3) * LG_STAGE;
        const uint32_t aH = base + aoff,         aL = base + 8192  + aoff;
        const uint32_t bH = base + 16384 + boff, bL = base + 20480 + boff;
        unsigned Ahf[4][4], Alf[4][4], Bf[4][2];
        #pragma unroll
        for (int mf = 0; mf < 4; mf++) ldsm4(Ahf[mf], aH + mf * 512);
        #pragma unroll
        for (int mf = 0; mf < 4; mf++) ldsm4(Alf[mf], aL + mf * 512);
        #pragma unroll
        for (int nf = 0; nf < 4; nf++) ldsm2(Bf[nf], bH + nf * 256);
        #pragma unroll
        for (int mf = 0; mf < 4; mf++)
            #pragma unroll
            for (int nf = 0; nf < 4; nf++) mma_bf16(acc[mf][nf], Ahf[mf], Bf[nf]);
        #pragma unroll
        for (int mf = 0; mf < 4; mf++)
            #pragma unroll
            for (int nf = 0; nf < 4; nf++) mma_bf16(acc[mf][nf], Alf[mf], Bf[nf]);
        #pragma unroll
        for (int nf = 0; nf < 4; nf++) ldsm2(Bf[nf], bL + nf * 256);
        #pragma unroll
        for (int mf = 0; mf < 4; mf++)
            #pragma unroll
            for (int nf = 0; nf < 4; nf++) mma_bf16(acc[mf][nf], Ahf[mf], Bf[nf]);
    }

    // ---- staged epilogue: 4 passes of 64 rows x 128 cols ----
    float* stg = (float*)smem;                     // 64*133*4 = 34 KB
    const int gID = lane >> 2, tg = lane & 3;
    #pragma unroll 1
    for (int p = 0; p < 4; p++) {
        __syncthreads();
        if (wm == p) {
            #pragma unroll
            for (int mf = 0; mf < 4; mf++)
                #pragma unroll
                for (int nf = 0; nf < 4; nf++)
                    #pragma unroll
                    for (int e = 0; e < 4; e++) {
                        int lr = mf * 16 + gID + (e >> 1) * 8;
                        int lcc = wn * 32 + nf * 8 + tg * 2 + (e & 1);
                        stg[lr * 133 + lcc] = acc[mf][nf][e];
                    }
        }
        __syncthreads();
        const size_t rowbase = (size_t)(m0 + p * 64);
        #pragma unroll
        for (int i = 0; i < 16; i++) {
            int linear = tid + i * 512;            // [0, 8192)
            int fr = linear >> 7, fc = linear & 127;
            int gn = n0 + fc;
            if (gn < NOUT)
                out[(rowbase + fr) * NOUT + gn] = stg[fr * 133 + fc];
        }
    }
}

// ---------------------------------------------------------------------------
// adj propagation (both dirs, grid (512,2), 640 threads)
// ---------------------------------------------------------------------------
__device__ __forceinline__ void store_split4(size_t o, float a, float b, float c, float d) {
    __nv_bfloat162 h01, h23, l01, l23;
    bf16 h, l;
    split_bf16(a, h, l); h01.x = h; l01.x = l;
    split_bf16(b, h, l); h01.y = h; l01.y = l;
    split_bf16(c, h, l); h23.x = h; l23.x = l;
    split_bf16(d, h, l); h23.y = h; l23.y = l;
    *(__nv_bfloat162*)(g_XH + o)     = h01;
    *(__nv_bfloat162*)(g_XH + o + 2) = h23;
    *(__nv_bfloat162*)(g_XL + o)     = l01;
    *(__nv_bfloat162*)(g_XL + o + 2) = l23;
}

__global__ void __launch_bounds__(640)
adj_kernel(const float* __restrict__ adj_in, const float* __restrict__ adj_out)
{
    __shared__ float adjS[Tt*Tt];
    __shared__ float hS[Tt*Dd];
    int b = blockIdx.x, io = blockIdx.y;
    const float* adj = io ? adj_out : adj_in;
    int tid = threadIdx.x;
    for (int i = tid; i < Tt*Tt; i += 640) adjS[i] = adj[(size_t)b*Tt*Tt + i];
    for (int i = tid; i < Tt*Dd; i += 640) {
        int s = i / Dd, c = i - s * Dd;
        hS[i] = g_hio[(size_t)(b*Tt + s) * 200 + io * Dd + c];
    }
    __syncthreads();

    if (tid < 625) {
        int tg = tid / 25, cg = tid - tg * 25;
        int t0 = tg * 2, c0 = cg * 4;
        ull a00=0, a01=0, a10=0, a11=0;
        ull e00=0, e01=0, e10=0, e11=0;
        #pragma unroll 5
        for (int s = 0; s < Tt; s += 2) {
            const ull* hp = reinterpret_cast<const ull*>(&hS[s * Dd + c0]);
            ull b0 = hp[0], b1 = hp[1];
            float w0 = adjS[t0 * Tt + s], w1 = adjS[(t0+1) * Tt + s];
            ull p0 = pack2(w0, w0), p1 = pack2(w1, w1);
            fma2(a00, p0, b0); fma2(a01, p0, b1);
            fma2(a10, p1, b0); fma2(a11, p1, b1);
            const ull* hq = reinterpret_cast<const ull*>(&hS[(s+1) * Dd + c0]);
            ull c0v = hq[0], c1v = hq[1];
            float v0 = adjS[t0 * Tt + s + 1], v1 = adjS[(t0+1) * Tt + s + 1];
            ull q0 = pack2(v0, v0), q1 = pack2(v1, v1);
            fma2(e00, q0, c0v); fma2(e01, q0, c1v);
            fma2(e10, q1, c0v); fma2(e11, q1, c1v);
        }
        float x0,x1,x2,x3,y0,y1,y2,y3;
        size_t base0 = (size_t)(b*Tt + t0) * KP3 + KP1 + io * KP1 + c0;
        unpack2(a00,x0,x1); unpack2(a01,x2,x3);
        unpack2(e00,y0,y1); unpack2(e01,y2,y3);
        store_split4(base0, x0+y0, x1+y1, x2+y2, x3+y3);
        size_t base1 = base0 + KP3;
        unpack2(a10,x0,x1); unpack2(a11,x2,x3);
        unpack2(e10,y0,y1); unpack2(e11,y2,y3);
        store_split4(base1, x0+y0, x1+y1, x2+y2, x3+y3);
    }
}

// ---------------------------------------------------------------------------
// last vector
// ---------------------------------------------------------------------------
__global__ void last_kernel(const float* __restrict__ mask,
                            const int* __restrict__ alias_,
                            const float* __restrict__ w1)
{
    __shared__ float msum[Tt];
    __shared__ float lh[Dd];
    __shared__ int   liS;
    int b = blockIdx.x, tid = threadIdx.x;
    if (tid < Tt) msum[tid] = mask[b * Tt + tid];
    __syncthreads();
    if (tid == 0) {
        float s = 0.0f;
        for (int t = 0; t < Tt; t++) s += msum[t];
        liS = alias_[b * Tt + ((int)s - 1)];
    }
    __syncthreads();
    int li = liS;
    if (tid < Dd) lh[tid] = g_hnew[(size_t)(b * Tt + li) * Dd + tid];
    __syncthreads();
    if (tid < Dd) {
        float acc = 0.0f;
        #pragma unroll 4
        for (int k = 0; k < Dd; k++) acc += lh[k] * w1[k * Dd + tid];
        g_last[b * Dd + tid] = acc;
    }
}

// ---------------------------------------------------------------------------
// attention + readout; writes split y1 directly
// ---------------------------------------------------------------------------
__global__ void __launch_bounds__(128)
att_kernel(const float* __restrict__ mask, const float* __restrict__ vv,
           const float* __restrict__ nb, const float* __restrict__ Bmat)
{
    __shared__ float lastS[Dd], nbS[Dd], vS[Dd];
    __shared__ float acc4[4][Dd];
    __shared__ float maS[2 * Dd];
    int b = blockIdx.x, tid = threadIdx.x;
    int w = tid >> 5, lane = tid & 31;

    if (tid < Dd) { lastS[tid] = g_last[b * Dd + tid]; nbS[tid] = nb[tid]; vS[tid] = vv[tid]; }
    __syncthreads();

    float accR[4] = {0.f, 0.f, 0.f, 0.f};
    for (int t = w; t < Tt; t += 4) {
        const float* seqrow = &g_seq [(size_t)(b * Tt + t) * Dd];
        const float* shrow  = &g_seqh[(size_t)(b * Tt + t) * Dd];
        float part = 0.0f;
        #pragma unroll
        for (int j = 0; j < 4; j++) {
            int c = lane + 32 * j;
            if (c < Dd) part += sigmoidf_(lastS[c] + seqrow[c] + nbS[c]) * vS[c];
        }
        #pragma unroll
        for (int off = 16; off > 0; off >>= 1)
            part += __shfl_xor_sync(0xffffffffu, part, off);
        float coef = part * mask[b * Tt + t];
        #pragma unroll
        for (int j = 0; j < 4; j++) {
            int c = lane + 32 * j;
            if (c < Dd) accR[j] += coef * shrow[c];
        }
    }
    #pragma unroll
    for (int j = 0; j < 4; j++) {
        int c = lane + 32 * j;
        if (c < Dd) acc4[w][c] = accR[j];
    }
    __syncthreads();
    if (tid < Dd) {
        maS[tid]      = acc4[0][tid] + acc4[1][tid] + acc4[2][tid] + acc4[3][tid];
        maS[Dd + tid] = lastS[tid];
    }
    __syncthreads();
    if (tid < Dd) {
        float y = 0.0f;
        #pragma unroll 4
        for (int k = 0; k < 2 * Dd; k++) y += maS[k] * Bmat[k * Dd + tid];
        split_bf16(y, g_yH[b * KP1 + tid], g_yL[b * KP1 + tid]);
    }
}

// ---------------------------------------------------------------------------
// Host launcher
// ---------------------------------------------------------------------------
static inline int cdiv(int a, int b) { return (a + b - 1) / b; }

extern "C" void kernel_launch(void* const* d_in, const int* in_sizes, int n_in,
                              void* d_out, int out_size)
{
    int o = 0;
    if (n_in < 20 || in_sizes[5] != 1) o = -1;  // step scalar possibly omitted

    const float* adj_in  = (const float*)d_in[0];
    const float* adj_out = (const float*)d_in[1];
    const float* mask    = (const float*)d_in[2];
    const int*   item    = (const int*)  d_in[3];
    const int*   alias_  = (const int*)  d_in[4];
    const float* emb     = (const float*)d_in[6  + o];
    const float* W_in    = (const float*)d_in[7  + o];
    const float* b_in    = (const float*)d_in[8  + o];
    const float* W_out   = (const float*)d_in[9  + o];
    const float* b_out   = (const float*)d_in[10 + o];
    const float* ggk     = (const float*)d_in[11 + o];
    const float* ggb     = (const float*)d_in[12 + o];
    const float* gck     = (const float*)d_in[13 + o];
    const float* gcb     = (const float*)d_in[14 + o];
    const float* w1      = (const float*)d_in[15 + o];
    const float* w2      = (const float*)d_in[16 + o];
    const float* vv      = (const float*)d_in[17 + o];
    const float* nb      = (const float*)d_in[18 + o];
    const float* Bmat    = (const float*)d_in[19 + o];
    float* out = (float*)d_out;

    void* p;
    #define SYM(T, var, sym) cudaGetSymbolAddress(&p, sym); T* var = (T*)p
    SYM(float, ph,    g_h);    SYM(float, phio,  g_hio);
    SYM(float, pu,    g_u);    SYM(float, phnew, g_hnew);
    SYM(float, pseq,  g_seq);  SYM(float, pbio,  g_bio);
    SYM(bf16, peH, g_eH);   SYM(bf16, peL, g_eL);
    SYM(bf16, pXH, g_XH);   SYM(bf16, pXL, g_XL);
    SYM(bf16, psH, g_sH);   SYM(bf16, psL, g_sL);
    SYM(bf16, pyH, g_yH);   SYM(bf16, pyL, g_yL);
    SYM(bf16, pWioH, g_WioH); SYM(bf16, pWioL, g_WioL);
    SYM(bf16, pggkH, g_ggkH); SYM(bf16, pggkL, g_ggkL);
    #undef SYM

    static bool attr_set = false;
    if (!attr_set) {
        cudaFuncSetAttribute(logits_gemm,
                             cudaFuncAttributeMaxDynamicSharedMemorySize, LG_SMEM);
        attr_set = true;
    }

    // Harness inserts 2 launches before ours; ncu (-s 5 -c 1) profiles OUR
    // launch #4 — placed so that's the hio mma_gemm (real mainloop data).
    gather_h_kernel<<<cdiv(BT * KP1, 256), 256>>>(emb, item);                     // 1
    conv_wio_kernel<<<cdiv(2 * Dd * KP1, 256), 256>>>(W_in, W_out, b_in, b_out);  // 2
    conv_wT_kernel<<<cdiv(2 * Dd * KP3, 256), 256>>>(ggk, pggkH, pggkL, 2*Dd, 3); // 3

    // [hin | hout] = h @ [W_in | W_out] + bio   (A = X segment 0, ldA = KP3)
    mma_gemm<0, 7, false><<<dim3(2, BT / 128), 256>>>(                            // 4 (profiled)
        pXH, pXL, KP3, pWioH, pWioL, pbio, phio, 2 * Dd, 2 * Dd,
        nullptr, nullptr, nullptr);

    conv_wT2_kernel<<<cdiv(Dd * (KP3 + KP1), 256), 256>>>(gck, w2);               // 5
    conv_emb_kernel<<<cdiv(NN * 56, 256), 256>>>(emb);                            // 6

    adj_kernel<<<dim3(Bb, 2), 640>>>(adj_in, adj_out);

    mma_gemm<1, 21, false><<<dim3(2, BT / 128), 256>>>(
        pXH, pXL, KP3, pggkH, pggkL, ggb, nullptr, 2 * Dd, 0,
        ph, nullptr, pu);

    {
        void* q;
        cudaGetSymbolAddress(&q, g_gckH); bf16* pgckH = (bf16*)q;
        cudaGetSymbolAddress(&q, g_gckL); bf16* pgckL = (bf16*)q;
        mma_gemm<2, 21, true><<<dim3(1, BT / 128), 256>>>(
            pXH, pXL, KP3, pgckH, pgckL, gcb, phnew, Dd, Dd,
            ph, pu, nullptr);
    }

    // ---- attention readout ----
    last_kernel<<<Bb, 128>>>(mask, alias_, w1);
    seqh_kernel<<<cdiv(BT * KP1, 256), 256>>>(alias_);

    {
        void* q;
        cudaGetSymbolAddress(&q, g_w2H); bf16* pw2H = (bf16*)q;
        cudaGetSymbolAddress(&q, g_w2L); bf16* pw2L = (bf16*)q;
        mma_gemm<0, 7, false><<<dim3(1, BT / 128), 256>>>(
            psH, psL, KP1, pw2H, pw2L, nullptr, pseq, Dd, Dd,
            nullptr, nullptr, nullptr);
    }

    att_kernel<<<Bb, 128>>>(mask, vv, nb, Bmat);

    // ---- logits: BM=256 tile, 3-stage pipeline, staged coalesced epilogue ----
    logits_gemm<<<dim3(2, cdiv(NOUT, 128)), 512, LG_SMEM>>>(pyH, pyL, peH, peL, out);
}

// round 17
// speedup vs baseline: 1.9318x; 1.0063x over previous
#include <cuda_runtime.h>
#include <cuda_bf16.h>
#include <cstdint>
#include <math.h>

// ---------------------------------------------------------------------------
// Problem constants
// ---------------------------------------------------------------------------
#define Bb   512
#define Tt   50
#define Dd   100
#define BT   (Bb*Tt)          // 25600
#define NN   100000
#define NOUT (NN-1)           // 99999
#define KP1  112              // padded segment width (7 chunks of 16)
#define KP3  336              // 3 padded segments

typedef unsigned long long ull;
typedef __nv_bfloat16 bf16;

// ---------------------------------------------------------------------------
// helpers
// ---------------------------------------------------------------------------
__device__ __forceinline__ ull pack2(float x, float y) {
    ull r; asm("mov.b64 %0, {%1, %2};" : "=l"(r) : "f"(x), "f"(y)); return r;
}
__device__ __forceinline__ void unpack2(ull v, float& x, float& y) {
    asm("mov.b64 {%0, %1}, %2;" : "=f"(x), "=f"(y) : "l"(v));
}
__device__ __forceinline__ void fma2(ull& d, ull a, ull b) {
    asm("fma.rn.f32x2 %0, %1, %2, %3;" : "=l"(d) : "l"(a), "l"(b), "l"(d));
}
__device__ __forceinline__ float sigmoidf_(float x) { return 1.0f / (1.0f + expf(-x)); }

__device__ __forceinline__ void split_bf16(float x, bf16& hi, bf16& lo) {
    bf16 h = __float2bfloat16(x);
    hi = h;
    lo = __float2bfloat16(x - __bfloat162float(h));
}
__device__ __forceinline__ uint32_t smem_u32a(const void* p) {
    return (uint32_t)__cvta_generic_to_shared(p);
}
__device__ __forceinline__ void ldsm4(unsigned r[4], uint32_t a) {
    asm volatile("ldmatrix.sync.aligned.m8n8.x4.shared.b16 {%0,%1,%2,%3},[%4];"
                 : "=r"(r[0]), "=r"(r[1]), "=r"(r[2]), "=r"(r[3]) : "r"(a));
}
__device__ __forceinline__ void ldsm2(unsigned r[2], uint32_t a) {
    asm volatile("ldmatrix.sync.aligned.m8n8.x2.shared.b16 {%0,%1},[%2];"
                 : "=r"(r[0]), "=r"(r[1]) : "r"(a));
}
__device__ __forceinline__ void mma_bf16(float c[4], const unsigned a[4], const unsigned b[2]) {
    asm volatile("mma.sync.aligned.m16n8k16.row.col.f32.bf16.bf16.f32 "
                 "{%0,%1,%2,%3},{%4,%5,%6,%7},{%8,%9},{%0,%1,%2,%3};"
                 : "+f"(c[0]), "+f"(c[1]), "+f"(c[2]), "+f"(c[3])
                 : "r"(a[0]), "r"(a[1]), "r"(a[2]), "r"(a[3]), "r"(b[0]), "r"(b[1]));
}
#define CP16(dst, src) \
    asm volatile("cp.async.cg.shared.global [%0], [%1], 16;" :: "r"(dst), "l"(src))
#define CPCOMMIT() asm volatile("cp.async.commit_group;")
#define CPWAIT0()  asm volatile("cp.async.wait_group 0;")
#define CPWAIT1()  asm volatile("cp.async.wait_group 1;")

// ---------------------------------------------------------------------------
// Scratch (static device globals; zero-initialized at load — segment pads
// k in [100,112) are NEVER written by any kernel, so they stay zero forever)
// ---------------------------------------------------------------------------
__device__ float g_hio [BT*2*Dd];   // [hin | hout] fp32 (adj input)
__device__ float g_h   [BT*Dd];
__device__ float g_u   [BT*Dd];
__device__ float g_hnew[BT*Dd];
__device__ float g_seqh[BT*Dd];
__device__ float g_seq [BT*Dd];
__device__ float g_last[Bb*Dd];
__device__ float g_bio [2*Dd];

// split-bf16 operands (hi/lo), k-major, per-segment padded
__device__ __align__(16) bf16 g_eH[(size_t)NN*KP1], g_eL[(size_t)NN*KP1];  // embedding
__device__ __align__(16) bf16 g_XH[(size_t)BT*KP3], g_XL[(size_t)BT*KP3];  // [h|a_in|a_out]
__device__ __align__(16) bf16 g_rhH[BT*KP1], g_rhL[BT*KP1];                // r*h
__device__ __align__(16) bf16 g_sH[BT*KP1],  g_sL[BT*KP1];                 // seq_h
__device__ __align__(16) bf16 g_yH[Bb*KP1],  g_yL[Bb*KP1];                 // y1
__device__ __align__(16) bf16 g_WioH[2*Dd*KP1], g_WioL[2*Dd*KP1];          // [W_in|W_out]^T
__device__ __align__(16) bf16 g_ggkH[2*Dd*KP3], g_ggkL[2*Dd*KP3];          // ggk^T (seg-permuted)
__device__ __align__(16) bf16 g_gckH[Dd*KP3],   g_gckL[Dd*KP3];            // gck^T (seg-permuted)
__device__ __align__(16) bf16 g_w2H[Dd*KP1],    g_w2L[Dd*KP1];             // w2^T

// ---------------------------------------------------------------------------
// Conversions / gathers
// ---------------------------------------------------------------------------
__global__ void conv_emb_kernel(const float* __restrict__ emb) {
    size_t i = (size_t)blockIdx.x * 256 + threadIdx.x;      // over NN * 56 pairs
    if (i >= (size_t)NN * 56) return;
    size_t r = i / 56; int kp = (int)(i - r * 56) * 2;
    float x0 = 0.f, x1 = 0.f;
    if (kp < Dd) { float2 v = *(const float2*)(emb + r * Dd + kp); x0 = v.x; x1 = v.y; }
    bf16 h0, l0, h1, l1; split_bf16(x0, h0, l0); split_bf16(x1, h1, l1);
    __nv_bfloat162 hh; hh.x = h0; hh.y = h1;
    __nv_bfloat162 ll; ll.x = l0; ll.y = l1;
    *(__nv_bfloat162*)(g_eH + r * KP1 + kp) = hh;
    *(__nv_bfloat162*)(g_eL + r * KP1 + kp) = ll;
}

// transpose + split + segment-permute: W[nseg*100][Norig] -> out[Norig][nseg*112]
__device__ __forceinline__ void conv_wT_one(const float* __restrict__ W,
                                            bf16* __restrict__ oh, bf16* __restrict__ ol,
                                            int Norig, int nseg, int i) {
    int KPp = nseg * KP1;
    int n = i / KPp, kp = i - n * KPp;
    int seg = kp / KP1, off = kp - seg * KP1;
    int blk = (seg + nseg - 1) % nseg;
    float x = (off < Dd) ? W[(blk * Dd + off) * Norig + n] : 0.0f;
    split_bf16(x, oh[i], ol[i]);
}

__global__ void conv_wT_kernel(const float* __restrict__ W,
                               bf16* __restrict__ oh, bf16* __restrict__ ol,
                               int Norig, int nseg) {
    int i = blockIdx.x * 256 + threadIdx.x;
    if (i >= Norig * nseg * KP1) return;
    conv_wT_one(W, oh, ol, Norig, nseg, i);
}

// merged gck (nseg=3) + w2 (nseg=1) conversion
__global__ void conv_wT2_kernel(const float* __restrict__ gck, const float* __restrict__ w2) {
    int i = blockIdx.x * 256 + threadIdx.x;
    if (i < Dd * KP3)                  conv_wT_one(gck, g_gckH, g_gckL, Dd, 3, i);
    else if (i < Dd * KP3 + Dd * KP1)  conv_wT_one(w2,  g_w2H,  g_w2L,  Dd, 1, i - Dd * KP3);
}

__global__ void conv_wio_kernel(const float* __restrict__ W_in, const float* __restrict__ W_out,
                                const float* __restrict__ b_in, const float* __restrict__ b_out) {
    int i = blockIdx.x * 256 + threadIdx.x;
    if (i >= 2 * Dd * KP1) return;
    int n = i / KP1, k = i - n * KP1;
    float x = 0.0f;
    if (k < Dd) x = (n < Dd) ? W_in[k * Dd + n] : W_out[k * Dd + (n - Dd)];
    split_bf16(x, g_WioH[i], g_WioL[i]);
    if (i < 2 * Dd) g_bio[i] = (i < Dd) ? b_in[i] : b_out[i - Dd];
}

// gather h = embedding[item]: fp32 g_h + split into X segment 0
__global__ void gather_h_kernel(const float* __restrict__ emb, const int* __restrict__ item) {
    int i = blockIdx.x * 256 + threadIdx.x;
    if (i >= BT * KP1) return;
    int r = i / KP1, k = i - r * KP1;
    if (k >= Dd) return;                       // pads stay zero (never written)
    float x = emb[(size_t)item[r] * Dd + k];
    g_h[r * Dd + k] = x;
    size_t o = (size_t)r * KP3 + k;
    split_bf16(x, g_XH[o], g_XL[o]);
}

// seq_h gather: fp32 g_seqh + split into sH/sL
__global__ void seqh_kernel(const int* __restrict__ alias_) {
    int i = blockIdx.x * 256 + threadIdx.x;
    if (i >= BT * KP1) return;
    int r = i / KP1, k = i - r * KP1;
    if (k >= Dd) return;
    int b = r / Tt;
    int al = alias_[r];
    float x = g_hnew[(size_t)(b * Tt + al) * Dd + k];
    g_seqh[r * Dd + k] = x;
    split_bf16(x, g_sH[(size_t)r * KP1 + k], g_sL[(size_t)r * KP1 + k]);
}

// ---------------------------------------------------------------------------
// Split-bf16 legacy tensor-core GEMM, cp.async 3-stage pipelined.
// Block 128x128, 8 warps (2x4), warp tile 64x32, mma m16n8k16, 3-term split.
// __launch_bounds__(256, 2): cap regs at 128 -> 2 CTAs/SM (occ was the
// measured bottleneck: regs=138 -> 1 CTA, issue=8.7%, tensor=20.7%).
// Mainloop keeps both A fragment sets resident so B-hi is ldsm'd only once:
//   Ah*Bh -> Al*Bh -> Ah*Bl.
// ---------------------------------------------------------------------------
template<int EPI, int NKCH, bool USE_RH>
__global__ void __launch_bounds__(256, 2)
mma_gemm(const bf16* __restrict__ Ahi, const bf16* __restrict__ Alo, int ldA,
         const bf16* __restrict__ Bhi, const bf16* __restrict__ Blo,
         const float* __restrict__ bias, float* __restrict__ C, int N, int ldc,
         const float* __restrict__ x1, const float* __restrict__ x2,
         float* __restrict__ y2p)
{
    __shared__ __align__(16) bf16 smem[3 * 4 * 128 * 16];   // 48 KB (3 stages)
    const int tid = threadIdx.x, lane = tid & 31, warp = tid >> 5;
    const int wm = warp >> 2, wn = warp & 3;
    const int m0 = blockIdx.y * 128, n0 = blockIdx.x * 128;
    const uint32_t sbase = smem_u32a(smem);

    const int lrow = tid >> 1, lc = tid & 1;
    const uint32_t dstoff = lrow * 32 + ((lc ^ ((lrow >> 2) & 1)) * 16);

    const size_t aRow = (size_t)(m0 + lrow);
    int br = n0 + lrow; if (br >= N) br = N - 1;   // clamp; epilogue guards
    const bf16* aH0 = Ahi + aRow * ldA + lc * 8;
    const bf16* aL0 = Alo + aRow * ldA + lc * 8;
    const bf16* rH0 = g_rhH + aRow * KP1 + lc * 8;
    const bf16* rL0 = g_rhL + aRow * KP1 + lc * 8;
    const bf16* bH0 = Bhi + (size_t)br * (NKCH * 16) + lc * 8;
    const bf16* bL0 = Blo + (size_t)br * (NKCH * 16) + lc * 8;

    auto load_chunk = [&](int k0, int st) {
        uint32_t d = sbase + st * 16384 + dstoff;
        const bf16 *ah, *al;
        if (USE_RH && k0 < KP1) { ah = rH0 + k0; al = rL0 + k0; }
        else                    { ah = aH0 + k0; al = aL0 + k0; }
        CP16(d,         ah);
        CP16(d + 4096,  al);
        CP16(d + 8192,  bH0 + k0);
        CP16(d + 12288, bL0 + k0);
        CPCOMMIT();
    };

    const int ra = wm * 64 + (lane & 15); const int ca = lane >> 4;
    const uint32_t aoff = ra * 32 + ((ca ^ ((ra >> 2) & 1)) * 16);
    const int rb = wn * 32 + (lane & 7);  const int cb = (lane >> 3) & 1;
    const uint32_t boff = rb * 32 + ((cb ^ ((rb >> 2) & 1)) * 16);

    float acc[4][4][4];
    #pragma unroll
    for (int i = 0; i < 4; i++)
        #pragma unroll
        for (int j = 0; j < 4; j++)
            #pragma unroll
            for (int e = 0; e < 4; e++) acc[i][j][e] = 0.0f;

    load_chunk(0, 0);
    if (NKCH > 1) load_chunk(16, 1);
    #pragma unroll
    for (int ch = 0; ch < NKCH; ch++) {
        if (ch == NKCH - 1) { CPWAIT0(); } else { CPWAIT1(); }
        __syncthreads();
        if (ch + 2 < NKCH) load_chunk((ch + 2) * 16, (ch + 2) % 3);

        const uint32_t base = sbase + (ch % 3) * 16384;
        const uint32_t aH = base + aoff,        aL = base + 4096  + aoff;
        const uint32_t bH = base + 8192 + boff, bL = base + 12288 + boff;
        unsigned Ahf[4][4], Alf[4][4], Bf[4][2];
        #pragma unroll
        for (int mf = 0; mf < 4; mf++) ldsm4(Ahf[mf], aH + mf * 512);
        #pragma unroll
        for (int mf = 0; mf < 4; mf++) ldsm4(Alf[mf], aL + mf * 512);
        #pragma unroll
        for (int nf = 0; nf < 4; nf++) ldsm2(Bf[nf], bH + nf * 256);
        #pragma unroll
        for (int mf = 0; mf < 4; mf++)
            #pragma unroll
            for (int nf = 0; nf < 4; nf++) mma_bf16(acc[mf][nf], Ahf[mf], Bf[nf]);
        #pragma unroll
        for (int mf = 0; mf < 4; mf++)
            #pragma unroll
            for (int nf = 0; nf < 4; nf++) mma_bf16(acc[mf][nf], Alf[mf], Bf[nf]);
        #pragma unroll
        for (int nf = 0; nf < 4; nf++) ldsm2(Bf[nf], bL + nf * 256);
        #pragma unroll
        for (int mf = 0; mf < 4; mf++)
            #pragma unroll
            for (int nf = 0; nf < 4; nf++) mma_bf16(acc[mf][nf], Ahf[mf], Bf[nf]);
    }

    const int gID = lane >> 2, tg = lane & 3;
    #pragma unroll
    for (int mf = 0; mf < 4; mf++) {
        const int gmb = m0 + wm * 64 + mf * 16 + gID;
        #pragma unroll
        for (int nf = 0; nf < 4; nf++) {
            const int gnb = n0 + wn * 32 + nf * 8 + tg * 2;
            #pragma unroll
            for (int e = 0; e < 4; e++) {
                int gm = gmb + (e >> 1) * 8;
                int gn = gnb + (e & 1);
                if (gn >= N) continue;
                float v = acc[mf][nf][e];
                if (EPI == 0) {
                    if (bias) v += bias[gn];
                    C[(size_t)gm * ldc + gn] = v;
                } else if (EPI == 1) {
                    float g = sigmoidf_(v + bias[gn]);
                    if (gn < Dd) {
                        float rh = g * x1[(size_t)gm * Dd + gn];
                        size_t o = (size_t)gm * KP1 + gn;
                        split_bf16(rh, g_rhH[o], g_rhL[o]);
                    } else {
                        y2p[(size_t)gm * Dd + (gn - Dd)] = g;
                    }
                } else {
                    float cc = tanhf(v + bias[gn]);
                    float uu = x2[(size_t)gm * Dd + gn];
                    float hh = x1[(size_t)gm * Dd + gn];
                    C[(size_t)gm * ldc + gn] = uu * hh + (1.0f - uu) * cc;
                }
            }
        }
    }
}

// ---------------------------------------------------------------------------
// Logits GEMM: out[512, NOUT] = y1 @ embedding[1:]^T, 3-term split.
// Block 256x128 (512 threads, warp grid 4x4, warp tile 64x32), K = 7 chunks,
// 3-stage cp.async (72 KB dynamic smem). Grid (2, 782) x-fastest.
// B pointers are the UNSHIFTED embedding bases; the [1:] offset applied once
// via er = 1 + n0 + row. Epilogue: smem-staged -> fully coalesced STG.32.
// (512 thr can never reach 2 CTAs/SM at >=64 regs; already 16 warps/SM.)
// ---------------------------------------------------------------------------
#define LG_STAGE 24576   // per-stage bytes: AH 8K | AL 8K | BH 4K | BL 4K
#define LG_SMEM  (3 * LG_STAGE)

__global__ void __launch_bounds__(512)
logits_gemm(const bf16* __restrict__ Ahi, const bf16* __restrict__ Alo,
            const bf16* __restrict__ Bhi, const bf16* __restrict__ Blo,
            float* __restrict__ out)
{
    extern __shared__ __align__(16) char smem[];   // 72 KB dynamic
    const int tid = threadIdx.x, lane = tid & 31, warp = tid >> 5;
    const int wm = warp >> 2, wn = warp & 3;
    const int m0 = blockIdx.x * 256, n0 = blockIdx.y * 128;
    const uint32_t sbase = smem_u32a(smem);

    // loader: 3 x 16B per thread per stage
    uint32_t ldst[3]; const bf16* lsrc[3];
    #pragma unroll
    for (int j = 0; j < 3; j++) {
        int c = tid + j * 512;       // [0,1536)
        int reg, row;
        if (c < 1024) { reg = c >> 9;              row = (c & 511) >> 1; }
        else          { reg = 2 + ((c >> 8) & 1);  row = (c & 255) >> 1; }
        int half = c & 1;
        uint32_t rb = (reg < 2) ? reg * 8192u : 16384u + (reg - 2) * 4096u;
        ldst[j] = sbase + rb + row * 32 + ((half ^ ((row >> 2) & 1)) * 16);
        if (reg < 2) {
            lsrc[j] = (reg ? Alo : Ahi) + (size_t)(m0 + row) * KP1 + half * 8;
        } else {
            int er = 1 + n0 + row;                  // embedding[1:] offset, applied ONCE
            if (er > NN - 1) er = NN - 1;           // clamp; stores guarded by gn < NOUT
            lsrc[j] = (reg == 3 ? Blo : Bhi) + (size_t)er * KP1 + half * 8;
        }
    }
    auto load_chunk = [&](int k0, int st) {
        uint32_t o = st * LG_STAGE;
        CP16(ldst[0] + o, lsrc[0] + k0);
        CP16(ldst[1] + o, lsrc[1] + k0);
        CP16(ldst[2] + o, lsrc[2] + k0);
        CPCOMMIT();
    };

    const int ra = wm * 64 + (lane & 15); const int ca = lane >> 4;
    const uint32_t aoff = ra * 32 + ((ca ^ ((ra >> 2) & 1)) * 16);
    const int rb2 = wn * 32 + (lane & 7); const int cb = (lane >> 3) & 1;
    const uint32_t boff = rb2 * 32 + ((cb ^ ((rb2 >> 2) & 1)) * 16);

    float acc[4][4][4];
    #pragma unroll
    for (int i = 0; i < 4; i++)
        #pragma unroll
        for (int j = 0; j < 4; j++)
            #pragma unroll
            for (int e = 0; e < 4; e++) acc[i][j][e] = 0.0f;

    load_chunk(0, 0);
    load_chunk(16, 1);
    #pragma unroll
    for (int ch = 0; ch < 7; ch++) {
        if (ch == 6) { CPWAIT0(); } else { CPWAIT1(); }
        __syncthreads();
        if (ch + 2 < 7) load_chunk((ch + 2) * 16, (ch + 2) % 3);

        const uint32_t base = sbase + (ch % 3) * LG_STAGE;
        const uint32_t aH = base + aoff,         aL = base + 8192  + aoff;
        const uint32_t bH = base + 16384 + boff, bL = base + 20480 + boff;
        unsigned Ahf[4][4], Alf[4][4], Bf[4][2];
        #pragma unroll
        for (int mf = 0; mf < 4; mf++) ldsm4(Ahf[mf], aH + mf * 512);
        #pragma unroll
        for (int mf = 0; mf < 4; mf++) ldsm4(Alf[mf], aL + mf * 512);
        #pragma unroll
        for (int nf = 0; nf < 4; nf++) ldsm2(Bf[nf], bH + nf * 256);
        #pragma unroll
        for (int mf = 0; mf < 4; mf++)
            #pragma unroll
            for (int nf = 0; nf < 4; nf++) mma_bf16(acc[mf][nf], Ahf[mf], Bf[nf]);
        #pragma unroll
        for (int mf = 0; mf < 4; mf++)
            #pragma unroll
            for (int nf = 0; nf < 4; nf++) mma_bf16(acc[mf][nf], Alf[mf], Bf[nf]);
        #pragma unroll
        for (int nf = 0; nf < 4; nf++) ldsm2(Bf[nf], bL + nf * 256);
        #pragma unroll
        for (int mf = 0; mf < 4; mf++)
            #pragma unroll
            for (int nf = 0; nf < 4; nf++) mma_bf16(acc[mf][nf], Ahf[mf], Bf[nf]);
    }

    // ---- staged epilogue: 4 passes of 64 rows x 128 cols ----
    float* stg = (float*)smem;                     // 64*133*4 = 34 KB
    const int gID = lane >> 2, tg = lane & 3;
    #pragma unroll 1
    for (int p = 0; p < 4; p++) {
        __syncthreads();
        if (wm == p) {
            #pragma unroll
            for (int mf = 0; mf < 4; mf++)
                #pragma unroll
                for (int nf = 0; nf < 4; nf++)
                    #pragma unroll
                    for (int e = 0; e < 4; e++) {
                        int lr = mf * 16 + gID + (e >> 1) * 8;
                        int lcc = wn * 32 + nf * 8 + tg * 2 + (e & 1);
                        stg[lr * 133 + lcc] = acc[mf][nf][e];
                    }
        }
        __syncthreads();
        const size_t rowbase = (size_t)(m0 + p * 64);
        #pragma unroll
        for (int i = 0; i < 16; i++) {
            int linear = tid + i * 512;            // [0, 8192)
            int fr = linear >> 7, fc = linear & 127;
            int gn = n0 + fc;
            if (gn < NOUT)
                out[(rowbase + fr) * NOUT + gn] = stg[fr * 133 + fc];
        }
    }
}

// ---------------------------------------------------------------------------
// adj propagation (both dirs, grid (512,2), 640 threads)
// ---------------------------------------------------------------------------
__device__ __forceinline__ void store_split4(size_t o, float a, float b, float c, float d) {
    __nv_bfloat162 h01, h23, l01, l23;
    bf16 h, l;
    split_bf16(a, h, l); h01.x = h; l01.x = l;
    split_bf16(b, h, l); h01.y = h; l01.y = l;
    split_bf16(c, h, l); h23.x = h; l23.x = l;
    split_bf16(d, h, l); h23.y = h; l23.y = l;
    *(__nv_bfloat162*)(g_XH + o)     = h01;
    *(__nv_bfloat162*)(g_XH + o + 2) = h23;
    *(__nv_bfloat162*)(g_XL + o)     = l01;
    *(__nv_bfloat162*)(g_XL + o + 2) = l23;
}

__global__ void __launch_bounds__(640)
adj_kernel(const float* __restrict__ adj_in, const float* __restrict__ adj_out)
{
    __shared__ float adjS[Tt*Tt];
    __shared__ float hS[Tt*Dd];
    int b = blockIdx.x, io = blockIdx.y;
    const float* adj = io ? adj_out : adj_in;
    int tid = threadIdx.x;
    for (int i = tid; i < Tt*Tt; i += 640) adjS[i] = adj[(size_t)b*Tt*Tt + i];
    for (int i = tid; i < Tt*Dd; i += 640) {
        int s = i / Dd, c = i - s * Dd;
        hS[i] = g_hio[(size_t)(b*Tt + s) * 200 + io * Dd + c];
    }
    __syncthreads();

    if (tid < 625) {
        int tg = tid / 25, cg = tid - tg * 25;
        int t0 = tg * 2, c0 = cg * 4;
        ull a00=0, a01=0, a10=0, a11=0;
        ull e00=0, e01=0, e10=0, e11=0;
        #pragma unroll 5
        for (int s = 0; s < Tt; s += 2) {
            const ull* hp = reinterpret_cast<const ull*>(&hS[s * Dd + c0]);
            ull b0 = hp[0], b1 = hp[1];
            float w0 = adjS[t0 * Tt + s], w1 = adjS[(t0+1) * Tt + s];
            ull p0 = pack2(w0, w0), p1 = pack2(w1, w1);
            fma2(a00, p0, b0); fma2(a01, p0, b1);
            fma2(a10, p1, b0); fma2(a11, p1, b1);
            const ull* hq = reinterpret_cast<const ull*>(&hS[(s+1) * Dd + c0]);
            ull c0v = hq[0], c1v = hq[1];
            float v0 = adjS[t0 * Tt + s + 1], v1 = adjS[(t0+1) * Tt + s + 1];
            ull q0 = pack2(v0, v0), q1 = pack2(v1, v1);
            fma2(e00, q0, c0v); fma2(e01, q0, c1v);
            fma2(e10, q1, c0v); fma2(e11, q1, c1v);
        }
        float x0,x1,x2,x3,y0,y1,y2,y3;
        size_t base0 = (size_t)(b*Tt + t0) * KP3 + KP1 + io * KP1 + c0;
        unpack2(a00,x0,x1); unpack2(a01,x2,x3);
        unpack2(e00,y0,y1); unpack2(e01,y2,y3);
        store_split4(base0, x0+y0, x1+y1, x2+y2, x3+y3);
        size_t base1 = base0 + KP3;
        unpack2(a10,x0,x1); unpack2(a11,x2,x3);
        unpack2(e10,y0,y1); unpack2(e11,y2,y3);
        store_split4(base1, x0+y0, x1+y1, x2+y2, x3+y3);
    }
}

// ---------------------------------------------------------------------------
// last vector
// ---------------------------------------------------------------------------
__global__ void last_kernel(const float* __restrict__ mask,
                            const int* __restrict__ alias_,
                            const float* __restrict__ w1)
{
    __shared__ float msum[Tt];
    __shared__ float lh[Dd];
    __shared__ int   liS;
    int b = blockIdx.x, tid = threadIdx.x;
    if (tid < Tt) msum[tid] = mask[b * Tt + tid];
    __syncthreads();
    if (tid == 0) {
        float s = 0.0f;
        for (int t = 0; t < Tt; t++) s += msum[t];
        liS = alias_[b * Tt + ((int)s - 1)];
    }
    __syncthreads();
    int li = liS;
    if (tid < Dd) lh[tid] = g_hnew[(size_t)(b * Tt + li) * Dd + tid];
    __syncthreads();
    if (tid < Dd) {
        float acc = 0.0f;
        #pragma unroll 4
        for (int k = 0; k < Dd; k++) acc += lh[k] * w1[k * Dd + tid];
        g_last[b * Dd + tid] = acc;
    }
}

// ---------------------------------------------------------------------------
// attention + readout; writes split y1 directly
// ---------------------------------------------------------------------------
__global__ void __launch_bounds__(128)
att_kernel(const float* __restrict__ mask, const float* __restrict__ vv,
           const float* __restrict__ nb, const float* __restrict__ Bmat)
{
    __shared__ float lastS[Dd], nbS[Dd], vS[Dd];
    __shared__ float acc4[4][Dd];
    __shared__ float maS[2 * Dd];
    int b = blockIdx.x, tid = threadIdx.x;
    int w = tid >> 5, lane = tid & 31;

    if (tid < Dd) { lastS[tid] = g_last[b * Dd + tid]; nbS[tid] = nb[tid]; vS[tid] = vv[tid]; }
    __syncthreads();

    float accR[4] = {0.f, 0.f, 0.f, 0.f};
    for (int t = w; t < Tt; t += 4) {
        const float* seqrow = &g_seq [(size_t)(b * Tt + t) * Dd];
        const float* shrow  = &g_seqh[(size_t)(b * Tt + t) * Dd];
        float part = 0.0f;
        #pragma unroll
        for (int j = 0; j < 4; j++) {
            int c = lane + 32 * j;
            if (c < Dd) part += sigmoidf_(lastS[c] + seqrow[c] + nbS[c]) * vS[c];
        }
        #pragma unroll
        for (int off = 16; off > 0; off >>= 1)
            part += __shfl_xor_sync(0xffffffffu, part, off);
        float coef = part * mask[b * Tt + t];
        #pragma unroll
        for (int j = 0; j < 4; j++) {
            int c = lane + 32 * j;
            if (c < Dd) accR[j] += coef * shrow[c];
        }
    }
    #pragma unroll
    for (int j = 0; j < 4; j++) {
        int c = lane + 32 * j;
        if (c < Dd) acc4[w][c] = accR[j];
    }
    __syncthreads();
    if (tid < Dd) {
        maS[tid]      = acc4[0][tid] + acc4[1][tid] + acc4[2][tid] + acc4[3][tid];
        maS[Dd + tid] = lastS[tid];
    }
    __syncthreads();
    if (tid < Dd) {
        float y = 0.0f;
        #pragma unroll 4
        for (int k = 0; k < 2 * Dd; k++) y += maS[k] * Bmat[k * Dd + tid];
        split_bf16(y, g_yH[b * KP1 + tid], g_yL[b * KP1 + tid]);
    }
}

// ---------------------------------------------------------------------------
// Host launcher
// ---------------------------------------------------------------------------
static inline int cdiv(int a, int b) { return (a + b - 1) / b; }

extern "C" void kernel_launch(void* const* d_in, const int* in_sizes, int n_in,
                              void* d_out, int out_size)
{
    int o = 0;
    if (n_in < 20 || in_sizes[5] != 1) o = -1;  // step scalar possibly omitted

    const float* adj_in  = (const float*)d_in[0];
    const float* adj_out = (const float*)d_in[1];
    const float* mask    = (const float*)d_in[2];
    const int*   item    = (const int*)  d_in[3];
    const int*   alias_  = (const int*)  d_in[4];
    const float* emb     = (const float*)d_in[6  + o];
    const float* W_in    = (const float*)d_in[7  + o];
    const float* b_in    = (const float*)d_in[8  + o];
    const float* W_out   = (const float*)d_in[9  + o];
    const float* b_out   = (const float*)d_in[10 + o];
    const float* ggk     = (const float*)d_in[11 + o];
    const float* ggb     = (const float*)d_in[12 + o];
    const float* gck     = (const float*)d_in[13 + o];
    const float* gcb     = (const float*)d_in[14 + o];
    const float* w1      = (const float*)d_in[15 + o];
    const float* w2      = (const float*)d_in[16 + o];
    const float* vv      = (const float*)d_in[17 + o];
    const float* nb      = (const float*)d_in[18 + o];
    const float* Bmat    = (const float*)d_in[19 + o];
    float* out = (float*)d_out;

    void* p;
    #define SYM(T, var, sym) cudaGetSymbolAddress(&p, sym); T* var = (T*)p
    SYM(float, ph,    g_h);    SYM(float, phio,  g_hio);
    SYM(float, pu,    g_u);    SYM(float, phnew, g_hnew);
    SYM(float, pseq,  g_seq);  SYM(float, pbio,  g_bio);
    SYM(bf16, peH, g_eH);   SYM(bf16, peL, g_eL);
    SYM(bf16, pXH, g_XH);   SYM(bf16, pXL, g_XL);
    SYM(bf16, psH, g_sH);   SYM(bf16, psL, g_sL);
    SYM(bf16, pyH, g_yH);   SYM(bf16, pyL, g_yL);
    SYM(bf16, pWioH, g_WioH); SYM(bf16, pWioL, g_WioL);
    SYM(bf16, pggkH, g_ggkH); SYM(bf16, pggkL, g_ggkL);
    #undef SYM

    static bool attr_set = false;
    if (!attr_set) {
        cudaFuncSetAttribute(logits_gemm,
                             cudaFuncAttributeMaxDynamicSharedMemorySize, LG_SMEM);
        attr_set = true;
    }

    // Harness inserts 2 launches before ours; ncu (-s 5 -c 1) profiles OUR
    // launch #4 — kept as the hio mma_gemm (verify occ/regs delta this round).
    gather_h_kernel<<<cdiv(BT * KP1, 256), 256>>>(emb, item);                     // 1
    conv_wio_kernel<<<cdiv(2 * Dd * KP1, 256), 256>>>(W_in, W_out, b_in, b_out);  // 2
    conv_wT_kernel<<<cdiv(2 * Dd * KP3, 256), 256>>>(ggk, pggkH, pggkL, 2*Dd, 3); // 3

    // [hin | hout] = h @ [W_in | W_out] + bio   (A = X segment 0, ldA = KP3)
    mma_gemm<0, 7, false><<<dim3(2, BT / 128), 256>>>(                            // 4 (profiled)
        pXH, pXL, KP3, pWioH, pWioL, pbio, phio, 2 * Dd, 2 * Dd,
        nullptr, nullptr, nullptr);

    conv_wT2_kernel<<<cdiv(Dd * (KP3 + KP1), 256), 256>>>(gck, w2);               // 5
    conv_emb_kernel<<<cdiv(NN * 56, 256), 256>>>(emb);                            // 6

    adj_kernel<<<dim3(Bb, 2), 640>>>(adj_in, adj_out);

    mma_gemm<1, 21, false><<<dim3(2, BT / 128), 256>>>(
        pXH, pXL, KP3, pggkH, pggkL, ggb, nullptr, 2 * Dd, 0,
        ph, nullptr, pu);

    {
        void* q;
        cudaGetSymbolAddress(&q, g_gckH); bf16* pgckH = (bf16*)q;
        cudaGetSymbolAddress(&q, g_gckL); bf16* pgckL = (bf16*)q;
        mma_gemm<2, 21, true><<<dim3(1, BT / 128), 256>>>(
            pXH, pXL, KP3, pgckH, pgckL, gcb, phnew, Dd, Dd,
            ph, pu, nullptr);
    }

    // ---- attention readout ----
    last_kernel<<<Bb, 128>>>(mask, alias_, w1);
    seqh_kernel<<<cdiv(BT * KP1, 256), 256>>>(alias_);

    {
        void* q;
        cudaGetSymbolAddress(&q, g_w2H); bf16* pw2H = (bf16*)q;
        cudaGetSymbolAddress(&q, g_w2L); bf16* pw2L = (bf16*)q;
        mma_gemm<0, 7, false><<<dim3(1, BT / 128), 256>>>(
            psH, psL, KP1, pw2H, pw2L, nullptr, pseq, Dd, Dd,
            nullptr, nullptr, nullptr);
    }

    att_kernel<<<Bb, 128>>>(mask, vv, nb, Bmat);

    // ---- logits: BM=256 tile, 3-stage pipeline, staged coalesced epilogue ----
    logits_gemm<<<dim3(2, cdiv(NOUT, 128)), 512, LG_SMEM>>>(pyH, pyL, peH, peL, out);
}